// round 11
// baseline (speedup 1.0000x reference)
#include <cuda_runtime.h>
#include <cstdint>

#define TOKS 8192
#define EDIM 768
#define FDIM 3072
#define SEQ  1024
#define NH   12
#define HD   64
#define NLAYER 6

#define EE (EDIM * EDIM)
#define EF (EDIM * FDIM)
#define WT_PER_LAYER (4 * EE + 2 * EF)

// ---------------- scratch (device globals; no allocation) ----------------
__device__ float g_x[TOKS * EDIM];
__device__ float g_q[TOKS * EDIM];
__device__ float g_k[TOKS * EDIM];
__device__ float g_v[TOKS * EDIM];   // holds V^T: [b][h][hd][seq]
__device__ float g_att[TOKS * EDIM];
__device__ float g_t[TOKS * EDIM];
__device__ float g_ffn[TOKS * FDIM];
__device__ float g_pool[8 * EDIM];
__device__ float g_wt[(long)NLAYER * WT_PER_LAYER];  // transposed + RNA-rounded weights

// ---------------- helpers ----------------
__device__ __forceinline__ uint32_t f2tf32(float x) {
    uint32_t r;
    asm("cvt.rna.tf32.f32 %0, %1;" : "=r"(r) : "f"(x));
    return r;
}
__device__ __forceinline__ float rna_f(float x) { return __uint_as_float(f2tf32(x)); }

__device__ __forceinline__ void mma8(float* c, uint32_t a0, uint32_t a1, uint32_t a2, uint32_t a3,
                                     uint32_t b0, uint32_t b1) {
    asm volatile(
        "mma.sync.aligned.m16n8k8.row.col.f32.tf32.tf32.f32 "
        "{%0,%1,%2,%3}, {%4,%5,%6,%7}, {%8,%9}, {%0,%1,%2,%3};"
        : "+f"(c[0]), "+f"(c[1]), "+f"(c[2]), "+f"(c[3])
        : "r"(a0), "r"(a1), "r"(a2), "r"(a3), "r"(b0), "r"(b1));
}

__device__ __forceinline__ void ldsm4(uint32_t* r, uint32_t a) {
    asm volatile("ldmatrix.sync.aligned.m8n8.x4.shared.b16 {%0,%1,%2,%3}, [%4];"
                 : "=r"(r[0]), "=r"(r[1]), "=r"(r[2]), "=r"(r[3]) : "r"(a));
}

__device__ __forceinline__ void cp16(uint32_t saddr, const void* gaddr) {
    asm volatile("cp.async.cg.shared.global [%0], [%1], 16;" ::"r"(saddr), "l"(gaddr));
}
__device__ __forceinline__ void cp_commit() { asm volatile("cp.async.commit_group;"); }

__device__ __forceinline__ uint32_t smem_u32(const void* p) {
    uint32_t a;
    asm("{ .reg .u64 t; cvta.to.shared.u64 t, %1; cvt.u32.u64 %0, t; }" : "=r"(a) : "l"(p));
    return a;
}

// ---------------- batched weight transpose + RNA round ----------------
// dst[N][K] = rna(src[K][N]^T), one layer per blockIdx.z
__global__ void transpose_all(const float* __restrict__ src, float* __restrict__ dst,
                              int K, int N, long sstride, long dstride) {
    int lz = blockIdx.z;
    src += (long)lz * sstride;
    dst += (long)lz * dstride;
    __shared__ float tl[32][33];
    int n0 = blockIdx.x * 32, k0 = blockIdx.y * 32;
    int tx = threadIdx.x, ty = threadIdx.y;
#pragma unroll
    for (int j = 0; j < 32; j += 8) tl[ty + j][tx] = src[(long)(k0 + ty + j) * N + n0 + tx];
    __syncthreads();
#pragma unroll
    for (int j = 0; j < 32; j += 8)
        dst[(long)(n0 + ty + j) * K + k0 + tx] = rna_f(tl[tx][ty + j]);
}

// ---------------- embedding + positional encoding (RNA-rounded output) ----------------
__global__ void embed_kernel(const int* __restrict__ ids, const float* __restrict__ emb,
                             const float* __restrict__ pe, float* __restrict__ x) {
    long idx = (long)blockIdx.x * blockDim.x + threadIdx.x;
    if (idx >= (long)TOKS * EDIM) return;
    int tok = (int)(idx / EDIM);
    int e = (int)(idx - (long)tok * EDIM);
    int s = tok & (SEQ - 1);
    x[idx] = rna_f(emb[(long)ids[tok] * EDIM + e] + pe[s * EDIM + e]);
}

// ---------------- TF32 mma GEMM, BK=64, 3-stage cp.async, 256 thr (2x4 warps) ------
// C[M,N] = A[M,K] @ Wt[N,K]^T + bias.  block 128x128, warp tile 64x32.
// modes: 0 plain, 1 relu+rna, 2 rna, 3 rna + V^T scatter ([b][h][hd][seq])
struct Trip {
    const float* W;   // [N][K] transposed, pre-rounded
    const float* b;
    float* C;
    int mode;
};

#define GROW 272                 // 64 floats (256B) + 16B pad
#define GAS (128 * GROW)         // 34816 per tensor
#define GSTAGE (2 * GAS)         // 69632
#define GEMM_SMEM (3 * GSTAGE)   // 208896

__global__ __launch_bounds__(256, 1) void gemm_lds(const float* __restrict__ A,
                                                   Trip t0, Trip t1, Trip t2,
                                                   int N, int K) {
    extern __shared__ __align__(128) char smc[];
    uint32_t sb = smem_u32(smc);
    int t = threadIdx.x, l = t & 31, warp = t >> 5;
    int wm = warp >> 2, wn = warp & 3;
    int g = l >> 2, tg = l & 3;

    int z = blockIdx.z;
    Trip tr = (z == 0) ? t0 : (z == 1) ? t1 : t2;
    long bm = blockIdx.y, bn = blockIdx.x;
    const float* Ab = A + bm * 128 * (long)K;
    const float* Bb = tr.W + bn * 128 * (long)K;

    int rbase = t >> 4, seg = t & 15;  // 16 rows/pass, 16 segs of 16B per row

    uint32_t aOff[4], bOff[2];
#pragma unroll
    for (int mf = 0; mf < 4; mf++)
        aOff[mf] = (uint32_t)((wm * 64 + mf * 16 + (l & 7) + ((l >> 3) & 1) * 8) * GROW +
                              (l >> 4) * 16);
#pragma unroll
    for (int j = 0; j < 2; j++)
        bOff[j] = (uint32_t)(GAS +
                             (wn * 32 + (2 * j + (l >> 4)) * 8 + (l & 7)) * GROW +
                             ((l >> 3) & 1) * 16);

    float acc[4][4][4];
#pragma unroll
    for (int i = 0; i < 4; i++)
#pragma unroll
        for (int j = 0; j < 4; j++)
#pragma unroll
            for (int q = 0; q < 4; q++) acc[i][j][q] = 0.f;

    int niter = K >> 6;  // BK=64

#pragma unroll
    for (int st = 0; st < 2; st++) {
        uint32_t sA = sb + st * GSTAGE, sB = sA + GAS;
        int k0 = st * 64;
#pragma unroll
        for (int p = 0; p < 8; p++) {
            int r = rbase + p * 16;
            cp16(sA + (uint32_t)(r * GROW + seg * 16), Ab + (long)r * K + k0 + seg * 4);
            cp16(sB + (uint32_t)(r * GROW + seg * 16), Bb + (long)r * K + k0 + seg * 4);
        }
        cp_commit();
    }

    int s = 0;
    for (int it = 0; it < niter; it++) {
        asm volatile("cp.async.wait_group 1;");
        __syncthreads();

        int jn = it + 2;
        if (jn < niter) {
            int s2 = jn % 3;
            uint32_t sA2 = sb + s2 * GSTAGE, sB2 = sA2 + GAS;
            int k0 = jn * 64;
#pragma unroll
            for (int p = 0; p < 8; p++) {
                int r = rbase + p * 16;
                cp16(sA2 + (uint32_t)(r * GROW + seg * 16), Ab + (long)r * K + k0 + seg * 4);
                cp16(sB2 + (uint32_t)(r * GROW + seg * 16), Bb + (long)r * K + k0 + seg * 4);
            }
        }
        cp_commit();

        uint32_t sA = sb + s * GSTAGE;
#pragma unroll
        for (int kk = 0; kk < 8; kk++) {
            uint32_t af[4][4], bf[4][2];
#pragma unroll
            for (int mf = 0; mf < 4; mf++) ldsm4(af[mf], sA + aOff[mf] + kk * 32);
#pragma unroll
            for (int j = 0; j < 2; j++) ldsm4(&bf[2 * j][0], sA + bOff[j] + kk * 32);
#pragma unroll
            for (int mf = 0; mf < 4; mf++)
#pragma unroll
                for (int nf = 0; nf < 4; nf++)
                    mma8(acc[mf][nf], af[mf][0], af[mf][1], af[mf][2], af[mf][3],
                         bf[nf][0], bf[nf][1]);
        }
        s = (s == 2) ? 0 : s + 1;
    }

    int mode = tr.mode;
    const float* bias = tr.b;
    float* C = tr.C;
#pragma unroll
    for (int mf = 0; mf < 4; mf++) {
        int r0 = (int)bm * 128 + wm * 64 + mf * 16 + g;
#pragma unroll
        for (int nf = 0; nf < 4; nf++) {
            int c0 = (int)bn * 128 + wn * 32 + nf * 8 + 2 * tg;
            float bb0 = bias[c0], bb1 = bias[c0 + 1];
            float v0 = acc[mf][nf][0] + bb0;
            float v1 = acc[mf][nf][1] + bb1;
            float v2 = acc[mf][nf][2] + bb0;
            float v3 = acc[mf][nf][3] + bb1;
            if (mode == 1) {
                v0 = rna_f(fmaxf(v0, 0.f)); v1 = rna_f(fmaxf(v1, 0.f));
                v2 = rna_f(fmaxf(v2, 0.f)); v3 = rna_f(fmaxf(v3, 0.f));
            } else if (mode >= 2) {
                v0 = rna_f(v0); v1 = rna_f(v1); v2 = rna_f(v2); v3 = rna_f(v3);
            }
            if (mode == 3) {
                int b_ = r0 >> 10, sp = r0 & 1023;
                int h0 = c0 >> 6, d0 = c0 & 63;
                long vb = ((long)(b_ * NH + h0) * HD + d0) * SEQ + sp;
                C[vb] = v0;
                C[vb + SEQ] = v1;
                C[vb + 8] = v2;
                C[vb + SEQ + 8] = v3;
            } else {
                *(float2*)&C[(long)r0 * N + c0] = make_float2(v0, v1);
                *(float2*)&C[(long)(r0 + 8) * N + c0] = make_float2(v2, v3);
            }
        }
    }
}

// ---------------- fused flash attention, q-tile 128, 256 threads (8 warps) ----------
// smem (bytes): Q[128][68] @0, P[128][68] @34816, mask[1024] @69632,
// stages @73728 + s*34816 : K[64][68] then V^T[64][68].  total 143360
#define ATT_SMEM 143360

__global__ __launch_bounds__(256) void attn_kernel(const float* __restrict__ Q,
                                                   const float* __restrict__ Kp,
                                                   const float* __restrict__ Vt,
                                                   const int* __restrict__ mask,
                                                   float* __restrict__ O) {
    extern __shared__ __align__(128) char smc[];
    uint32_t sb = smem_u32(smc);
    float* mAdd = (float*)(smc + 69632);

    int t = threadIdx.x, l = t & 31, warp = t >> 5;
    int g = l >> 2, tg = l & 3;
    int b = blockIdx.z, h = blockIdx.y, qt = blockIdx.x;
    int rq = warp * 16;

    const float* Qb = Q + ((long)(b * SEQ + qt * 128)) * EDIM + h * HD;
    const float* Kb = Kp + ((long)(b * SEQ)) * EDIM + h * HD;
    const float* Vb = Vt + ((long)(b * NH + h) * HD) * SEQ;

    uint32_t aQoff = (uint32_t)((rq + (l & 7) + ((l >> 3) & 1) * 8) * 272 + (l >> 4) * 16);
    uint32_t bOff[4];
#pragma unroll
    for (int j = 0; j < 4; j++)
        bOff[j] = (uint32_t)(((2 * j + (l >> 4)) * 8 + (l & 7)) * 272 + ((l >> 3) & 1) * 16);

    {
        int r = t >> 1, s0 = (t & 1) * 8;
#pragma unroll
        for (int j = 0; j < 8; j++)
            cp16(sb + (uint32_t)(r * 272 + (s0 + j) * 16), Qb + (long)r * EDIM + (s0 + j) * 4);
        cp_commit();
    }
    for (int i = t; i < SEQ; i += 256) mAdd[i] = mask[b * SEQ + i] ? 0.f : -1e30f;

#pragma unroll
    for (int st = 0; st < 2; st++) {
        uint32_t Kst = sb + 73728 + st * 34816, Vst = Kst + 17408;
        int r = t >> 2, j0 = (t & 3) * 4;
        const float* Ks = Kb + (long)(st * 64) * EDIM;
        const float* Vs = Vb + st * 64;
#pragma unroll
        for (int j = 0; j < 4; j++) {
            cp16(Kst + (uint32_t)(r * 272 + (j0 + j) * 16), Ks + (long)r * EDIM + (j0 + j) * 4);
            cp16(Vst + (uint32_t)(r * 272 + (j0 + j) * 16), Vs + (long)r * SEQ + (j0 + j) * 4);
        }
        cp_commit();
    }

    float m_[2] = {-INFINITY, -INFINITY};
    float l_[2] = {0.f, 0.f};
    float o[8][4];
#pragma unroll
    for (int nf = 0; nf < 8; nf++)
#pragma unroll
        for (int q = 0; q < 4; q++) o[nf][q] = 0.f;

    for (int kt = 0; kt < 16; kt++) {
        int s = kt & 1;
        uint32_t Kst = sb + 73728 + s * 34816, Vst = Kst + 17408;
        asm volatile("cp.async.wait_group 1;");
        __syncthreads();

        float sc[8][4];
#pragma unroll
        for (int nf = 0; nf < 8; nf++)
#pragma unroll
            for (int q = 0; q < 4; q++) sc[nf][q] = 0.f;
#pragma unroll
        for (int kk = 0; kk < 8; kk++) {
            uint32_t af[4], bf[8][2];
            ldsm4(af, sb + aQoff + kk * 32);
#pragma unroll
            for (int j = 0; j < 4; j++) ldsm4(&bf[2 * j][0], Kst + bOff[j] + kk * 32);
#pragma unroll
            for (int nf = 0; nf < 8; nf++)
                mma8(sc[nf], af[0], af[1], af[2], af[3], bf[nf][0], bf[nf][1]);
        }

        float rmax0 = -INFINITY, rmax1 = -INFINITY;
#pragma unroll
        for (int nf = 0; nf < 8; nf++) {
            int c0 = kt * 64 + nf * 8 + 2 * tg;
            float ma = mAdd[c0], mb = mAdd[c0 + 1];
            sc[nf][0] = sc[nf][0] * 0.125f + ma;
            sc[nf][1] = sc[nf][1] * 0.125f + mb;
            sc[nf][2] = sc[nf][2] * 0.125f + ma;
            sc[nf][3] = sc[nf][3] * 0.125f + mb;
            rmax0 = fmaxf(rmax0, fmaxf(sc[nf][0], sc[nf][1]));
            rmax1 = fmaxf(rmax1, fmaxf(sc[nf][2], sc[nf][3]));
        }
        rmax0 = fmaxf(rmax0, __shfl_xor_sync(0xffffffffu, rmax0, 1));
        rmax0 = fmaxf(rmax0, __shfl_xor_sync(0xffffffffu, rmax0, 2));
        rmax1 = fmaxf(rmax1, __shfl_xor_sync(0xffffffffu, rmax1, 1));
        rmax1 = fmaxf(rmax1, __shfl_xor_sync(0xffffffffu, rmax1, 2));
        float mn0 = fmaxf(m_[0], rmax0), mn1 = fmaxf(m_[1], rmax1);
        float cf0 = __expf(m_[0] - mn0), cf1 = __expf(m_[1] - mn1);
        float rs0 = 0.f, rs1 = 0.f;
#pragma unroll
        for (int nf = 0; nf < 8; nf++) {
            sc[nf][0] = __expf(sc[nf][0] - mn0);
            sc[nf][1] = __expf(sc[nf][1] - mn0);
            sc[nf][2] = __expf(sc[nf][2] - mn1);
            sc[nf][3] = __expf(sc[nf][3] - mn1);
            rs0 += sc[nf][0] + sc[nf][1];
            rs1 += sc[nf][2] + sc[nf][3];
        }
        rs0 += __shfl_xor_sync(0xffffffffu, rs0, 1);
        rs0 += __shfl_xor_sync(0xffffffffu, rs0, 2);
        rs1 += __shfl_xor_sync(0xffffffffu, rs1, 1);
        rs1 += __shfl_xor_sync(0xffffffffu, rs1, 2);
        l_[0] = l_[0] * cf0 + rs0;
        l_[1] = l_[1] * cf1 + rs1;
        m_[0] = mn0; m_[1] = mn1;
#pragma unroll
        for (int nf = 0; nf < 8; nf++) {
            o[nf][0] *= cf0; o[nf][1] *= cf0;
            o[nf][2] *= cf1; o[nf][3] *= cf1;
        }

#pragma unroll
        for (int nf = 0; nf < 8; nf++) {
            int pc = nf * 8 + 2 * tg;
            uint32_t a0 = sb + 34816 + (uint32_t)((rq + g) * 272 + pc * 4);
            uint32_t a1 = sb + 34816 + (uint32_t)((rq + 8 + g) * 272 + pc * 4);
            asm volatile("st.shared.v2.b32 [%0], {%1, %2};" ::"r"(a0),
                         "r"(f2tf32(sc[nf][0])), "r"(f2tf32(sc[nf][1])) : "memory");
            asm volatile("st.shared.v2.b32 [%0], {%1, %2};" ::"r"(a1),
                         "r"(f2tf32(sc[nf][2])), "r"(f2tf32(sc[nf][3])) : "memory");
        }
        __syncwarp();
#pragma unroll
        for (int kk = 0; kk < 8; kk++) {
            uint32_t af[4], bf[8][2];
            ldsm4(af, sb + 34816 + aQoff + kk * 32);
#pragma unroll
            for (int j = 0; j < 4; j++) ldsm4(&bf[2 * j][0], Vst + bOff[j] + kk * 32);
#pragma unroll
            for (int nf = 0; nf < 8; nf++)
                mma8(o[nf], af[0], af[1], af[2], af[3], bf[nf][0], bf[nf][1]);
        }
        __syncthreads();

        int jn = kt + 2;
        if (jn < 16) {
            int r = t >> 2, j0 = (t & 3) * 4;
            const float* Ks = Kb + (long)(jn * 64) * EDIM;
            const float* Vs = Vb + jn * 64;
#pragma unroll
            for (int j = 0; j < 4; j++) {
                cp16(Kst + (uint32_t)(r * 272 + (j0 + j) * 16), Ks + (long)r * EDIM + (j0 + j) * 4);
                cp16(Vst + (uint32_t)(r * 272 + (j0 + j) * 16), Vs + (long)r * SEQ + (j0 + j) * 4);
            }
        }
        cp_commit();
    }

    float il0 = 1.f / l_[0], il1 = 1.f / l_[1];
#pragma unroll
    for (int nf = 0; nf < 8; nf++) {
        long rowg = (long)(b * SEQ + qt * 128 + rq + g);
        int colg = h * HD + nf * 8 + 2 * tg;
        O[rowg * EDIM + colg] = rna_f(o[nf][0] * il0);
        O[rowg * EDIM + colg + 1] = rna_f(o[nf][1] * il0);
        O[(rowg + 8) * EDIM + colg] = rna_f(o[nf][2] * il1);
        O[(rowg + 8) * EDIM + colg + 1] = rna_f(o[nf][3] * il1);
    }
}

// ---------------- fused residual add + LayerNorm, float4, 192 threads ----------------
__global__ __launch_bounds__(192) void ln_res_kernel(const float* __restrict__ x,
                                                     const float* __restrict__ y,
                                                     const float* __restrict__ gam,
                                                     const float* __restrict__ bet,
                                                     float* __restrict__ out) {
    int row = blockIdx.x, t = threadIdx.x;
    const float4* xr = (const float4*)(x + (long)row * EDIM);
    const float4* yr = (const float4*)(y + (long)row * EDIM);
    float4 a = xr[t], b4 = yr[t];
    float v0 = a.x + b4.x, v1 = a.y + b4.y, v2 = a.z + b4.z, v3 = a.w + b4.w;
    float s1 = v0 + v1 + v2 + v3;
    float s2 = v0 * v0 + v1 * v1 + v2 * v2 + v3 * v3;
    __shared__ float sh[2][6];
    int lane = t & 31, w = t >> 5;
#pragma unroll
    for (int off = 16; off; off >>= 1) {
        s1 += __shfl_xor_sync(0xffffffffu, s1, off);
        s2 += __shfl_xor_sync(0xffffffffu, s2, off);
    }
    if (!lane) { sh[0][w] = s1; sh[1][w] = s2; }
    __syncthreads();
    float a1 = 0.f, a2 = 0.f;
#pragma unroll
    for (int i = 0; i < 6; i++) { a1 += sh[0][i]; a2 += sh[1][i]; }
    float mean = a1 * (1.f / EDIM);
    float var = a2 * (1.f / EDIM) - mean * mean;
    float rstd = rsqrtf(var + 1e-5f);
    float4 gg = ((const float4*)gam)[t];
    float4 bb = ((const float4*)bet)[t];
    float4 o;
    o.x = rna_f((v0 - mean) * rstd * gg.x + bb.x);
    o.y = rna_f((v1 - mean) * rstd * gg.y + bb.y);
    o.z = rna_f((v2 - mean) * rstd * gg.z + bb.z);
    o.w = rna_f((v3 - mean) * rstd * gg.w + bb.w);
    ((float4*)(out + (long)row * EDIM))[t] = o;
}

// ---------------- mean pool ----------------
__global__ void pool_kernel(const float* __restrict__ x, float* __restrict__ p) {
    int idx = blockIdx.x * blockDim.x + threadIdx.x;
    if (idx >= 8 * (EDIM / 4)) return;
    int b = idx / (EDIM / 4), e4 = idx % (EDIM / 4);
    const float4* xb = (const float4*)(x + (long)b * SEQ * EDIM) + e4;
    float4 s = make_float4(0.f, 0.f, 0.f, 0.f);
    for (int si = 0; si < SEQ; si++) {
        float4 v = xb[(long)si * (EDIM / 4)];
        s.x += v.x; s.y += v.y; s.z += v.z; s.w += v.w;
    }
    s.x *= (1.f / SEQ); s.y *= (1.f / SEQ); s.z *= (1.f / SEQ); s.w *= (1.f / SEQ);
    ((float4*)p)[idx] = s;
}

// ---------------- classifier ----------------
__global__ void cls_kernel(const float* __restrict__ p, const float* __restrict__ Wc,
                           const float* __restrict__ bc, float* __restrict__ out) {
    int w = threadIdx.x >> 5, lane = threadIdx.x & 31;
    int b = w >> 1, c = w & 1;
    float s = 0.f;
    for (int e = lane; e < EDIM; e += 32) s += p[b * EDIM + e] * Wc[e * 2 + c];
#pragma unroll
    for (int off = 16; off; off >>= 1) s += __shfl_xor_sync(0xffffffffu, s, off);
    if (!lane) out[b * 2 + c] = s + bc[c];
}

// ---------------- launch ----------------
extern "C" void kernel_launch(void* const* d_in, const int* in_sizes, int n_in,
                              void* d_out, int out_size) {
    (void)in_sizes; (void)n_in; (void)out_size;
    const int* ids = (const int*)d_in[0];
    const int* amask = (const int*)d_in[1];
    const float* emb = (const float*)d_in[2];
    const float* pe = (const float*)d_in[3];
    const float* Wq = (const float*)d_in[4];
    const float* bq = (const float*)d_in[5];
    const float* Wk = (const float*)d_in[6];
    const float* bk = (const float*)d_in[7];
    const float* Wv = (const float*)d_in[8];
    const float* bv = (const float*)d_in[9];
    const float* Wo = (const float*)d_in[10];
    const float* bo = (const float*)d_in[11];
    const float* l1g = (const float*)d_in[12];
    const float* l1b = (const float*)d_in[13];
    const float* W1 = (const float*)d_in[14];
    const float* b1 = (const float*)d_in[15];
    const float* W2 = (const float*)d_in[16];
    const float* b2 = (const float*)d_in[17];
    const float* l2g = (const float*)d_in[18];
    const float* l2b = (const float*)d_in[19];
    const float* Wc = (const float*)d_in[20];
    const float* bc = (const float*)d_in[21];
    float* out = (float*)d_out;

    float *x, *q, *k, *v, *att, *tmp, *ffn, *pl, *wt;
    cudaGetSymbolAddress((void**)&x, g_x);
    cudaGetSymbolAddress((void**)&q, g_q);
    cudaGetSymbolAddress((void**)&k, g_k);
    cudaGetSymbolAddress((void**)&v, g_v);
    cudaGetSymbolAddress((void**)&att, g_att);
    cudaGetSymbolAddress((void**)&tmp, g_t);
    cudaGetSymbolAddress((void**)&ffn, g_ffn);
    cudaGetSymbolAddress((void**)&pl, g_pool);
    cudaGetSymbolAddress((void**)&wt, g_wt);

    cudaFuncSetAttribute(gemm_lds, cudaFuncAttributeMaxDynamicSharedMemorySize, GEMM_SMEM);
    cudaFuncSetAttribute(attn_kernel, cudaFuncAttributeMaxDynamicSharedMemorySize, ATT_SMEM);

    // one-time per launch: transpose + RNA-round all weights (batched over layers)
    dim3 tb(32, 8);
    transpose_all<<<dim3(EDIM / 32, EDIM / 32, NLAYER), tb>>>(Wq, wt + 0L * EE, EDIM, EDIM,
                                                             (long)EE, (long)WT_PER_LAYER);
    transpose_all<<<dim3(EDIM / 32, EDIM / 32, NLAYER), tb>>>(Wk, wt + 1L * EE, EDIM, EDIM,
                                                             (long)EE, (long)WT_PER_LAYER);
    transpose_all<<<dim3(EDIM / 32, EDIM / 32, NLAYER), tb>>>(Wv, wt + 2L * EE, EDIM, EDIM,
                                                             (long)EE, (long)WT_PER_LAYER);
    transpose_all<<<dim3(EDIM / 32, EDIM / 32, NLAYER), tb>>>(Wo, wt + 3L * EE, EDIM, EDIM,
                                                             (long)EE, (long)WT_PER_LAYER);
    transpose_all<<<dim3(FDIM / 32, EDIM / 32, NLAYER), tb>>>(W1, wt + 4L * EE, EDIM, FDIM,
                                                             (long)EF, (long)WT_PER_LAYER);
    transpose_all<<<dim3(EDIM / 32, FDIM / 32, NLAYER), tb>>>(W2, wt + 4L * EE + EF, FDIM, EDIM,
                                                             (long)EF, (long)WT_PER_LAYER);

    embed_kernel<<<(TOKS * EDIM + 255) / 256, 256>>>(ids, emb, pe, x);

    for (int l = 0; l < NLAYER; l++) {
        long boff = (long)l * EDIM;
        float* base = wt + (long)l * WT_PER_LAYER;
        Trip tq = {base + 0L * EE, bq + boff, q, 2};
        Trip tk = {base + 1L * EE, bk + boff, k, 2};
        Trip tv = {base + 2L * EE, bv + boff, v, 3};
        gemm_lds<<<dim3(6, 64, 3), 256, GEMM_SMEM>>>(x, tq, tk, tv, EDIM, EDIM);
        attn_kernel<<<dim3(8, 12, 8), 256, ATT_SMEM>>>(q, k, v, amask, att);
        Trip to = {base + 3L * EE, bo + boff, tmp, 0};
        gemm_lds<<<dim3(6, 64, 1), 256, GEMM_SMEM>>>(att, to, to, to, EDIM, EDIM);
        ln_res_kernel<<<TOKS, 192>>>(x, tmp, l1g + boff, l1b + boff, x);
        Trip t1 = {base + 4L * EE, b1 + (long)l * FDIM, ffn, 1};
        gemm_lds<<<dim3(24, 64, 1), 256, GEMM_SMEM>>>(x, t1, t1, t1, FDIM, EDIM);
        Trip t2 = {base + 4L * EE + EF, b2 + boff, tmp, 0};
        gemm_lds<<<dim3(6, 64, 1), 256, GEMM_SMEM>>>(ffn, t2, t2, t2, EDIM, FDIM);
        ln_res_kernel<<<TOKS, 192>>>(x, tmp, l2g + boff, l2b + boff, x);
    }

    pool_kernel<<<(8 * EDIM / 4 + 255) / 256, 256>>>(x, pl);
    cls_kernel<<<1, 512>>>(pl, Wc, bc, out);
}

// round 12
// speedup vs baseline: 1.1243x; 1.1243x over previous
#include <cuda_runtime.h>
#include <cstdint>

#define TOKS 8192
#define EDIM 768
#define FDIM 3072
#define SEQ  1024
#define NH   12
#define HD   64
#define NLAYER 6

#define EE (EDIM * EDIM)
#define EF (EDIM * FDIM)
#define WT_PER_LAYER (4 * EE + 2 * EF)

// ---------------- scratch (device globals; no allocation) ----------------
__device__ float g_x[TOKS * EDIM];
__device__ float g_q[TOKS * EDIM];
__device__ float g_k[TOKS * EDIM];
__device__ float g_v[TOKS * EDIM];   // holds V^T: [b][h][hd][seq]
__device__ float g_att[TOKS * EDIM];
__device__ float g_t[TOKS * EDIM];
__device__ float g_ffn[TOKS * FDIM];
__device__ float g_pool[8 * EDIM];
__device__ float g_wt[(long)NLAYER * WT_PER_LAYER];  // transposed + RNA-rounded weights

// ---------------- helpers ----------------
__device__ __forceinline__ uint32_t f2tf32(float x) {
    uint32_t r;
    asm("cvt.rna.tf32.f32 %0, %1;" : "=r"(r) : "f"(x));
    return r;
}
__device__ __forceinline__ float rna_f(float x) { return __uint_as_float(f2tf32(x)); }

__device__ __forceinline__ void mma8(float* c, uint32_t a0, uint32_t a1, uint32_t a2, uint32_t a3,
                                     uint32_t b0, uint32_t b1) {
    asm volatile(
        "mma.sync.aligned.m16n8k8.row.col.f32.tf32.tf32.f32 "
        "{%0,%1,%2,%3}, {%4,%5,%6,%7}, {%8,%9}, {%0,%1,%2,%3};"
        : "+f"(c[0]), "+f"(c[1]), "+f"(c[2]), "+f"(c[3])
        : "r"(a0), "r"(a1), "r"(a2), "r"(a3), "r"(b0), "r"(b1));
}

__device__ __forceinline__ void ldsm4(uint32_t* r, uint32_t a) {
    asm volatile("ldmatrix.sync.aligned.m8n8.x4.shared.b16 {%0,%1,%2,%3}, [%4];"
                 : "=r"(r[0]), "=r"(r[1]), "=r"(r[2]), "=r"(r[3]) : "r"(a));
}

__device__ __forceinline__ void cp16(uint32_t saddr, const void* gaddr) {
    asm volatile("cp.async.cg.shared.global [%0], [%1], 16;" ::"r"(saddr), "l"(gaddr));
}
__device__ __forceinline__ void cp_commit() { asm volatile("cp.async.commit_group;"); }

__device__ __forceinline__ uint32_t smem_u32(const void* p) {
    uint32_t a;
    asm("{ .reg .u64 t; cvta.to.shared.u64 t, %1; cvt.u32.u64 %0, t; }" : "=r"(a) : "l"(p));
    return a;
}

// ---------------- batched weight transpose + RNA round ----------------
__global__ void transpose_all(const float* __restrict__ src, float* __restrict__ dst,
                              int K, int N, long sstride, long dstride) {
    int lz = blockIdx.z;
    src += (long)lz * sstride;
    dst += (long)lz * dstride;
    __shared__ float tl[32][33];
    int n0 = blockIdx.x * 32, k0 = blockIdx.y * 32;
    int tx = threadIdx.x, ty = threadIdx.y;
#pragma unroll
    for (int j = 0; j < 32; j += 8) tl[ty + j][tx] = src[(long)(k0 + ty + j) * N + n0 + tx];
    __syncthreads();
#pragma unroll
    for (int j = 0; j < 32; j += 8)
        dst[(long)(n0 + ty + j) * K + k0 + tx] = rna_f(tl[tx][ty + j]);
}

// ---------------- embedding + positional encoding (RNA-rounded output) ----------------
__global__ void embed_kernel(const int* __restrict__ ids, const float* __restrict__ emb,
                             const float* __restrict__ pe, float* __restrict__ x) {
    long idx = (long)blockIdx.x * blockDim.x + threadIdx.x;
    if (idx >= (long)TOKS * EDIM) return;
    int tok = (int)(idx / EDIM);
    int e = (int)(idx - (long)tok * EDIM);
    int s = tok & (SEQ - 1);
    x[idx] = rna_f(emb[(long)ids[tok] * EDIM + e] + pe[s * EDIM + e]);
}

// ---------------- TF32 mma GEMM (round-6 config: BK=32, 3-stage, 256thr, 2 CTA/SM) --
struct Trip {
    const float* W;   // [N][K] transposed, pre-rounded
    const float* b;
    float* C;
    int mode;         // 0 plain, 1 relu+rna, 2 rna, 3 rna + V^T scatter
};

#define GSTAGE 36864  // A 18432 + B 18432
#define GEMM_SMEM (3 * GSTAGE)

__global__ __launch_bounds__(256, 2) void gemm_lds(const float* __restrict__ A,
                                                   Trip t0, Trip t1, Trip t2,
                                                   int N, int K) {
    extern __shared__ __align__(128) char smc[];
    uint32_t sb = smem_u32(smc);
    int t = threadIdx.x, l = t & 31, warp = t >> 5;
    int wm = warp >> 2, wn = warp & 3;
    int g = l >> 2, tg = l & 3;

    int z = blockIdx.z;
    Trip tr = (z == 0) ? t0 : (z == 1) ? t1 : t2;
    long bm = blockIdx.y, bn = blockIdx.x;
    const float* Ab = A + bm * 128 * (long)K;
    const float* Bb = tr.W + bn * 128 * (long)K;

    int ra = t >> 3, seg = t & 7;

    uint32_t aOff[4], bOff[2];
#pragma unroll
    for (int mf = 0; mf < 4; mf++)
        aOff[mf] = (uint32_t)((wm * 64 + mf * 16 + (l & 7) + ((l >> 3) & 1) * 8) * 144 +
                              (l >> 4) * 16);
#pragma unroll
    for (int j = 0; j < 2; j++)
        bOff[j] = (uint32_t)(18432 +
                             (wn * 32 + (2 * j + (l >> 4)) * 8 + (l & 7)) * 144 +
                             ((l >> 3) & 1) * 16);

    float acc[4][4][4];
#pragma unroll
    for (int i = 0; i < 4; i++)
#pragma unroll
        for (int j = 0; j < 4; j++)
#pragma unroll
            for (int q = 0; q < 4; q++) acc[i][j][q] = 0.f;

    int niter = K >> 5;

#pragma unroll
    for (int st = 0; st < 2; st++) {
        uint32_t sA = sb + st * GSTAGE, sB = sA + 18432;
        int k0 = st * 32;
#pragma unroll
        for (int p = 0; p < 4; p++) {
            int r = ra + p * 32;
            cp16(sA + (uint32_t)(r * 144 + seg * 16), Ab + (long)r * K + k0 + seg * 4);
            cp16(sB + (uint32_t)(r * 144 + seg * 16), Bb + (long)r * K + k0 + seg * 4);
        }
        cp_commit();
    }

    int s = 0;
    for (int it = 0; it < niter; it++) {
        asm volatile("cp.async.wait_group 1;");
        __syncthreads();

        int jn = it + 2;
        if (jn < niter) {
            int s2 = jn % 3;
            uint32_t sA2 = sb + s2 * GSTAGE, sB2 = sA2 + 18432;
            int k0 = jn * 32;
#pragma unroll
            for (int p = 0; p < 4; p++) {
                int r = ra + p * 32;
                cp16(sA2 + (uint32_t)(r * 144 + seg * 16), Ab + (long)r * K + k0 + seg * 4);
                cp16(sB2 + (uint32_t)(r * 144 + seg * 16), Bb + (long)r * K + k0 + seg * 4);
            }
        }
        cp_commit();

        uint32_t sA = sb + s * GSTAGE;
#pragma unroll
        for (int kk = 0; kk < 4; kk++) {
            uint32_t af[4][4], bf[4][2];
#pragma unroll
            for (int mf = 0; mf < 4; mf++) ldsm4(af[mf], sA + aOff[mf] + kk * 32);
#pragma unroll
            for (int j = 0; j < 2; j++) ldsm4(&bf[2 * j][0], sA + bOff[j] + kk * 32);
#pragma unroll
            for (int mf = 0; mf < 4; mf++)
#pragma unroll
                for (int nf = 0; nf < 4; nf++)
                    mma8(acc[mf][nf], af[mf][0], af[mf][1], af[mf][2], af[mf][3],
                         bf[nf][0], bf[nf][1]);
        }
        s = (s == 2) ? 0 : s + 1;
    }

    int mode = tr.mode;
    const float* bias = tr.b;
    float* C = tr.C;
#pragma unroll
    for (int mf = 0; mf < 4; mf++) {
        int r0 = (int)bm * 128 + wm * 64 + mf * 16 + g;
#pragma unroll
        for (int nf = 0; nf < 4; nf++) {
            int c0 = (int)bn * 128 + wn * 32 + nf * 8 + 2 * tg;
            float bb0 = bias[c0], bb1 = bias[c0 + 1];
            float v0 = acc[mf][nf][0] + bb0;
            float v1 = acc[mf][nf][1] + bb1;
            float v2 = acc[mf][nf][2] + bb0;
            float v3 = acc[mf][nf][3] + bb1;
            if (mode == 1) {
                v0 = rna_f(fmaxf(v0, 0.f)); v1 = rna_f(fmaxf(v1, 0.f));
                v2 = rna_f(fmaxf(v2, 0.f)); v3 = rna_f(fmaxf(v3, 0.f));
            } else if (mode >= 2) {
                v0 = rna_f(v0); v1 = rna_f(v1); v2 = rna_f(v2); v3 = rna_f(v3);
            }
            if (mode == 3) {
                int b_ = r0 >> 10, sp = r0 & 1023;
                int h0 = c0 >> 6, d0 = c0 & 63;
                long vb = ((long)(b_ * NH + h0) * HD + d0) * SEQ + sp;
                C[vb] = v0;
                C[vb + SEQ] = v1;
                C[vb + 8] = v2;
                C[vb + SEQ + 8] = v3;
            } else {
                *(float2*)&C[(long)r0 * N + c0] = make_float2(v0, v1);
                *(float2*)&C[(long)(r0 + 8) * N + c0] = make_float2(v2, v3);
            }
        }
    }
}

// ---------------- fused flash attention, q-tile 128, 3-stage K/V, 1 barrier/iter ----
// smem (bytes): Q[128][68] @0, P[128][68] @34816, mask[1024] @69632,
// stages @73728 + s*34816 (s in 0..2): K[64][68] then V^T[64][68].  total 178176
#define ATT_SMEM 178176

__global__ __launch_bounds__(256) void attn_kernel(const float* __restrict__ Q,
                                                   const float* __restrict__ Kp,
                                                   const float* __restrict__ Vt,
                                                   const int* __restrict__ mask,
                                                   float* __restrict__ O) {
    extern __shared__ __align__(128) char smc[];
    uint32_t sb = smem_u32(smc);
    float* mAdd = (float*)(smc + 69632);

    int t = threadIdx.x, l = t & 31, warp = t >> 5;
    int g = l >> 2, tg = l & 3;
    int b = blockIdx.z, h = blockIdx.y, qt = blockIdx.x;
    int rq = warp * 16;

    const float* Qb = Q + ((long)(b * SEQ + qt * 128)) * EDIM + h * HD;
    const float* Kb = Kp + ((long)(b * SEQ)) * EDIM + h * HD;
    const float* Vb = Vt + ((long)(b * NH + h) * HD) * SEQ;

    uint32_t aQoff = (uint32_t)((rq + (l & 7) + ((l >> 3) & 1) * 8) * 272 + (l >> 4) * 16);
    uint32_t bOff[4];
#pragma unroll
    for (int j = 0; j < 4; j++)
        bOff[j] = (uint32_t)(((2 * j + (l >> 4)) * 8 + (l & 7)) * 272 + ((l >> 3) & 1) * 16);

    // Q load (group 0)
    {
        int r = t >> 1, s0 = (t & 1) * 8;
#pragma unroll
        for (int j = 0; j < 8; j++)
            cp16(sb + (uint32_t)(r * 272 + (s0 + j) * 16), Qb + (long)r * EDIM + (s0 + j) * 4);
        cp_commit();
    }
    for (int i = t; i < SEQ; i += 256) mAdd[i] = mask[b * SEQ + i] ? 0.f : -1e30f;

    // prologue: stages for kt=0,1
#pragma unroll
    for (int st = 0; st < 2; st++) {
        uint32_t Kst = sb + 73728 + st * 34816, Vst = Kst + 17408;
        int r = t >> 2, j0 = (t & 3) * 4;
        const float* Ks = Kb + (long)(st * 64) * EDIM;
        const float* Vs = Vb + st * 64;
#pragma unroll
        for (int j = 0; j < 4; j++) {
            cp16(Kst + (uint32_t)(r * 272 + (j0 + j) * 16), Ks + (long)r * EDIM + (j0 + j) * 4);
            cp16(Vst + (uint32_t)(r * 272 + (j0 + j) * 16), Vs + (long)r * SEQ + (j0 + j) * 4);
        }
        cp_commit();
    }

    float m_[2] = {-INFINITY, -INFINITY};
    float l_[2] = {0.f, 0.f};
    float o[8][4];
#pragma unroll
    for (int nf = 0; nf < 8; nf++)
#pragma unroll
        for (int q = 0; q < 4; q++) o[nf][q] = 0.f;

    for (int kt = 0; kt < 16; kt++) {
        int s = kt % 3;
        uint32_t Kst = sb + 73728 + s * 34816, Vst = Kst + 17408;
        asm volatile("cp.async.wait_group 1;");
        __syncthreads();   // single barrier per iteration

        // early prefetch of kt+2 into stage (kt+2)%3 (disjoint from stages kt, kt+1)
        int jn = kt + 2;
        if (jn < 16) {
            int s2 = jn % 3;
            uint32_t Kp2 = sb + 73728 + s2 * 34816, Vp2 = Kp2 + 17408;
            int r = t >> 2, j0 = (t & 3) * 4;
            const float* Ks = Kb + (long)(jn * 64) * EDIM;
            const float* Vs = Vb + jn * 64;
#pragma unroll
            for (int j = 0; j < 4; j++) {
                cp16(Kp2 + (uint32_t)(r * 272 + (j0 + j) * 16), Ks + (long)r * EDIM + (j0 + j) * 4);
                cp16(Vp2 + (uint32_t)(r * 272 + (j0 + j) * 16), Vs + (long)r * SEQ + (j0 + j) * 4);
            }
        }
        cp_commit();

        // ---- S = Q K^T ----
        float sc[8][4];
#pragma unroll
        for (int nf = 0; nf < 8; nf++)
#pragma unroll
            for (int q = 0; q < 4; q++) sc[nf][q] = 0.f;
#pragma unroll
        for (int kk = 0; kk < 8; kk++) {
            uint32_t af[4], bf[8][2];
            ldsm4(af, sb + aQoff + kk * 32);
#pragma unroll
            for (int j = 0; j < 4; j++) ldsm4(&bf[2 * j][0], Kst + bOff[j] + kk * 32);
#pragma unroll
            for (int nf = 0; nf < 8; nf++)
                mma8(sc[nf], af[0], af[1], af[2], af[3], bf[nf][0], bf[nf][1]);
        }

        // ---- mask + online softmax ----
        float rmax0 = -INFINITY, rmax1 = -INFINITY;
#pragma unroll
        for (int nf = 0; nf < 8; nf++) {
            int c0 = kt * 64 + nf * 8 + 2 * tg;
            float ma = mAdd[c0], mb = mAdd[c0 + 1];
            sc[nf][0] = sc[nf][0] * 0.125f + ma;
            sc[nf][1] = sc[nf][1] * 0.125f + mb;
            sc[nf][2] = sc[nf][2] * 0.125f + ma;
            sc[nf][3] = sc[nf][3] * 0.125f + mb;
            rmax0 = fmaxf(rmax0, fmaxf(sc[nf][0], sc[nf][1]));
            rmax1 = fmaxf(rmax1, fmaxf(sc[nf][2], sc[nf][3]));
        }
        rmax0 = fmaxf(rmax0, __shfl_xor_sync(0xffffffffu, rmax0, 1));
        rmax0 = fmaxf(rmax0, __shfl_xor_sync(0xffffffffu, rmax0, 2));
        rmax1 = fmaxf(rmax1, __shfl_xor_sync(0xffffffffu, rmax1, 1));
        rmax1 = fmaxf(rmax1, __shfl_xor_sync(0xffffffffu, rmax1, 2));
        float mn0 = fmaxf(m_[0], rmax0), mn1 = fmaxf(m_[1], rmax1);
        float cf0 = __expf(m_[0] - mn0), cf1 = __expf(m_[1] - mn1);
        float rs0 = 0.f, rs1 = 0.f;
#pragma unroll
        for (int nf = 0; nf < 8; nf++) {
            sc[nf][0] = __expf(sc[nf][0] - mn0);
            sc[nf][1] = __expf(sc[nf][1] - mn0);
            sc[nf][2] = __expf(sc[nf][2] - mn1);
            sc[nf][3] = __expf(sc[nf][3] - mn1);
            rs0 += sc[nf][0] + sc[nf][1];
            rs1 += sc[nf][2] + sc[nf][3];
        }
        rs0 += __shfl_xor_sync(0xffffffffu, rs0, 1);
        rs0 += __shfl_xor_sync(0xffffffffu, rs0, 2);
        rs1 += __shfl_xor_sync(0xffffffffu, rs1, 1);
        rs1 += __shfl_xor_sync(0xffffffffu, rs1, 2);
        l_[0] = l_[0] * cf0 + rs0;
        l_[1] = l_[1] * cf1 + rs1;
        m_[0] = mn0; m_[1] = mn1;
#pragma unroll
        for (int nf = 0; nf < 8; nf++) {
            o[nf][0] *= cf0; o[nf][1] *= cf0;
            o[nf][2] *= cf1; o[nf][3] *= cf1;
        }

        // ---- P -> smem (per-warp private rows), PV ----
#pragma unroll
        for (int nf = 0; nf < 8; nf++) {
            int pc = nf * 8 + 2 * tg;
            uint32_t a0 = sb + 34816 + (uint32_t)((rq + g) * 272 + pc * 4);
            uint32_t a1 = sb + 34816 + (uint32_t)((rq + 8 + g) * 272 + pc * 4);
            asm volatile("st.shared.v2.b32 [%0], {%1, %2};" ::"r"(a0),
                         "r"(f2tf32(sc[nf][0])), "r"(f2tf32(sc[nf][1])) : "memory");
            asm volatile("st.shared.v2.b32 [%0], {%1, %2};" ::"r"(a1),
                         "r"(f2tf32(sc[nf][2])), "r"(f2tf32(sc[nf][3])) : "memory");
        }
        __syncwarp();
#pragma unroll
        for (int kk = 0; kk < 8; kk++) {
            uint32_t af[4], bf[8][2];
            ldsm4(af, sb + 34816 + aQoff + kk * 32);
#pragma unroll
            for (int j = 0; j < 4; j++) ldsm4(&bf[2 * j][0], Vst + bOff[j] + kk * 32);
#pragma unroll
            for (int nf = 0; nf < 8; nf++)
                mma8(o[nf], af[0], af[1], af[2], af[3], bf[nf][0], bf[nf][1]);
        }
    }

    float il0 = 1.f / l_[0], il1 = 1.f / l_[1];
#pragma unroll
    for (int nf = 0; nf < 8; nf++) {
        long rowg = (long)(b * SEQ + qt * 128 + rq + g);
        int colg = h * HD + nf * 8 + 2 * tg;
        O[rowg * EDIM + colg] = rna_f(o[nf][0] * il0);
        O[rowg * EDIM + colg + 1] = rna_f(o[nf][1] * il0);
        O[(rowg + 8) * EDIM + colg] = rna_f(o[nf][2] * il1);
        O[(rowg + 8) * EDIM + colg + 1] = rna_f(o[nf][3] * il1);
    }
}

// ---------------- fused residual add + LayerNorm, float4, 192 threads ----------------
__global__ __launch_bounds__(192) void ln_res_kernel(const float* __restrict__ x,
                                                     const float* __restrict__ y,
                                                     const float* __restrict__ gam,
                                                     const float* __restrict__ bet,
                                                     float* __restrict__ out) {
    int row = blockIdx.x, t = threadIdx.x;
    const float4* xr = (const float4*)(x + (long)row * EDIM);
    const float4* yr = (const float4*)(y + (long)row * EDIM);
    float4 a = xr[t], b4 = yr[t];
    float v0 = a.x + b4.x, v1 = a.y + b4.y, v2 = a.z + b4.z, v3 = a.w + b4.w;
    float s1 = v0 + v1 + v2 + v3;
    float s2 = v0 * v0 + v1 * v1 + v2 * v2 + v3 * v3;
    __shared__ float sh[2][6];
    int lane = t & 31, w = t >> 5;
#pragma unroll
    for (int off = 16; off; off >>= 1) {
        s1 += __shfl_xor_sync(0xffffffffu, s1, off);
        s2 += __shfl_xor_sync(0xffffffffu, s2, off);
    }
    if (!lane) { sh[0][w] = s1; sh[1][w] = s2; }
    __syncthreads();
    float a1 = 0.f, a2 = 0.f;
#pragma unroll
    for (int i = 0; i < 6; i++) { a1 += sh[0][i]; a2 += sh[1][i]; }
    float mean = a1 * (1.f / EDIM);
    float var = a2 * (1.f / EDIM) - mean * mean;
    float rstd = rsqrtf(var + 1e-5f);
    float4 gg = ((const float4*)gam)[t];
    float4 bb = ((const float4*)bet)[t];
    float4 o;
    o.x = rna_f((v0 - mean) * rstd * gg.x + bb.x);
    o.y = rna_f((v1 - mean) * rstd * gg.y + bb.y);
    o.z = rna_f((v2 - mean) * rstd * gg.z + bb.z);
    o.w = rna_f((v3 - mean) * rstd * gg.w + bb.w);
    ((float4*)(out + (long)row * EDIM))[t] = o;
}

// ---------------- mean pool ----------------
__global__ void pool_kernel(const float* __restrict__ x, float* __restrict__ p) {
    int idx = blockIdx.x * blockDim.x + threadIdx.x;
    if (idx >= 8 * (EDIM / 4)) return;
    int b = idx / (EDIM / 4), e4 = idx % (EDIM / 4);
    const float4* xb = (const float4*)(x + (long)b * SEQ * EDIM) + e4;
    float4 s = make_float4(0.f, 0.f, 0.f, 0.f);
    for (int si = 0; si < SEQ; si++) {
        float4 v = xb[(long)si * (EDIM / 4)];
        s.x += v.x; s.y += v.y; s.z += v.z; s.w += v.w;
    }
    s.x *= (1.f / SEQ); s.y *= (1.f / SEQ); s.z *= (1.f / SEQ); s.w *= (1.f / SEQ);
    ((float4*)p)[idx] = s;
}

// ---------------- classifier ----------------
__global__ void cls_kernel(const float* __restrict__ p, const float* __restrict__ Wc,
                           const float* __restrict__ bc, float* __restrict__ out) {
    int w = threadIdx.x >> 5, lane = threadIdx.x & 31;
    int b = w >> 1, c = w & 1;
    float s = 0.f;
    for (int e = lane; e < EDIM; e += 32) s += p[b * EDIM + e] * Wc[e * 2 + c];
#pragma unroll
    for (int off = 16; off; off >>= 1) s += __shfl_xor_sync(0xffffffffu, s, off);
    if (!lane) out[b * 2 + c] = s + bc[c];
}

// ---------------- launch ----------------
extern "C" void kernel_launch(void* const* d_in, const int* in_sizes, int n_in,
                              void* d_out, int out_size) {
    (void)in_sizes; (void)n_in; (void)out_size;
    const int* ids = (const int*)d_in[0];
    const int* amask = (const int*)d_in[1];
    const float* emb = (const float*)d_in[2];
    const float* pe = (const float*)d_in[3];
    const float* Wq = (const float*)d_in[4];
    const float* bq = (const float*)d_in[5];
    const float* Wk = (const float*)d_in[6];
    const float* bk = (const float*)d_in[7];
    const float* Wv = (const float*)d_in[8];
    const float* bv = (const float*)d_in[9];
    const float* Wo = (const float*)d_in[10];
    const float* bo = (const float*)d_in[11];
    const float* l1g = (const float*)d_in[12];
    const float* l1b = (const float*)d_in[13];
    const float* W1 = (const float*)d_in[14];
    const float* b1 = (const float*)d_in[15];
    const float* W2 = (const float*)d_in[16];
    const float* b2 = (const float*)d_in[17];
    const float* l2g = (const float*)d_in[18];
    const float* l2b = (const float*)d_in[19];
    const float* Wc = (const float*)d_in[20];
    const float* bc = (const float*)d_in[21];
    float* out = (float*)d_out;

    float *x, *q, *k, *v, *att, *tmp, *ffn, *pl, *wt;
    cudaGetSymbolAddress((void**)&x, g_x);
    cudaGetSymbolAddress((void**)&q, g_q);
    cudaGetSymbolAddress((void**)&k, g_k);
    cudaGetSymbolAddress((void**)&v, g_v);
    cudaGetSymbolAddress((void**)&att, g_att);
    cudaGetSymbolAddress((void**)&tmp, g_t);
    cudaGetSymbolAddress((void**)&ffn, g_ffn);
    cudaGetSymbolAddress((void**)&pl, g_pool);
    cudaGetSymbolAddress((void**)&wt, g_wt);

    cudaFuncSetAttribute(gemm_lds, cudaFuncAttributeMaxDynamicSharedMemorySize, GEMM_SMEM);
    cudaFuncSetAttribute(attn_kernel, cudaFuncAttributeMaxDynamicSharedMemorySize, ATT_SMEM);

    // one-time per launch: transpose + RNA-round all weights (batched over layers)
    dim3 tb(32, 8);
    transpose_all<<<dim3(EDIM / 32, EDIM / 32, NLAYER), tb>>>(Wq, wt + 0L * EE, EDIM, EDIM,
                                                             (long)EE, (long)WT_PER_LAYER);
    transpose_all<<<dim3(EDIM / 32, EDIM / 32, NLAYER), tb>>>(Wk, wt + 1L * EE, EDIM, EDIM,
                                                             (long)EE, (long)WT_PER_LAYER);
    transpose_all<<<dim3(EDIM / 32, EDIM / 32, NLAYER), tb>>>(Wv, wt + 2L * EE, EDIM, EDIM,
                                                             (long)EE, (long)WT_PER_LAYER);
    transpose_all<<<dim3(EDIM / 32, EDIM / 32, NLAYER), tb>>>(Wo, wt + 3L * EE, EDIM, EDIM,
                                                             (long)EE, (long)WT_PER_LAYER);
    transpose_all<<<dim3(FDIM / 32, EDIM / 32, NLAYER), tb>>>(W1, wt + 4L * EE, EDIM, FDIM,
                                                             (long)EF, (long)WT_PER_LAYER);
    transpose_all<<<dim3(EDIM / 32, FDIM / 32, NLAYER), tb>>>(W2, wt + 4L * EE + EF, FDIM, EDIM,
                                                             (long)EF, (long)WT_PER_LAYER);

    embed_kernel<<<(TOKS * EDIM + 255) / 256, 256>>>(ids, emb, pe, x);

    for (int l = 0; l < NLAYER; l++) {
        long boff = (long)l * EDIM;
        float* base = wt + (long)l * WT_PER_LAYER;
        Trip tq = {base + 0L * EE, bq + boff, q, 2};
        Trip tk = {base + 1L * EE, bk + boff, k, 2};
        Trip tv = {base + 2L * EE, bv + boff, v, 3};
        gemm_lds<<<dim3(6, 64, 3), 256, GEMM_SMEM>>>(x, tq, tk, tv, EDIM, EDIM);
        attn_kernel<<<dim3(8, 12, 8), 256, ATT_SMEM>>>(q, k, v, amask, att);
        Trip to = {base + 3L * EE, bo + boff, tmp, 0};
        gemm_lds<<<dim3(6, 64, 1), 256, GEMM_SMEM>>>(att, to, to, to, EDIM, EDIM);
        ln_res_kernel<<<TOKS, 192>>>(x, tmp, l1g + boff, l1b + boff, x);
        Trip t1 = {base + 4L * EE, b1 + (long)l * FDIM, ffn, 1};
        gemm_lds<<<dim3(24, 64, 1), 256, GEMM_SMEM>>>(x, t1, t1, t1, FDIM, EDIM);
        Trip t2 = {base + 4L * EE + EF, b2 + boff, tmp, 0};
        gemm_lds<<<dim3(6, 64, 1), 256, GEMM_SMEM>>>(ffn, t2, t2, t2, EDIM, FDIM);
        ln_res_kernel<<<TOKS, 192>>>(x, tmp, l2g + boff, l2b + boff, x);
    }

    pool_kernel<<<(8 * EDIM / 4 + 255) / 256, 256>>>(x, pl);
    cls_kernel<<<1, 512>>>(pl, Wc, bc, out);
}

// round 13
// speedup vs baseline: 1.6253x; 1.4456x over previous
#include <cuda_runtime.h>
#include <cuda_fp16.h>
#include <cstdint>

#define TOKS 8192
#define EDIM 768
#define FDIM 3072
#define SEQ  1024
#define NH   12
#define HD   64
#define NLAYER 6

#define EE (EDIM * EDIM)
#define EF (EDIM * FDIM)
#define WT_PER_LAYER (4 * EE + 2 * EF)

// ---------------- scratch (device globals; no allocation) ----------------
__device__ float g_x[TOKS * EDIM];          // fp32 residual stream
__device__ __half g_xh[TOKS * EDIM];        // fp16 copy for GEMM A
__device__ float g_q[TOKS * EDIM];
__device__ float g_k[TOKS * EDIM];
__device__ float g_v[TOKS * EDIM];          // V^T: [b][h][hd][seq]
__device__ __half g_atth[TOKS * EDIM];      // attention out (fp16, feeds O-proj)
__device__ float g_t[TOKS * EDIM];
__device__ __half g_ffnh[TOKS * FDIM];      // relu out (fp16, feeds FFN2)
__device__ float g_pool[8 * EDIM];
__device__ __half g_wt[(long)NLAYER * WT_PER_LAYER];  // transposed fp16 weights

// ---------------- helpers ----------------
__device__ __forceinline__ uint32_t f2tf32(float x) {
    uint32_t r;
    asm("cvt.rna.tf32.f32 %0, %1;" : "=r"(r) : "f"(x));
    return r;
}
__device__ __forceinline__ float rna_f(float x) { return __uint_as_float(f2tf32(x)); }

// tf32 m16n8k8 (attention path)
__device__ __forceinline__ void mma8(float* c, uint32_t a0, uint32_t a1, uint32_t a2, uint32_t a3,
                                     uint32_t b0, uint32_t b1) {
    asm volatile(
        "mma.sync.aligned.m16n8k8.row.col.f32.tf32.tf32.f32 "
        "{%0,%1,%2,%3}, {%4,%5,%6,%7}, {%8,%9}, {%0,%1,%2,%3};"
        : "+f"(c[0]), "+f"(c[1]), "+f"(c[2]), "+f"(c[3])
        : "r"(a0), "r"(a1), "r"(a2), "r"(a3), "r"(b0), "r"(b1));
}

// fp16 m16n8k16 (GEMM path)
__device__ __forceinline__ void mma16(float* c, uint32_t a0, uint32_t a1, uint32_t a2, uint32_t a3,
                                      uint32_t b0, uint32_t b1) {
    asm volatile(
        "mma.sync.aligned.m16n8k16.row.col.f32.f16.f16.f32 "
        "{%0,%1,%2,%3}, {%4,%5,%6,%7}, {%8,%9}, {%0,%1,%2,%3};"
        : "+f"(c[0]), "+f"(c[1]), "+f"(c[2]), "+f"(c[3])
        : "r"(a0), "r"(a1), "r"(a2), "r"(a3), "r"(b0), "r"(b1));
}

__device__ __forceinline__ void ldsm4(uint32_t* r, uint32_t a) {
    asm volatile("ldmatrix.sync.aligned.m8n8.x4.shared.b16 {%0,%1,%2,%3}, [%4];"
                 : "=r"(r[0]), "=r"(r[1]), "=r"(r[2]), "=r"(r[3]) : "r"(a));
}

__device__ __forceinline__ void cp16(uint32_t saddr, const void* gaddr) {
    asm volatile("cp.async.cg.shared.global [%0], [%1], 16;" ::"r"(saddr), "l"(gaddr));
}
__device__ __forceinline__ void cp_commit() { asm volatile("cp.async.commit_group;"); }

__device__ __forceinline__ uint32_t smem_u32(const void* p) {
    uint32_t a;
    asm("{ .reg .u64 t; cvta.to.shared.u64 t, %1; cvt.u32.u64 %0, t; }" : "=r"(a) : "l"(p));
    return a;
}

// ---------------- batched weight transpose -> fp16: dst[N][K] = (half)src[K][N]^T ----
__global__ void transpose_all(const float* __restrict__ src, __half* __restrict__ dst,
                              int K, int N, long sstride, long dstride) {
    int lz = blockIdx.z;
    src += (long)lz * sstride;
    dst += (long)lz * dstride;
    __shared__ float tl[32][33];
    int n0 = blockIdx.x * 32, k0 = blockIdx.y * 32;
    int tx = threadIdx.x, ty = threadIdx.y;
#pragma unroll
    for (int j = 0; j < 32; j += 8) tl[ty + j][tx] = src[(long)(k0 + ty + j) * N + n0 + tx];
    __syncthreads();
#pragma unroll
    for (int j = 0; j < 32; j += 8)
        dst[(long)(n0 + ty + j) * K + k0 + tx] = __float2half_rn(tl[tx][ty + j]);
}

// ---------------- embedding + positional encoding ----------------
__global__ void embed_kernel(const int* __restrict__ ids, const float* __restrict__ emb,
                             const float* __restrict__ pe, float* __restrict__ x,
                             __half* __restrict__ xh) {
    long idx = (long)blockIdx.x * blockDim.x + threadIdx.x;
    if (idx >= (long)TOKS * EDIM) return;
    int tok = (int)(idx / EDIM);
    int e = (int)(idx - (long)tok * EDIM);
    int s = tok & (SEQ - 1);
    float v = emb[(long)ids[tok] * EDIM + e] + pe[s * EDIM + e];
    x[idx] = v;
    xh[idx] = __float2half_rn(v);
}

// ---------------- fp16 mma GEMM: block 128x128, BK=64, 3-stage, 256 thr (2x4) -------
// C[M,N] = A[M,K] @ Wt[N,K]^T + bias.
// modes: 0 fp32 out, 1 relu -> half out, 2 rna fp32 out, 3 rna fp32 + V^T scatter
struct Trip {
    const __half* W;   // [N][K] transposed fp16
    const float* b;
    void* C;
    int mode;
};

#define GROW 144                 // 64 halfs (128B) + 16B pad
#define GAS (128 * GROW)         // 18432 per tensor
#define GSTAGE (2 * GAS)         // 36864
#define GEMM_SMEM (3 * GSTAGE)   // 110592

__global__ __launch_bounds__(256, 2) void gemm_h(const __half* __restrict__ A,
                                                 Trip t0, Trip t1, Trip t2,
                                                 int N, int K) {
    extern __shared__ __align__(128) char smc[];
    uint32_t sb = smem_u32(smc);
    int t = threadIdx.x, l = t & 31, warp = t >> 5;
    int wm = warp >> 2, wn = warp & 3;
    int g = l >> 2, tg = l & 3;

    int z = blockIdx.z;
    Trip tr = (z == 0) ? t0 : (z == 1) ? t1 : t2;
    long bm = blockIdx.y, bn = blockIdx.x;
    const __half* Ab = A + bm * 128 * (long)K;
    const __half* Bb = tr.W + bn * 128 * (long)K;

    int ra = t >> 3, seg = t & 7;  // 32 rows/pass (4 passes), 8 segs of 16B (=8 halfs)

    // ldmatrix offsets (bytes, relative to stage base)
    // A frag (m16n8k16): rows m0+(l&7)+((l>>3)&1)*8, col16 = (l>>4)
    uint32_t aOff[4], bOff[2];
#pragma unroll
    for (int mf = 0; mf < 4; mf++)
        aOff[mf] = (uint32_t)((wm * 64 + mf * 16 + (l & 7) + ((l >> 3) & 1) * 8) * GROW +
                              (l >> 4) * 16);
    // B frag pairs: rows n0+(l&7)+(l>>4)*8, col16 = ((l>>3)&1)
#pragma unroll
    for (int j = 0; j < 2; j++)
        bOff[j] = (uint32_t)(GAS +
                             (wn * 32 + j * 16 + (l & 7) + (l >> 4) * 8) * GROW +
                             ((l >> 3) & 1) * 16);

    float acc[4][4][4];
#pragma unroll
    for (int i = 0; i < 4; i++)
#pragma unroll
        for (int j = 0; j < 4; j++)
#pragma unroll
            for (int q = 0; q < 4; q++) acc[i][j][q] = 0.f;

    int niter = K >> 6;  // BK=64

#pragma unroll
    for (int st = 0; st < 2; st++) {
        uint32_t sA = sb + st * GSTAGE, sB = sA + GAS;
        int k0 = st * 64;
#pragma unroll
        for (int p = 0; p < 4; p++) {
            int r = ra + p * 32;
            cp16(sA + (uint32_t)(r * GROW + seg * 16), Ab + (long)r * K + k0 + seg * 8);
            cp16(sB + (uint32_t)(r * GROW + seg * 16), Bb + (long)r * K + k0 + seg * 8);
        }
        cp_commit();
    }

    int s = 0;
    for (int it = 0; it < niter; it++) {
        asm volatile("cp.async.wait_group 1;");
        __syncthreads();

        int jn = it + 2;
        if (jn < niter) {
            int s2 = jn % 3;
            uint32_t sA2 = sb + s2 * GSTAGE, sB2 = sA2 + GAS;
            int k0 = jn * 64;
#pragma unroll
            for (int p = 0; p < 4; p++) {
                int r = ra + p * 32;
                cp16(sA2 + (uint32_t)(r * GROW + seg * 16), Ab + (long)r * K + k0 + seg * 8);
                cp16(sB2 + (uint32_t)(r * GROW + seg * 16), Bb + (long)r * K + k0 + seg * 8);
            }
        }
        cp_commit();

        uint32_t sA = sb + s * GSTAGE;
#pragma unroll
        for (int kk = 0; kk < 4; kk++) {    // 4 k-steps of 16 halfs (32B each)
            uint32_t af[4][4], bf[2][4];
#pragma unroll
            for (int mf = 0; mf < 4; mf++) ldsm4(af[mf], sA + aOff[mf] + kk * 32);
#pragma unroll
            for (int j = 0; j < 2; j++) ldsm4(bf[j], sA + bOff[j] + kk * 32);
#pragma unroll
            for (int mf = 0; mf < 4; mf++) {
#pragma unroll
                for (int nf = 0; nf < 4; nf++) {
                    uint32_t b0 = bf[nf >> 1][(nf & 1) * 2];
                    uint32_t b1 = bf[nf >> 1][(nf & 1) * 2 + 1];
                    mma16(acc[mf][nf], af[mf][0], af[mf][1], af[mf][2], af[mf][3], b0, b1);
                }
            }
        }
        s = (s == 2) ? 0 : s + 1;
    }

    int mode = tr.mode;
    const float* bias = tr.b;
#pragma unroll
    for (int mf = 0; mf < 4; mf++) {
        int r0 = (int)bm * 128 + wm * 64 + mf * 16 + g;
#pragma unroll
        for (int nf = 0; nf < 4; nf++) {
            int c0 = (int)bn * 128 + wn * 32 + nf * 8 + 2 * tg;
            float bb0 = bias[c0], bb1 = bias[c0 + 1];
            float v0 = acc[mf][nf][0] + bb0;
            float v1 = acc[mf][nf][1] + bb1;
            float v2 = acc[mf][nf][2] + bb0;
            float v3 = acc[mf][nf][3] + bb1;
            if (mode == 1) {
                __half* Ch = (__half*)tr.C;
                *(\
__half2*)&Ch[(long)r0 * N + c0] = __floats2half2_rn(fmaxf(v0, 0.f), fmaxf(v1, 0.f));
                *(__half2*)&Ch[(long)(r0 + 8) * N + c0] =
                    __floats2half2_rn(fmaxf(v2, 0.f), fmaxf(v3, 0.f));
            } else if (mode == 3) {
                float* C = (float*)tr.C;
                int b_ = r0 >> 10, sp = r0 & 1023;
                int h0 = c0 >> 6, d0 = c0 & 63;
                long vb = ((long)(b_ * NH + h0) * HD + d0) * SEQ + sp;
                C[vb] = rna_f(v0);
                C[vb + SEQ] = rna_f(v1);
                C[vb + 8] = rna_f(v2);
                C[vb + SEQ + 8] = rna_f(v3);
            } else {
                float* C = (float*)tr.C;
                if (mode == 2) {
                    v0 = rna_f(v0); v1 = rna_f(v1); v2 = rna_f(v2); v3 = rna_f(v3);
                }
                *(float2*)&C[(long)r0 * N + c0] = make_float2(v0, v1);
                *(float2*)&C[(long)(r0 + 8) * N + c0] = make_float2(v2, v3);
            }
        }
    }
}

// ---------------- fused flash attention (TF32), q-tile 128, 2-stage K/V -------------
// smem (bytes): Q[128][68] @0, P[128][68] @34816, mask[1024] @69632,
// stages @73728 + s*34816 : K[64][68] then V^T[64][68].  total 143360
#define ATT_SMEM 143360

__global__ __launch_bounds__(256) void attn_kernel(const float* __restrict__ Q,
                                                   const float* __restrict__ Kp,
                                                   const float* __restrict__ Vt,
                                                   const int* __restrict__ mask,
                                                   __half* __restrict__ O) {
    extern __shared__ __align__(128) char smc[];
    uint32_t sb = smem_u32(smc);
    float* mAdd = (float*)(smc + 69632);

    int t = threadIdx.x, l = t & 31, warp = t >> 5;
    int g = l >> 2, tg = l & 3;
    int b = blockIdx.z, h = blockIdx.y, qt = blockIdx.x;
    int rq = warp * 16;

    const float* Qb = Q + ((long)(b * SEQ + qt * 128)) * EDIM + h * HD;
    const float* Kb = Kp + ((long)(b * SEQ)) * EDIM + h * HD;
    const float* Vb = Vt + ((long)(b * NH + h) * HD) * SEQ;

    uint32_t aQoff = (uint32_t)((rq + (l & 7) + ((l >> 3) & 1) * 8) * 272 + (l >> 4) * 16);
    uint32_t bOff[4];
#pragma unroll
    for (int j = 0; j < 4; j++)
        bOff[j] = (uint32_t)(((2 * j + (l >> 4)) * 8 + (l & 7)) * 272 + ((l >> 3) & 1) * 16);

    {
        int r = t >> 1, s0 = (t & 1) * 8;
#pragma unroll
        for (int j = 0; j < 8; j++)
            cp16(sb + (uint32_t)(r * 272 + (s0 + j) * 16), Qb + (long)r * EDIM + (s0 + j) * 4);
        cp_commit();
    }
    for (int i = t; i < SEQ; i += 256) mAdd[i] = mask[b * SEQ + i] ? 0.f : -1e30f;

#pragma unroll
    for (int st = 0; st < 2; st++) {
        uint32_t Kst = sb + 73728 + st * 34816, Vst = Kst + 17408;
        int r = t >> 2, j0 = (t & 3) * 4;
        const float* Ks = Kb + (long)(st * 64) * EDIM;
        const float* Vs = Vb + st * 64;
#pragma unroll
        for (int j = 0; j < 4; j++) {
            cp16(Kst + (uint32_t)(r * 272 + (j0 + j) * 16), Ks + (long)r * EDIM + (j0 + j) * 4);
            cp16(Vst + (uint32_t)(r * 272 + (j0 + j) * 16), Vs + (long)r * SEQ + (j0 + j) * 4);
        }
        cp_commit();
    }

    float m_[2] = {-INFINITY, -INFINITY};
    float l_[2] = {0.f, 0.f};
    float o[8][4];
#pragma unroll
    for (int nf = 0; nf < 8; nf++)
#pragma unroll
        for (int q = 0; q < 4; q++) o[nf][q] = 0.f;

    for (int kt = 0; kt < 16; kt++) {
        int s = kt & 1;
        uint32_t Kst = sb + 73728 + s * 34816, Vst = Kst + 17408;
        asm volatile("cp.async.wait_group 1;");
        __syncthreads();

        float sc[8][4];
#pragma unroll
        for (int nf = 0; nf < 8; nf++)
#pragma unroll
            for (int q = 0; q < 4; q++) sc[nf][q] = 0.f;
#pragma unroll
        for (int kk = 0; kk < 8; kk++) {
            uint32_t af[4], bf[8][2];
            ldsm4(af, sb + aQoff + kk * 32);
#pragma unroll
            for (int j = 0; j < 4; j++) ldsm4(&bf[2 * j][0], Kst + bOff[j] + kk * 32);
#pragma unroll
            for (int nf = 0; nf < 8; nf++)
                mma8(sc[nf], af[0], af[1], af[2], af[3], bf[nf][0], bf[nf][1]);
        }

        float rmax0 = -INFINITY, rmax1 = -INFINITY;
#pragma unroll
        for (int nf = 0; nf < 8; nf++) {
            int c0 = kt * 64 + nf * 8 + 2 * tg;
            float ma = mAdd[c0], mb = mAdd[c0 + 1];
            sc[nf][0] = sc[nf][0] * 0.125f + ma;
            sc[nf][1] = sc[nf][1] * 0.125f + mb;
            sc[nf][2] = sc[nf][2] * 0.125f + ma;
            sc[nf][3] = sc[nf][3] * 0.125f + mb;
            rmax0 = fmaxf(rmax0, fmaxf(sc[nf][0], sc[nf][1]));
            rmax1 = fmaxf(rmax1, fmaxf(sc[nf][2], sc[nf][3]));
        }
        rmax0 = fmaxf(rmax0, __shfl_xor_sync(0xffffffffu, rmax0, 1));
        rmax0 = fmaxf(rmax0, __shfl_xor_sync(0xffffffffu, rmax0, 2));
        rmax1 = fmaxf(rmax1, __shfl_xor_sync(0xffffffffu, rmax1, 1));
        rmax1 = fmaxf(rmax1, __shfl_xor_sync(0xffffffffu, rmax1, 2));
        float mn0 = fmaxf(m_[0], rmax0), mn1 = fmaxf(m_[1], rmax1);
        float cf0 = __expf(m_[0] - mn0), cf1 = __expf(m_[1] - mn1);
        float rs0 = 0.f, rs1 = 0.f;
#pragma unroll
        for (int nf = 0; nf < 8; nf++) {
            sc[nf][0] = __expf(sc[nf][0] - mn0);
            sc[nf][1] = __expf(sc[nf][1] - mn0);
            sc[nf][2] = __expf(sc[nf][2] - mn1);
            sc[nf][3] = __expf(sc[nf][3] - mn1);
            rs0 += sc[nf][0] + sc[nf][1];
            rs1 += sc[nf][2] + sc[nf][3];
        }
        rs0 += __shfl_xor_sync(0xffffffffu, rs0, 1);
        rs0 += __shfl_xor_sync(0xffffffffu, rs0, 2);
        rs1 += __shfl_xor_sync(0xffffffffu, rs1, 1);
        rs1 += __shfl_xor_sync(0xffffffffu, rs1, 2);
        l_[0] = l_[0] * cf0 + rs0;
        l_[1] = l_[1] * cf1 + rs1;
        m_[0] = mn0; m_[1] = mn1;
#pragma unroll
        for (int nf = 0; nf < 8; nf++) {
            o[nf][0] *= cf0; o[nf][1] *= cf0;
            o[nf][2] *= cf1; o[nf][3] *= cf1;
        }

#pragma unroll
        for (int nf = 0; nf < 8; nf++) {
            int pc = nf * 8 + 2 * tg;
            uint32_t a0 = sb + 34816 + (uint32_t)((rq + g) * 272 + pc * 4);
            uint32_t a1 = sb + 34816 + (uint32_t)((rq + 8 + g) * 272 + pc * 4);
            asm volatile("st.shared.v2.b32 [%0], {%1, %2};" ::"r"(a0),
                         "r"(f2tf32(sc[nf][0])), "r"(f2tf32(sc[nf][1])) : "memory");
            asm volatile("st.shared.v2.b32 [%0], {%1, %2};" ::"r"(a1),
                         "r"(f2tf32(sc[nf][2])), "r"(f2tf32(sc[nf][3])) : "memory");
        }
        __syncwarp();
#pragma unroll
        for (int kk = 0; kk < 8; kk++) {
            uint32_t af[4], bf[8][2];
            ldsm4(af, sb + 34816 + aQoff + kk * 32);
#pragma unroll
            for (int j = 0; j < 4; j++) ldsm4(&bf[2 * j][0], Vst + bOff[j] + kk * 32);
#pragma unroll
            for (int nf = 0; nf < 8; nf++)
                mma8(o[nf], af[0], af[1], af[2], af[3], bf[nf][0], bf[nf][1]);
        }
        __syncthreads();

        int jn = kt + 2;
        if (jn < 16) {
            int r = t >> 2, j0 = (t & 3) * 4;
            const float* Ks = Kb + (long)(jn * 64) * EDIM;
            const float* Vs = Vb + jn * 64;
#pragma unroll
            for (int j = 0; j < 4; j++) {
                cp16(Kst + (uint32_t)(r * 272 + (j0 + j) * 16), Ks + (long)r * EDIM + (j0 + j) * 4);
                cp16(Vst + (uint32_t)(r * 272 + (j0 + j) * 16), Vs + (long)r * SEQ + (j0 + j) * 4);
            }
        }
        cp_commit();
    }

    float il0 = 1.f / l_[0], il1 = 1.f / l_[1];
#pragma unroll
    for (int nf = 0; nf < 8; nf++) {
        long rowg = (long)(b * SEQ + qt * 128 + rq + g);
        int colg = h * HD + nf * 8 + 2 * tg;
        *(__half2*)&O[rowg * EDIM + colg] = __floats2half2_rn(o[nf][0] * il0, o[nf][1] * il0);
        *(__half2*)&O[(rowg + 8) * EDIM + colg] = __floats2half2_rn(o[nf][2] * il1, o[nf][3] * il1);
    }
}

// ---------------- fused residual add + LayerNorm (fp32 + fp16 outputs) --------------
__global__ __launch_bounds__(192) void ln_res_kernel(const float* __restrict__ x,
                                                     const float* __restrict__ y,
                                                     const float* __restrict__ gam,
                                                     const float* __restrict__ bet,
                                                     float* __restrict__ out,
                                                     __half* __restrict__ outh) {
    int row = blockIdx.x, t = threadIdx.x;
    const float4* xr = (const float4*)(x + (long)row * EDIM);
    const float4* yr = (const float4*)(y + (long)row * EDIM);
    float4 a = xr[t], b4 = yr[t];
    float v0 = a.x + b4.x, v1 = a.y + b4.y, v2 = a.z + b4.z, v3 = a.w + b4.w;
    float s1 = v0 + v1 + v2 + v3;
    float s2 = v0 * v0 + v1 * v1 + v2 * v2 + v3 * v3;
    __shared__ float sh[2][6];
    int lane = t & 31, w = t >> 5;
#pragma unroll
    for (int off = 16; off; off >>= 1) {
        s1 += __shfl_xor_sync(0xffffffffu, s1, off);
        s2 += __shfl_xor_sync(0xffffffffu, s2, off);
    }
    if (!lane) { sh[0][w] = s1; sh[1][w] = s2; }
    __syncthreads();
    float a1 = 0.f, a2 = 0.f;
#pragma unroll
    for (int i = 0; i < 6; i++) { a1 += sh[0][i]; a2 += sh[1][i]; }
    float mean = a1 * (1.f / EDIM);
    float var = a2 * (1.f / EDIM) - mean * mean;
    float rstd = rsqrtf(var + 1e-5f);
    float4 gg = ((const float4*)gam)[t];
    float4 bb = ((const float4*)bet)[t];
    float4 o;
    o.x = (v0 - mean) * rstd * gg.x + bb.x;
    o.y = (v1 - mean) * rstd * gg.y + bb.y;
    o.z = (v2 - mean) * rstd * gg.z + bb.z;
    o.w = (v3 - mean) * rstd * gg.w + bb.w;
    ((float4*)(out + (long)row * EDIM))[t] = o;
    __half2* oh = (__half2*)(outh + (long)row * EDIM);
    oh[2 * t] = __floats2half2_rn(o.x, o.y);
    oh[2 * t + 1] = __floats2half2_rn(o.z, o.w);
}

// ---------------- mean pool ----------------
__global__ void pool_kernel(const float* __restrict__ x, float* __restrict__ p) {
    int idx = blockIdx.x * blockDim.x + threadIdx.x;
    if (idx >= 8 * (EDIM / 4)) return;
    int b = idx / (EDIM / 4), e4 = idx % (EDIM / 4);
    const float4* xb = (const float4*)(x + (long)b * SEQ * EDIM) + e4;
    float4 s = make_float4(0.f, 0.f, 0.f, 0.f);
    for (int si = 0; si < SEQ; si++) {
        float4 v = xb[(long)si * (EDIM / 4)];
        s.x += v.x; s.y += v.y; s.z += v.z; s.w += v.w;
    }
    s.x *= (1.f / SEQ); s.y *= (1.f / SEQ); s.z *= (1.f / SEQ); s.w *= (1.f / SEQ);
    ((float4*)p)[idx] = s;
}

// ---------------- classifier ----------------
__global__ void cls_kernel(const float* __restrict__ p, const float* __restrict__ Wc,
                           const float* __restrict__ bc, float* __restrict__ out) {
    int w = threadIdx.x >> 5, lane = threadIdx.x & 31;
    int b = w >> 1, c = w & 1;
    float s = 0.f;
    for (int e = lane; e < EDIM; e += 32) s += p[b * EDIM + e] * Wc[e * 2 + c];
#pragma unroll
    for (int off = 16; off; off >>= 1) s += __shfl_xor_sync(0xffffffffu, s, off);
    if (!lane) out[b * 2 + c] = s + bc[c];
}

// ---------------- launch ----------------
extern "C" void kernel_launch(void* const* d_in, const int* in_sizes, int n_in,
                              void* d_out, int out_size) {
    (void)in_sizes; (void)n_in; (void)out_size;
    const int* ids = (const int*)d_in[0];
    const int* amask = (const int*)d_in[1];
    const float* emb = (const float*)d_in[2];
    const float* pe = (const float*)d_in[3];
    const float* Wq = (const float*)d_in[4];
    const float* bq = (const float*)d_in[5];
    const float* Wk = (const float*)d_in[6];
    const float* bk = (const float*)d_in[7];
    const float* Wv = (const float*)d_in[8];
    const float* bv = (const float*)d_in[9];
    const float* Wo = (const float*)d_in[10];
    const float* bo = (const float*)d_in[11];
    const float* l1g = (const float*)d_in[12];
    const float* l1b = (const float*)d_in[13];
    const float* W1 = (const float*)d_in[14];
    const float* b1 = (const float*)d_in[15];
    const float* W2 = (const float*)d_in[16];
    const float* b2 = (const float*)d_in[17];
    const float* l2g = (const float*)d_in[18];
    const float* l2b = (const float*)d_in[19];
    const float* Wc = (const float*)d_in[20];
    const float* bc = (const float*)d_in[21];
    float* out = (float*)d_out;

    float *x, *q, *k, *v, *tmp, *pl;
    __half *xh, *atth, *ffnh, *wt;
    cudaGetSymbolAddress((void**)&x, g_x);
    cudaGetSymbolAddress((void**)&xh, g_xh);
    cudaGetSymbolAddress((void**)&q, g_q);
    cudaGetSymbolAddress((void**)&k, g_k);
    cudaGetSymbolAddress((void**)&v, g_v);
    cudaGetSymbolAddress((void**)&atth, g_atth);
    cudaGetSymbolAddress((void**)&tmp, g_t);
    cudaGetSymbolAddress((void**)&ffnh, g_ffnh);
    cudaGetSymbolAddress((void**)&pl, g_pool);
    cudaGetSymbolAddress((void**)&wt, g_wt);

    cudaFuncSetAttribute(gemm_h, cudaFuncAttributeMaxDynamicSharedMemorySize, GEMM_SMEM);
    cudaFuncSetAttribute(attn_kernel, cudaFuncAttributeMaxDynamicSharedMemorySize, ATT_SMEM);

    // one-time: transpose + fp16-convert all weights (batched over layers)
    dim3 tb(32, 8);
    transpose_all<<<dim3(EDIM / 32, EDIM / 32, NLAYER), tb>>>(Wq, wt + 0L * EE, EDIM, EDIM,
                                                             (long)EE, (long)WT_PER_LAYER);
    transpose_all<<<dim3(EDIM / 32, EDIM / 32, NLAYER), tb>>>(Wk, wt + 1L * EE, EDIM, EDIM,
                                                             (long)EE, (long)WT_PER_LAYER);
    transpose_all<<<dim3(EDIM / 32, EDIM / 32, NLAYER), tb>>>(Wv, wt + 2L * EE, EDIM, EDIM,
                                                             (long)EE, (long)WT_PER_LAYER);
    transpose_all<<<dim3(EDIM / 32, EDIM / 32, NLAYER), tb>>>(Wo, wt + 3L * EE, EDIM, EDIM,
                                                             (long)EE, (long)WT_PER_LAYER);
    transpose_all<<<dim3(FDIM / 32, EDIM / 32, NLAYER), tb>>>(W1, wt + 4L * EE, EDIM, FDIM,
                                                             (long)EF, (long)WT_PER_LAYER);
    transpose_all<<<dim3(EDIM / 32, FDIM / 32, NLAYER), tb>>>(W2, wt + 4L * EE + EF, FDIM, EDIM,
                                                             (long)EF, (long)WT_PER_LAYER);

    embed_kernel<<<(TOKS * EDIM + 255) / 256, 256>>>(ids, emb, pe, x, xh);

    for (int l = 0; l < NLAYER; l++) {
        long boff = (long)l * EDIM;
        __half* base = wt + (long)l * WT_PER_LAYER;
        Trip tq = {base + 0L * EE, bq + boff, q, 2};
        Trip tk = {base + 1L * EE, bk + boff, k, 2};
        Trip tv = {base + 2L * EE, bv + boff, v, 3};
        gemm_h<<<dim3(6, 64, 3), 256, GEMM_SMEM>>>(xh, tq, tk, tv, EDIM, EDIM);
        attn_kernel<<<dim3(8, 12, 8), 256, ATT_SMEM>>>(q, k, v, amask, atth);
        Trip to = {base + 3L * EE, bo + boff, tmp, 0};
        gemm_h<<<dim3(6, 64, 1), 256, GEMM_SMEM>>>(atth, to, to, to, EDIM, EDIM);
        ln_res_kernel<<<TOKS, 192>>>(x, tmp, l1g + boff, l1b + boff, x, xh);
        Trip t1 = {base + 4L * EE, b1 + (long)l * FDIM, ffnh, 1};
        gemm_h<<<dim3(24, 64, 1), 256, GEMM_SMEM>>>(xh, t1, t1, t1, FDIM, EDIM);
        Trip t2 = {base + 4L * EE + EF, b2 + boff, tmp, 0};
        gemm_h<<<dim3(6, 64, 1), 256, GEMM_SMEM>>>(ffnh, t2, t2, t2, EDIM, FDIM);
        ln_res_kernel<<<TOKS, 192>>>(x, tmp, l2g + boff, l2b + boff, x, xh);
    }

    pool_kernel<<<(8 * EDIM / 4 + 255) / 256, 256>>>(x, pl);
    cls_kernel<<<1, 512>>>(pl, Wc, bc, out);
}

// round 14
// speedup vs baseline: 2.1382x; 1.3156x over previous
#include <cuda_runtime.h>
#include <cuda_fp16.h>
#include <cstdint>

#define TOKS 8192
#define EDIM 768
#define FDIM 3072
#define SEQ  1024
#define NH   12
#define HD   64
#define NLAYER 6

#define EE (EDIM * EDIM)
#define EF (EDIM * FDIM)
#define WT_PER_LAYER (4 * EE + 2 * EF)

// ---------------- scratch (device globals; no allocation) ----------------
__device__ float g_x[TOKS * EDIM];          // fp32 residual stream
__device__ __half g_xh[TOKS * EDIM];        // fp16 copy for GEMM A
__device__ __half g_qh[TOKS * EDIM];        // Q fp16
__device__ __half g_kh[TOKS * EDIM];        // K fp16
__device__ __half g_vh[TOKS * EDIM];        // V^T fp16: [b][h][hd][seq]
__device__ __half g_atth[TOKS * EDIM];      // attention out (fp16, feeds O-proj)
__device__ float g_t[TOKS * EDIM];
__device__ __half g_ffnh[TOKS * FDIM];      // relu out (fp16, feeds FFN2)
__device__ float g_pool[8 * EDIM];
__device__ __half g_wt[(long)NLAYER * WT_PER_LAYER];  // transposed fp16 weights

// ---------------- helpers ----------------
// fp16 m16n8k16
__device__ __forceinline__ void mma16(float* c, uint32_t a0, uint32_t a1, uint32_t a2, uint32_t a3,
                                      uint32_t b0, uint32_t b1) {
    asm volatile(
        "mma.sync.aligned.m16n8k16.row.col.f32.f16.f16.f32 "
        "{%0,%1,%2,%3}, {%4,%5,%6,%7}, {%8,%9}, {%0,%1,%2,%3};"
        : "+f"(c[0]), "+f"(c[1]), "+f"(c[2]), "+f"(c[3])
        : "r"(a0), "r"(a1), "r"(a2), "r"(a3), "r"(b0), "r"(b1));
}

__device__ __forceinline__ void ldsm4(uint32_t* r, uint32_t a) {
    asm volatile("ldmatrix.sync.aligned.m8n8.x4.shared.b16 {%0,%1,%2,%3}, [%4];"
                 : "=r"(r[0]), "=r"(r[1]), "=r"(r[2]), "=r"(r[3]) : "r"(a));
}

__device__ __forceinline__ void cp16(uint32_t saddr, const void* gaddr) {
    asm volatile("cp.async.cg.shared.global [%0], [%1], 16;" ::"r"(saddr), "l"(gaddr));
}
__device__ __forceinline__ void cp_commit() { asm volatile("cp.async.commit_group;"); }

__device__ __forceinline__ uint32_t smem_u32(const void* p) {
    uint32_t a;
    asm("{ .reg .u64 t; cvta.to.shared.u64 t, %1; cvt.u32.u64 %0, t; }" : "=r"(a) : "l"(p));
    return a;
}

// ---------------- batched weight transpose -> fp16: dst[N][K] = (half)src[K][N]^T ----
__global__ void transpose_all(const float* __restrict__ src, __half* __restrict__ dst,
                              int K, int N, long sstride, long dstride) {
    int lz = blockIdx.z;
    src += (long)lz * sstride;
    dst += (long)lz * dstride;
    __shared__ float tl[32][33];
    int n0 = blockIdx.x * 32, k0 = blockIdx.y * 32;
    int tx = threadIdx.x, ty = threadIdx.y;
#pragma unroll
    for (int j = 0; j < 32; j += 8) tl[ty + j][tx] = src[(long)(k0 + ty + j) * N + n0 + tx];
    __syncthreads();
#pragma unroll
    for (int j = 0; j < 32; j += 8)
        dst[(long)(n0 + ty + j) * K + k0 + tx] = __float2half_rn(tl[tx][ty + j]);
}

// ---------------- embedding + positional encoding ----------------
__global__ void embed_kernel(const int* __restrict__ ids, const float* __restrict__ emb,
                             const float* __restrict__ pe, float* __restrict__ x,
                             __half* __restrict__ xh) {
    long idx = (long)blockIdx.x * blockDim.x + threadIdx.x;
    if (idx >= (long)TOKS * EDIM) return;
    int tok = (int)(idx / EDIM);
    int e = (int)(idx - (long)tok * EDIM);
    int s = tok & (SEQ - 1);
    float v = emb[(long)ids[tok] * EDIM + e] + pe[s * EDIM + e];
    x[idx] = v;
    xh[idx] = __float2half_rn(v);
}

// ---------------- fp16 mma GEMM: block 128x128, BK=64, 3-stage, 256 thr (2x4) -------
// modes: 0 fp32 out, 1 relu half out, 2 half out, 3 half V^T scatter
struct Trip {
    const __half* W;   // [N][K] transposed fp16
    const float* b;
    void* C;
    int mode;
};

#define GROW 144                 // 64 halfs (128B) + 16B pad
#define GAS (128 * GROW)         // 18432 per tensor
#define GSTAGE (2 * GAS)         // 36864
#define GEMM_SMEM (3 * GSTAGE)   // 110592

__global__ __launch_bounds__(256, 2) void gemm_h(const __half* __restrict__ A,
                                                 Trip t0, Trip t1, Trip t2,
                                                 int N, int K) {
    extern __shared__ __align__(128) char smc[];
    uint32_t sb = smem_u32(smc);
    int t = threadIdx.x, l = t & 31, warp = t >> 5;
    int wm = warp >> 2, wn = warp & 3;
    int g = l >> 2, tg = l & 3;

    int z = blockIdx.z;
    Trip tr = (z == 0) ? t0 : (z == 1) ? t1 : t2;
    long bm = blockIdx.y, bn = blockIdx.x;
    const __half* Ab = A + bm * 128 * (long)K;
    const __half* Bb = tr.W + bn * 128 * (long)K;

    int ra = t >> 3, seg = t & 7;

    uint32_t aOff[4], bOff[2];
#pragma unroll
    for (int mf = 0; mf < 4; mf++)
        aOff[mf] = (uint32_t)((wm * 64 + mf * 16 + (l & 7) + ((l >> 3) & 1) * 8) * GROW +
                              (l >> 4) * 16);
#pragma unroll
    for (int j = 0; j < 2; j++)
        bOff[j] = (uint32_t)(GAS +
                             (wn * 32 + j * 16 + (l & 7) + (l >> 4) * 8) * GROW +
                             ((l >> 3) & 1) * 16);

    float acc[4][4][4];
#pragma unroll
    for (int i = 0; i < 4; i++)
#pragma unroll
        for (int j = 0; j < 4; j++)
#pragma unroll
            for (int q = 0; q < 4; q++) acc[i][j][q] = 0.f;

    int niter = K >> 6;

#pragma unroll
    for (int st = 0; st < 2; st++) {
        uint32_t sA = sb + st * GSTAGE, sB = sA + GAS;
        int k0 = st * 64;
#pragma unroll
        for (int p = 0; p < 4; p++) {
            int r = ra + p * 32;
            cp16(sA + (uint32_t)(r * GROW + seg * 16), Ab + (long)r * K + k0 + seg * 8);
            cp16(sB + (uint32_t)(r * GROW + seg * 16), Bb + (long)r * K + k0 + seg * 8);
        }
        cp_commit();
    }

    int s = 0;
    for (int it = 0; it < niter; it++) {
        asm volatile("cp.async.wait_group 1;");
        __syncthreads();

        int jn = it + 2;
        if (jn < niter) {
            int s2 = jn % 3;
            uint32_t sA2 = sb + s2 * GSTAGE, sB2 = sA2 + GAS;
            int k0 = jn * 64;
#pragma unroll
            for (int p = 0; p < 4; p++) {
                int r = ra + p * 32;
                cp16(sA2 + (uint32_t)(r * GROW + seg * 16), Ab + (long)r * K + k0 + seg * 8);
                cp16(sB2 + (uint32_t)(r * GROW + seg * 16), Bb + (long)r * K + k0 + seg * 8);
            }
        }
        cp_commit();

        uint32_t sA = sb + s * GSTAGE;
#pragma unroll
        for (int kk = 0; kk < 4; kk++) {
            uint32_t af[4][4], bf[2][4];
#pragma unroll
            for (int mf = 0; mf < 4; mf++) ldsm4(af[mf], sA + aOff[mf] + kk * 32);
#pragma unroll
            for (int j = 0; j < 2; j++) ldsm4(bf[j], sA + bOff[j] + kk * 32);
#pragma unroll
            for (int mf = 0; mf < 4; mf++) {
#pragma unroll
                for (int nf = 0; nf < 4; nf++) {
                    uint32_t b0 = bf[nf >> 1][(nf & 1) * 2];
                    uint32_t b1 = bf[nf >> 1][(nf & 1) * 2 + 1];
                    mma16(acc[mf][nf], af[mf][0], af[mf][1], af[mf][2], af[mf][3], b0, b1);
                }
            }
        }
        s = (s == 2) ? 0 : s + 1;
    }

    int mode = tr.mode;
    const float* bias = tr.b;
#pragma unroll
    for (int mf = 0; mf < 4; mf++) {
        int r0 = (int)bm * 128 + wm * 64 + mf * 16 + g;
#pragma unroll
        for (int nf = 0; nf < 4; nf++) {
            int c0 = (int)bn * 128 + wn * 32 + nf * 8 + 2 * tg;
            float bb0 = bias[c0], bb1 = bias[c0 + 1];
            float v0 = acc[mf][nf][0] + bb0;
            float v1 = acc[mf][nf][1] + bb1;
            float v2 = acc[mf][nf][2] + bb0;
            float v3 = acc[mf][nf][3] + bb1;
            if (mode == 1) {
                __half* Ch = (__half*)tr.C;
                *(__half2*)&Ch[(long)r0 * N + c0] =
                    __floats2half2_rn(fmaxf(v0, 0.f), fmaxf(v1, 0.f));
                *(__half2*)&Ch[(long)(r0 + 8) * N + c0] =
                    __floats2half2_rn(fmaxf(v2, 0.f), fmaxf(v3, 0.f));
            } else if (mode == 2) {
                __half* Ch = (__half*)tr.C;
                *(__half2*)&Ch[(long)r0 * N + c0] = __floats2half2_rn(v0, v1);
                *(__half2*)&Ch[(long)(r0 + 8) * N + c0] = __floats2half2_rn(v2, v3);
            } else if (mode == 3) {
                __half* Ch = (__half*)tr.C;
                int b_ = r0 >> 10, sp = r0 & 1023;
                int h0 = c0 >> 6, d0 = c0 & 63;
                long vb = ((long)(b_ * NH + h0) * HD + d0) * SEQ + sp;
                Ch[vb] = __float2half_rn(v0);
                Ch[vb + SEQ] = __float2half_rn(v1);
                Ch[vb + 8] = __float2half_rn(v2);
                Ch[vb + SEQ + 8] = __float2half_rn(v3);
            } else {
                float* C = (float*)tr.C;
                *(float2*)&C[(long)r0 * N + c0] = make_float2(v0, v1);
                *(float2*)&C[(long)(r0 + 8) * N + c0] = make_float2(v2, v3);
            }
        }
    }
}

// ---------------- fused flash attention (fp16 mma), q-tile 128, 2-stage K/V ---------
// smem (bytes): Q[128][144B] @0 (18432), P @18432 (18432), mask(f32) @36864 (4096),
// stages @40960 + s*18432 : K[64][144B] (9216) then V^T[64][144B] (9216). total 77824
#define ATT_SMEM 77824

__global__ __launch_bounds__(256, 2) void attn_kernel(const __half* __restrict__ Q,
                                                      const __half* __restrict__ Kp,
                                                      const __half* __restrict__ Vt,
                                                      const int* __restrict__ mask,
                                                      __half* __restrict__ O) {
    extern __shared__ __align__(128) char smc[];
    uint32_t sb = smem_u32(smc);
    float* mAdd = (float*)(smc + 36864);

    int t = threadIdx.x, l = t & 31, warp = t >> 5;
    int g = l >> 2, tg = l & 3;
    int b = blockIdx.z, h = blockIdx.y, qt = blockIdx.x;
    int rq = warp * 16;

    const __half* Qb = Q + ((long)(b * SEQ + qt * 128)) * EDIM + h * HD;
    const __half* Kb = Kp + ((long)(b * SEQ)) * EDIM + h * HD;
    const __half* Vb = Vt + ((long)(b * NH + h) * HD) * SEQ;

    // fragment smem offsets (m16n8k16 mappings, validated in gemm_h)
    uint32_t aQoff = (uint32_t)((rq + (l & 7) + ((l >> 3) & 1) * 8) * 144 + (l >> 4) * 16);
    uint32_t bOff[4];
#pragma unroll
    for (int j = 0; j < 4; j++)
        bOff[j] = (uint32_t)((j * 16 + (l & 7) + (l >> 4) * 8) * 144 + ((l >> 3) & 1) * 16);

    // Q load: 128 rows x 8 segs of 16B
    {
        int r = t >> 1, s0 = (t & 1) * 4;
#pragma unroll
        for (int j = 0; j < 4; j++)
            cp16(sb + (uint32_t)(r * 144 + (s0 + j) * 16), Qb + (long)r * EDIM + (s0 + j) * 8);
        cp_commit();
    }
    for (int i = t; i < SEQ; i += 256) mAdd[i] = mask[b * SEQ + i] ? 0.f : -1e30f;

    // prologue stages 0,1: K/V 64 rows x 8 segs each
#pragma unroll
    for (int st = 0; st < 2; st++) {
        uint32_t Kst = sb + 40960 + st * 18432, Vst = Kst + 9216;
        int r = t >> 2, j0 = (t & 3) * 2;
        const __half* Ks = Kb + (long)(st * 64) * EDIM;
        const __half* Vs = Vb + st * 64;
#pragma unroll
        for (int j = 0; j < 2; j++) {
            cp16(Kst + (uint32_t)(r * 144 + (j0 + j) * 16), Ks + (long)r * EDIM + (j0 + j) * 8);
            cp16(Vst + (uint32_t)(r * 144 + (j0 + j) * 16), Vs + (long)r * SEQ + (j0 + j) * 8);
        }
        cp_commit();
    }

    float m_[2] = {-INFINITY, -INFINITY};
    float l_[2] = {0.f, 0.f};
    float o[8][4];
#pragma unroll
    for (int nf = 0; nf < 8; nf++)
#pragma unroll
        for (int q = 0; q < 4; q++) o[nf][q] = 0.f;

    for (int kt = 0; kt < 16; kt++) {
        int s = kt & 1;
        uint32_t Kst = sb + 40960 + s * 18432, Vst = Kst + 9216;
        asm volatile("cp.async.wait_group 1;");
        __syncthreads();

        // ---- S = Q K^T  (fp16 mma, HD=64 -> 4 k-steps) ----
        float sc[8][4];
#pragma unroll
        for (int nf = 0; nf < 8; nf++)
#pragma unroll
            for (int q = 0; q < 4; q++) sc[nf][q] = 0.f;
#pragma unroll
        for (int kk = 0; kk < 4; kk++) {
            uint32_t af[4], bf[4][4];
            ldsm4(af, sb + aQoff + kk * 32);
#pragma unroll
            for (int j = 0; j < 4; j++) ldsm4(bf[j], Kst + bOff[j] + kk * 32);
#pragma unroll
            for (int nf = 0; nf < 8; nf++) {
                uint32_t b0 = bf[nf >> 1][(nf & 1) * 2];
                uint32_t b1 = bf[nf >> 1][(nf & 1) * 2 + 1];
                mma16(sc[nf], af[0], af[1], af[2], af[3], b0, b1);
            }
        }

        // ---- mask + online softmax (fp32) ----
        float rmax0 = -INFINITY, rmax1 = -INFINITY;
#pragma unroll
        for (int nf = 0; nf < 8; nf++) {
            int c0 = kt * 64 + nf * 8 + 2 * tg;
            float ma = mAdd[c0], mb = mAdd[c0 + 1];
            sc[nf][0] = sc[nf][0] * 0.125f + ma;
            sc[nf][1] = sc[nf][1] * 0.125f + mb;
            sc[nf][2] = sc[nf][2] * 0.125f + ma;
            sc[nf][3] = sc[nf][3] * 0.125f + mb;
            rmax0 = fmaxf(rmax0, fmaxf(sc[nf][0], sc[nf][1]));
            rmax1 = fmaxf(rmax1, fmaxf(sc[nf][2], sc[nf][3]));
        }
        rmax0 = fmaxf(rmax0, __shfl_xor_sync(0xffffffffu, rmax0, 1));
        rmax0 = fmaxf(rmax0, __shfl_xor_sync(0xffffffffu, rmax0, 2));
        rmax1 = fmaxf(rmax1, __shfl_xor_sync(0xffffffffu, rmax1, 1));
        rmax1 = fmaxf(rmax1, __shfl_xor_sync(0xffffffffu, rmax1, 2));
        float mn0 = fmaxf(m_[0], rmax0), mn1 = fmaxf(m_[1], rmax1);
        float cf0 = __expf(m_[0] - mn0), cf1 = __expf(m_[1] - mn1);
        float rs0 = 0.f, rs1 = 0.f;
#pragma unroll
        for (int nf = 0; nf < 8; nf++) {
            sc[nf][0] = __expf(sc[nf][0] - mn0);
            sc[nf][1] = __expf(sc[nf][1] - mn0);
            sc[nf][2] = __expf(sc[nf][2] - mn1);
            sc[nf][3] = __expf(sc[nf][3] - mn1);
            rs0 += sc[nf][0] + sc[nf][1];
            rs1 += sc[nf][2] + sc[nf][3];
        }
        rs0 += __shfl_xor_sync(0xffffffffu, rs0, 1);
        rs0 += __shfl_xor_sync(0xffffffffu, rs0, 2);
        rs1 += __shfl_xor_sync(0xffffffffu, rs1, 1);
        rs1 += __shfl_xor_sync(0xffffffffu, rs1, 2);
        l_[0] = l_[0] * cf0 + rs0;
        l_[1] = l_[1] * cf1 + rs1;
        m_[0] = mn0; m_[1] = mn1;
#pragma unroll
        for (int nf = 0; nf < 8; nf++) {
            o[nf][0] *= cf0; o[nf][1] *= cf0;
            o[nf][2] *= cf1; o[nf][3] *= cf1;
        }

        // ---- P -> smem (fp16, per-warp private rows), then O += P V ----
#pragma unroll
        for (int nf = 0; nf < 8; nf++) {
            int pc = nf * 8 + 2 * tg;
            uint32_t a0 = sb + 18432 + (uint32_t)((rq + g) * 144 + pc * 2);
            uint32_t a1 = sb + 18432 + (uint32_t)((rq + 8 + g) * 144 + pc * 2);
            __half2 p01 = __floats2half2_rn(sc[nf][0], sc[nf][1]);
            __half2 p23 = __floats2half2_rn(sc[nf][2], sc[nf][3]);
            asm volatile("st.shared.b32 [%0], %1;" ::"r"(a0),
                         "r"(*(uint32_t*)&p01) : "memory");
            asm volatile("st.shared.b32 [%0], %1;" ::"r"(a1),
                         "r"(*(uint32_t*)&p23) : "memory");
        }
        __syncwarp();
#pragma unroll
        for (int kk = 0; kk < 4; kk++) {
            uint32_t af[4], bf[4][4];
            ldsm4(af, sb + 18432 + aQoff + kk * 32);
#pragma unroll
            for (int j = 0; j < 4; j++) ldsm4(bf[j], Vst + bOff[j] + kk * 32);
#pragma unroll
            for (int nf = 0; nf < 8; nf++) {
                uint32_t b0 = bf[nf >> 1][(nf & 1) * 2];
                uint32_t b1 = bf[nf >> 1][(nf & 1) * 2 + 1];
                mma16(o[nf], af[0], af[1], af[2], af[3], b0, b1);
            }
        }
        __syncthreads();

        // prefetch kt+2 into stage s
        int jn = kt + 2;
        if (jn < 16) {
            int r = t >> 2, j0 = (t & 3) * 2;
            const __half* Ks = Kb + (long)(jn * 64) * EDIM;
            const __half* Vs = Vb + jn * 64;
#pragma unroll
            for (int j = 0; j < 2; j++) {
                cp16(Kst + (uint32_t)(r * 144 + (j0 + j) * 16), Ks + (long)r * EDIM + (j0 + j) * 8);
                cp16(Vst + (uint32_t)(r * 144 + (j0 + j) * 16), Vs + (long)r * SEQ + (j0 + j) * 8);
            }
        }
        cp_commit();
    }

    float il0 = 1.f / l_[0], il1 = 1.f / l_[1];
#pragma unroll
    for (int nf = 0; nf < 8; nf++) {
        long rowg = (long)(b * SEQ + qt * 128 + rq + g);
        int colg = h * HD + nf * 8 + 2 * tg;
        *(__half2*)&O[rowg * EDIM + colg] = __floats2half2_rn(o[nf][0] * il0, o[nf][1] * il0);
        *(__half2*)&O[(rowg + 8) * EDIM + colg] = __floats2half2_rn(o[nf][2] * il1, o[nf][3] * il1);
    }
}

// ---------------- fused residual add + LayerNorm (fp32 + fp16 outputs) --------------
__global__ __launch_bounds__(192) void ln_res_kernel(const float* __restrict__ x,
                                                     const float* __restrict__ y,
                                                     const float* __restrict__ gam,
                                                     const float* __restrict__ bet,
                                                     float* __restrict__ out,
                                                     __half* __restrict__ outh) {
    int row = blockIdx.x, t = threadIdx.x;
    const float4* xr = (const float4*)(x + (long)row * EDIM);
    const float4* yr = (const float4*)(y + (long)row * EDIM);
    float4 a = xr[t], b4 = yr[t];
    float v0 = a.x + b4.x, v1 = a.y + b4.y, v2 = a.z + b4.z, v3 = a.w + b4.w;
    float s1 = v0 + v1 + v2 + v3;
    float s2 = v0 * v0 + v1 * v1 + v2 * v2 + v3 * v3;
    __shared__ float sh[2][6];
    int lane = t & 31, w = t >> 5;
#pragma unroll
    for (int off = 16; off; off >>= 1) {
        s1 += __shfl_xor_sync(0xffffffffu, s1, off);
        s2 += __shfl_xor_sync(0xffffffffu, s2, off);
    }
    if (!lane) { sh[0][w] = s1; sh[1][w] = s2; }
    __syncthreads();
    float a1 = 0.f, a2 = 0.f;
#pragma unroll
    for (int i = 0; i < 6; i++) { a1 += sh[0][i]; a2 += sh[1][i]; }
    float mean = a1 * (1.f / EDIM);
    float var = a2 * (1.f / EDIM) - mean * mean;
    float rstd = rsqrtf(var + 1e-5f);
    float4 gg = ((const float4*)gam)[t];
    float4 bb = ((const float4*)bet)[t];
    float4 o;
    o.x = (v0 - mean) * rstd * gg.x + bb.x;
    o.y = (v1 - mean) * rstd * gg.y + bb.y;
    o.z = (v2 - mean) * rstd * gg.z + bb.z;
    o.w = (v3 - mean) * rstd * gg.w + bb.w;
    ((float4*)(out + (long)row * EDIM))[t] = o;
    __half2* oh = (__half2*)(outh + (long)row * EDIM);
    oh[2 * t] = __floats2half2_rn(o.x, o.y);
    oh[2 * t + 1] = __floats2half2_rn(o.z, o.w);
}

// ---------------- mean pool ----------------
__global__ void pool_kernel(const float* __restrict__ x, float* __restrict__ p) {
    int idx = blockIdx.x * blockDim.x + threadIdx.x;
    if (idx >= 8 * (EDIM / 4)) return;
    int b = idx / (EDIM / 4), e4 = idx % (EDIM / 4);
    const float4* xb = (const float4*)(x + (long)b * SEQ * EDIM) + e4;
    float4 s = make_float4(0.f, 0.f, 0.f, 0.f);
    for (int si = 0; si < SEQ; si++) {
        float4 v = xb[(long)si * (EDIM / 4)];
        s.x += v.x; s.y += v.y; s.z += v.z; s.w += v.w;
    }
    s.x *= (1.f / SEQ); s.y *= (1.f / SEQ); s.z *= (1.f / SEQ); s.w *= (1.f / SEQ);
    ((float4*)p)[idx] = s;
}

// ---------------- classifier ----------------
__global__ void cls_kernel(const float* __restrict__ p, const float* __restrict__ Wc,
                           const float* __restrict__ bc, float* __restrict__ out) {
    int w = threadIdx.x >> 5, lane = threadIdx.x & 31;
    int b = w >> 1, c = w & 1;
    float s = 0.f;
    for (int e = lane; e < EDIM; e += 32) s += p[b * EDIM + e] * Wc[e * 2 + c];
#pragma unroll
    for (int off = 16; off; off >>= 1) s += __shfl_xor_sync(0xffffffffu, s, off);
    if (!lane) out[b * 2 + c] = s + bc[c];
}

// ---------------- launch ----------------
extern "C" void kernel_launch(void* const* d_in, const int* in_sizes, int n_in,
                              void* d_out, int out_size) {
    (void)in_sizes; (void)n_in; (void)out_size;
    const int* ids = (const int*)d_in[0];
    const int* amask = (const int*)d_in[1];
    const float* emb = (const float*)d_in[2];
    const float* pe = (const float*)d_in[3];
    const float* Wq = (const float*)d_in[4];
    const float* bq = (const float*)d_in[5];
    const float* Wk = (const float*)d_in[6];
    const float* bk = (const float*)d_in[7];
    const float* Wv = (const float*)d_in[8];
    const float* bv = (const float*)d_in[9];
    const float* Wo = (const float*)d_in[10];
    const float* bo = (const float*)d_in[11];
    const float* l1g = (const float*)d_in[12];
    const float* l1b = (const float*)d_in[13];
    const float* W1 = (const float*)d_in[14];
    const float* b1 = (const float*)d_in[15];
    const float* W2 = (const float*)d_in[16];
    const float* b2 = (const float*)d_in[17];
    const float* l2g = (const float*)d_in[18];
    const float* l2b = (const float*)d_in[19];
    const float* Wc = (const float*)d_in[20];
    const float* bc = (const float*)d_in[21];
    float* out = (float*)d_out;

    float *x, *tmp, *pl;
    __half *xh, *qh, *kh, *vh, *atth, *ffnh, *wt;
    cudaGetSymbolAddress((void**)&x, g_x);
    cudaGetSymbolAddress((void**)&xh, g_xh);
    cudaGetSymbolAddress((void**)&qh, g_qh);
    cudaGetSymbolAddress((void**)&kh, g_kh);
    cudaGetSymbolAddress((void**)&vh, g_vh);
    cudaGetSymbolAddress((void**)&atth, g_atth);
    cudaGetSymbolAddress((void**)&tmp, g_t);
    cudaGetSymbolAddress((void**)&ffnh, g_ffnh);
    cudaGetSymbolAddress((void**)&pl, g_pool);
    cudaGetSymbolAddress((void**)&wt, g_wt);

    cudaFuncSetAttribute(gemm_h, cudaFuncAttributeMaxDynamicSharedMemorySize, GEMM_SMEM);
    cudaFuncSetAttribute(attn_kernel, cudaFuncAttributeMaxDynamicSharedMemorySize, ATT_SMEM);

    // one-time: transpose + fp16-convert all weights (batched over layers)
    dim3 tb(32, 8);
    transpose_all<<<dim3(EDIM / 32, EDIM / 32, NLAYER), tb>>>(Wq, wt + 0L * EE, EDIM, EDIM,
                                                             (long)EE, (long)WT_PER_LAYER);
    transpose_all<<<dim3(EDIM / 32, EDIM / 32, NLAYER), tb>>>(Wk, wt + 1L * EE, EDIM, EDIM,
                                                             (long)EE, (long)WT_PER_LAYER);
    transpose_all<<<dim3(EDIM / 32, EDIM / 32, NLAYER), tb>>>(Wv, wt + 2L * EE, EDIM, EDIM,
                                                             (long)EE, (long)WT_PER_LAYER);
    transpose_all<<<dim3(EDIM / 32, EDIM / 32, NLAYER), tb>>>(Wo, wt + 3L * EE, EDIM, EDIM,
                                                             (long)EE, (long)WT_PER_LAYER);
    transpose_all<<<dim3(FDIM / 32, EDIM / 32, NLAYER), tb>>>(W1, wt + 4L * EE, EDIM, FDIM,
                                                             (long)EF, (long)WT_PER_LAYER);
    transpose_all<<<dim3(EDIM / 32, FDIM / 32, NLAYER), tb>>>(W2, wt + 4L * EE + EF, FDIM, EDIM,
                                                             (long)EF, (long)WT_PER_LAYER);

    embed_kernel<<<(TOKS * EDIM + 255) / 256, 256>>>(ids, emb, pe, x, xh);

    for (int l = 0; l < NLAYER; l++) {
        long boff = (long)l * EDIM;
        __half* base = wt + (long)l * WT_PER_LAYER;
        Trip tq = {base + 0L * EE, bq + boff, qh, 2};
        Trip tk = {base + 1L * EE, bk + boff, kh, 2};
        Trip tv = {base + 2L * EE, bv + boff, vh, 3};
        gemm_h<<<dim3(6, 64, 3), 256, GEMM_SMEM>>>(xh, tq, tk, tv, EDIM, EDIM);
        attn_kernel<<<dim3(8, 12, 8), 256, ATT_SMEM>>>(qh, kh, vh, amask, atth);
        Trip to = {base + 3L * EE, bo + boff, tmp, 0};
        gemm_h<<<dim3(6, 64, 1), 256, GEMM_SMEM>>>(atth, to, to, to, EDIM, EDIM);
        ln_res_kernel<<<TOKS, 192>>>(x, tmp, l1g + boff, l1b + boff, x, xh);
        Trip t1 = {base + 4L * EE, b1 + (long)l * FDIM, ffnh, 1};
        gemm_h<<<dim3(24, 64, 1), 256, GEMM_SMEM>>>(xh, t1, t1, t1, FDIM, EDIM);
        Trip t2 = {base + 4L * EE + EF, b2 + boff, tmp, 0};
        gemm_h<<<dim3(6, 64, 1), 256, GEMM_SMEM>>>(ffnh, t2, t2, t2, EDIM, FDIM);
        ln_res_kernel<<<TOKS, 192>>>(x, tmp, l2g + boff, l2b + boff, x, xh);
    }

    pool_kernel<<<(8 * EDIM / 4 + 255) / 256, 256>>>(x, pl);
    cls_kernel<<<1, 512>>>(pl, Wc, bc, out);
}

// round 15
// speedup vs baseline: 2.1458x; 1.0035x over previous
#include <cuda_runtime.h>
#include <cuda_fp16.h>
#include <cstdint>

#define TOKS 8192
#define EDIM 768
#define FDIM 3072
#define SEQ  1024
#define NH   12
#define HD   64
#define NLAYER 6

#define EE (EDIM * EDIM)
#define EF (EDIM * FDIM)
#define WT_PER_LAYER (4 * EE + 2 * EF)

// ---------------- scratch (device globals; no allocation) ----------------
__device__ float g_x[TOKS * EDIM];          // fp32 residual stream
__device__ __half g_xh[TOKS * EDIM];        // fp16 copy for GEMM A
__device__ __half g_qh[TOKS * EDIM];        // Q fp16
__device__ __half g_kh[TOKS * EDIM];        // K fp16
__device__ __half g_vh[TOKS * EDIM];        // V^T fp16: [b][h][hd][seq]
__device__ __half g_atth[TOKS * EDIM];      // attention out (fp16, feeds O-proj)
__device__ __half g_th[TOKS * EDIM];        // O-proj / FFN2 out (fp16, feeds LN)
__device__ __half g_ffnh[TOKS * FDIM];      // relu out (fp16, feeds FFN2)
__device__ float g_pool[8 * EDIM];
__device__ __half g_wt[(long)NLAYER * WT_PER_LAYER];  // transposed fp16 weights

// ---------------- helpers ----------------
__device__ __forceinline__ void mma16(float* c, uint32_t a0, uint32_t a1, uint32_t a2, uint32_t a3,
                                      uint32_t b0, uint32_t b1) {
    asm volatile(
        "mma.sync.aligned.m16n8k16.row.col.f32.f16.f16.f32 "
        "{%0,%1,%2,%3}, {%4,%5,%6,%7}, {%8,%9}, {%0,%1,%2,%3};"
        : "+f"(c[0]), "+f"(c[1]), "+f"(c[2]), "+f"(c[3])
        : "r"(a0), "r"(a1), "r"(a2), "r"(a3), "r"(b0), "r"(b1));
}

__device__ __forceinline__ void ldsm4(uint32_t* r, uint32_t a) {
    asm volatile("ldmatrix.sync.aligned.m8n8.x4.shared.b16 {%0,%1,%2,%3}, [%4];"
                 : "=r"(r[0]), "=r"(r[1]), "=r"(r[2]), "=r"(r[3]) : "r"(a));
}

__device__ __forceinline__ void cp16(uint32_t saddr, const void* gaddr) {
    asm volatile("cp.async.cg.shared.global [%0], [%1], 16;" ::"r"(saddr), "l"(gaddr));
}
__device__ __forceinline__ void cp_commit() { asm volatile("cp.async.commit_group;"); }

__device__ __forceinline__ uint32_t smem_u32(const void* p) {
    uint32_t a;
    asm("{ .reg .u64 t; cvta.to.shared.u64 t, %1; cvt.u32.u64 %0, t; }" : "=r"(a) : "l"(p));
    return a;
}

// ---------------- batched weight transpose -> fp16: dst[N][K] = (half)src[K][N]^T ----
__global__ void transpose_all(const float* __restrict__ src, __half* __restrict__ dst,
                              int K, int N, long sstride, long dstride) {
    int lz = blockIdx.z;
    src += (long)lz * sstride;
    dst += (long)lz * dstride;
    __shared__ float tl[32][33];
    int n0 = blockIdx.x * 32, k0 = blockIdx.y * 32;
    int tx = threadIdx.x, ty = threadIdx.y;
#pragma unroll
    for (int j = 0; j < 32; j += 8) tl[ty + j][tx] = src[(long)(k0 + ty + j) * N + n0 + tx];
    __syncthreads();
#pragma unroll
    for (int j = 0; j < 32; j += 8)
        dst[(long)(n0 + ty + j) * K + k0 + tx] = __float2half_rn(tl[tx][ty + j]);
}

// ---------------- embedding + positional encoding ----------------
__global__ void embed_kernel(const int* __restrict__ ids, const float* __restrict__ emb,
                             const float* __restrict__ pe, float* __restrict__ x,
                             __half* __restrict__ xh) {
    long idx = (long)blockIdx.x * blockDim.x + threadIdx.x;
    if (idx >= (long)TOKS * EDIM) return;
    int tok = (int)(idx / EDIM);
    int e = (int)(idx - (long)tok * EDIM);
    int s = tok & (SEQ - 1);
    float v = emb[(long)ids[tok] * EDIM + e] + pe[s * EDIM + e];
    x[idx] = v;
    xh[idx] = __float2half_rn(v);
}

// ---------------- fp16 mma GEMM: block 128x128, BK=64, 3-stage, 256 thr (2x4) -------
// modes: 1 relu half out, 2 half out, 3 half V^T scatter
struct Trip {
    const __half* W;   // [N][K] transposed fp16
    const float* b;
    __half* C;
    int mode;
};

#define GROW 144                 // 64 halfs (128B) + 16B pad
#define GAS (128 * GROW)         // 18432 per tensor
#define GSTAGE (2 * GAS)         // 36864
#define GEMM_SMEM (3 * GSTAGE)   // 110592

__global__ __launch_bounds__(256, 2) void gemm_h(const __half* __restrict__ A,
                                                 Trip t0, Trip t1, Trip t2,
                                                 int N, int K) {
    extern __shared__ __align__(128) char smc[];
    uint32_t sb = smem_u32(smc);
    int t = threadIdx.x, l = t & 31, warp = t >> 5;
    int wm = warp >> 2, wn = warp & 3;
    int g = l >> 2, tg = l & 3;

    int z = blockIdx.z;
    Trip tr = (z == 0) ? t0 : (z == 1) ? t1 : t2;
    long bm = blockIdx.y, bn = blockIdx.x;
    const __half* Ab = A + bm * 128 * (long)K;
    const __half* Bb = tr.W + bn * 128 * (long)K;

    int ra = t >> 3, seg = t & 7;

    uint32_t aOff[4], bOff[2];
#pragma unroll
    for (int mf = 0; mf < 4; mf++)
        aOff[mf] = (uint32_t)((wm * 64 + mf * 16 + (l & 7) + ((l >> 3) & 1) * 8) * GROW +
                              (l >> 4) * 16);
#pragma unroll
    for (int j = 0; j < 2; j++)
        bOff[j] = (uint32_t)(GAS +
                             (wn * 32 + j * 16 + (l & 7) + (l >> 4) * 8) * GROW +
                             ((l >> 3) & 1) * 16);

    float acc[4][4][4];
#pragma unroll
    for (int i = 0; i < 4; i++)
#pragma unroll
        for (int j = 0; j < 4; j++)
#pragma unroll
            for (int q = 0; q < 4; q++) acc[i][j][q] = 0.f;

    int niter = K >> 6;

#pragma unroll
    for (int st = 0; st < 2; st++) {
        uint32_t sA = sb + st * GSTAGE, sB = sA + GAS;
        int k0 = st * 64;
#pragma unroll
        for (int p = 0; p < 4; p++) {
            int r = ra + p * 32;
            cp16(sA + (uint32_t)(r * GROW + seg * 16), Ab + (long)r * K + k0 + seg * 8);
            cp16(sB + (uint32_t)(r * GROW + seg * 16), Bb + (long)r * K + k0 + seg * 8);
        }
        cp_commit();
    }

    int s = 0;
    for (int it = 0; it < niter; it++) {
        asm volatile("cp.async.wait_group 1;");
        __syncthreads();

        int jn = it + 2;
        if (jn < niter) {
            int s2 = jn % 3;
            uint32_t sA2 = sb + s2 * GSTAGE, sB2 = sA2 + GAS;
            int k0 = jn * 64;
#pragma unroll
            for (int p = 0; p < 4; p++) {
                int r = ra + p * 32;
                cp16(sA2 + (uint32_t)(r * GROW + seg * 16), Ab + (long)r * K + k0 + seg * 8);
                cp16(sB2 + (uint32_t)(r * GROW + seg * 16), Bb + (long)r * K + k0 + seg * 8);
            }
        }
        cp_commit();

        uint32_t sA = sb + s * GSTAGE;
#pragma unroll
        for (int kk = 0; kk < 4; kk++) {
            uint32_t af[4][4], bf[2][4];
#pragma unroll
            for (int mf = 0; mf < 4; mf++) ldsm4(af[mf], sA + aOff[mf] + kk * 32);
#pragma unroll
            for (int j = 0; j < 2; j++) ldsm4(bf[j], sA + bOff[j] + kk * 32);
#pragma unroll
            for (int mf = 0; mf < 4; mf++) {
#pragma unroll
                for (int nf = 0; nf < 4; nf++) {
                    uint32_t b0 = bf[nf >> 1][(nf & 1) * 2];
                    uint32_t b1 = bf[nf >> 1][(nf & 1) * 2 + 1];
                    mma16(acc[mf][nf], af[mf][0], af[mf][1], af[mf][2], af[mf][3], b0, b1);
                }
            }
        }
        s = (s == 2) ? 0 : s + 1;
    }

    int mode = tr.mode;
    const float* bias = tr.b;
    __half* Ch = tr.C;
#pragma unroll
    for (int mf = 0; mf < 4; mf++) {
        int r0 = (int)bm * 128 + wm * 64 + mf * 16 + g;
#pragma unroll
        for (int nf = 0; nf < 4; nf++) {
            int c0 = (int)bn * 128 + wn * 32 + nf * 8 + 2 * tg;
            float bb0 = bias[c0], bb1 = bias[c0 + 1];
            float v0 = acc[mf][nf][0] + bb0;
            float v1 = acc[mf][nf][1] + bb1;
            float v2 = acc[mf][nf][2] + bb0;
            float v3 = acc[mf][nf][3] + bb1;
            if (mode == 1) {
                v0 = fmaxf(v0, 0.f); v1 = fmaxf(v1, 0.f);
                v2 = fmaxf(v2, 0.f); v3 = fmaxf(v3, 0.f);
            }
            if (mode == 3) {
                int b_ = r0 >> 10, sp = r0 & 1023;
                int h0 = c0 >> 6, d0 = c0 & 63;
                long vb = ((long)(b_ * NH + h0) * HD + d0) * SEQ + sp;
                Ch[vb] = __float2half_rn(v0);
                Ch[vb + SEQ] = __float2half_rn(v1);
                Ch[vb + 8] = __float2half_rn(v2);
                Ch[vb + SEQ + 8] = __float2half_rn(v3);
            } else {
                *(__half2*)&Ch[(long)r0 * N + c0] = __floats2half2_rn(v0, v1);
                *(__half2*)&Ch[(long)(r0 + 8) * N + c0] = __floats2half2_rn(v2, v3);
            }
        }
    }
}

// ---------------- fused flash attention (fp16 mma), q-tile 128, 2-stage K/V ---------
// smem: Q[128][144B] @0, P @18432, mask(f32) @36864, stages @40960 + s*18432
#define ATT_SMEM 77824

__global__ __launch_bounds__(256, 2) void attn_kernel(const __half* __restrict__ Q,
                                                      const __half* __restrict__ Kp,
                                                      const __half* __restrict__ Vt,
                                                      const int* __restrict__ mask,
                                                      __half* __restrict__ O) {
    extern __shared__ __align__(128) char smc[];
    uint32_t sb = smem_u32(smc);
    float* mAdd = (float*)(smc + 36864);

    int t = threadIdx.x, l = t & 31, warp = t >> 5;
    int g = l >> 2, tg = l & 3;
    int b = blockIdx.z, h = blockIdx.y, qt = blockIdx.x;
    int rq = warp * 16;

    const __half* Qb = Q + ((long)(b * SEQ + qt * 128)) * EDIM + h * HD;
    const __half* Kb = Kp + ((long)(b * SEQ)) * EDIM + h * HD;
    const __half* Vb = Vt + ((long)(b * NH + h) * HD) * SEQ;

    uint32_t aQoff = (uint32_t)((rq + (l & 7) + ((l >> 3) & 1) * 8) * 144 + (l >> 4) * 16);
    uint32_t bOff[4];
#pragma unroll
    for (int j = 0; j < 4; j++)
        bOff[j] = (uint32_t)((j * 16 + (l & 7) + (l >> 4) * 8) * 144 + ((l >> 3) & 1) * 16);

    {
        int r = t >> 1, s0 = (t & 1) * 4;
#pragma unroll
        for (int j = 0; j < 4; j++)
            cp16(sb + (uint32_t)(r * 144 + (s0 + j) * 16), Qb + (long)r * EDIM + (s0 + j) * 8);
        cp_commit();
    }
    for (int i = t; i < SEQ; i += 256) mAdd[i] = mask[b * SEQ + i] ? 0.f : -1e30f;

#pragma unroll
    for (int st = 0; st < 2; st++) {
        uint32_t Kst = sb + 40960 + st * 18432, Vst = Kst + 9216;
        int r = t >> 2, j0 = (t & 3) * 2;
        const __half* Ks = Kb + (long)(st * 64) * EDIM;
        const __half* Vs = Vb + st * 64;
#pragma unroll
        for (int j = 0; j < 2; j++) {
            cp16(Kst + (uint32_t)(r * 144 + (j0 + j) * 16), Ks + (long)r * EDIM + (j0 + j) * 8);
            cp16(Vst + (uint32_t)(r * 144 + (j0 + j) * 16), Vs + (long)r * SEQ + (j0 + j) * 8);
        }
        cp_commit();
    }

    float m_[2] = {-INFINITY, -INFINITY};
    float l_[2] = {0.f, 0.f};
    float o[8][4];
#pragma unroll
    for (int nf = 0; nf < 8; nf++)
#pragma unroll
        for (int q = 0; q < 4; q++) o[nf][q] = 0.f;

    for (int kt = 0; kt < 16; kt++) {
        int s = kt & 1;
        uint32_t Kst = sb + 40960 + s * 18432, Vst = Kst + 9216;
        asm volatile("cp.async.wait_group 1;");
        __syncthreads();

        float sc[8][4];
#pragma unroll
        for (int nf = 0; nf < 8; nf++)
#pragma unroll
            for (int q = 0; q < 4; q++) sc[nf][q] = 0.f;
#pragma unroll
        for (int kk = 0; kk < 4; kk++) {
            uint32_t af[4], bf[4][4];
            ldsm4(af, sb + aQoff + kk * 32);
#pragma unroll
            for (int j = 0; j < 4; j++) ldsm4(bf[j], Kst + bOff[j] + kk * 32);
#pragma unroll
            for (int nf = 0; nf < 8; nf++) {
                uint32_t b0 = bf[nf >> 1][(nf & 1) * 2];
                uint32_t b1 = bf[nf >> 1][(nf & 1) * 2 + 1];
                mma16(sc[nf], af[0], af[1], af[2], af[3], b0, b1);
            }
        }

        float rmax0 = -INFINITY, rmax1 = -INFINITY;
#pragma unroll
        for (int nf = 0; nf < 8; nf++) {
            int c0 = kt * 64 + nf * 8 + 2 * tg;
            float ma = mAdd[c0], mb = mAdd[c0 + 1];
            sc[nf][0] = sc[nf][0] * 0.125f + ma;
            sc[nf][1] = sc[nf][1] * 0.125f + mb;
            sc[nf][2] = sc[nf][2] * 0.125f + ma;
            sc[nf][3] = sc[nf][3] * 0.125f + mb;
            rmax0 = fmaxf(rmax0, fmaxf(sc[nf][0], sc[nf][1]));
            rmax1 = fmaxf(rmax1, fmaxf(sc[nf][2], sc[nf][3]));
        }
        rmax0 = fmaxf(rmax0, __shfl_xor_sync(0xffffffffu, rmax0, 1));
        rmax0 = fmaxf(rmax0, __shfl_xor_sync(0xffffffffu, rmax0, 2));
        rmax1 = fmaxf(rmax1, __shfl_xor_sync(0xffffffffu, rmax1, 1));
        rmax1 = fmaxf(rmax1, __shfl_xor_sync(0xffffffffu, rmax1, 2));
        float mn0 = fmaxf(m_[0], rmax0), mn1 = fmaxf(m_[1], rmax1);
        float cf0 = __expf(m_[0] - mn0), cf1 = __expf(m_[1] - mn1);
        float rs0 = 0.f, rs1 = 0.f;
#pragma unroll
        for (int nf = 0; nf < 8; nf++) {
            sc[nf][0] = __expf(sc[nf][0] - mn0);
            sc[nf][1] = __expf(sc[nf][1] - mn0);
            sc[nf][2] = __expf(sc[nf][2] - mn1);
            sc[nf][3] = __expf(sc[nf][3] - mn1);
            rs0 += sc[nf][0] + sc[nf][1];
            rs1 += sc[nf][2] + sc[nf][3];
        }
        rs0 += __shfl_xor_sync(0xffffffffu, rs0, 1);
        rs0 += __shfl_xor_sync(0xffffffffu, rs0, 2);
        rs1 += __shfl_xor_sync(0xffffffffu, rs1, 1);
        rs1 += __shfl_xor_sync(0xffffffffu, rs1, 2);
        l_[0] = l_[0] * cf0 + rs0;
        l_[1] = l_[1] * cf1 + rs1;
        m_[0] = mn0; m_[1] = mn1;
#pragma unroll
        for (int nf = 0; nf < 8; nf++) {
            o[nf][0] *= cf0; o[nf][1] *= cf0;
            o[nf][2] *= cf1; o[nf][3] *= cf1;
        }

#pragma unroll
        for (int nf = 0; nf < 8; nf++) {
            int pc = nf * 8 + 2 * tg;
            uint32_t a0 = sb + 18432 + (uint32_t)((rq + g) * 144 + pc * 2);
            uint32_t a1 = sb + 18432 + (uint32_t)((rq + 8 + g) * 144 + pc * 2);
            __half2 p01 = __floats2half2_rn(sc[nf][0], sc[nf][1]);
            __half2 p23 = __floats2half2_rn(sc[nf][2], sc[nf][3]);
            asm volatile("st.shared.b32 [%0], %1;" ::"r"(a0),
                         "r"(*(uint32_t*)&p01) : "memory");
            asm volatile("st.shared.b32 [%0], %1;" ::"r"(a1),
                         "r"(*(uint32_t*)&p23) : "memory");
        }
        __syncwarp();
#pragma unroll
        for (int kk = 0; kk < 4; kk++) {
            uint32_t af[4], bf[4][4];
            ldsm4(af, sb + 18432 + aQoff + kk * 32);
#pragma unroll
            for (int j = 0; j < 4; j++) ldsm4(bf[j], Vst + bOff[j] + kk * 32);
#pragma unroll
            for (int nf = 0; nf < 8; nf++) {
                uint32_t b0 = bf[nf >> 1][(nf & 1) * 2];
                uint32_t b1 = bf[nf >> 1][(nf & 1) * 2 + 1];
                mma16(o[nf], af[0], af[1], af[2], af[3], b0, b1);
            }
        }
        __syncthreads();

        int jn = kt + 2;
        if (jn < 16) {
            int r = t >> 2, j0 = (t & 3) * 2;
            const __half* Ks = Kb + (long)(jn * 64) * EDIM;
            const __half* Vs = Vb + jn * 64;
#pragma unroll
            for (int j = 0; j < 2; j++) {
                cp16(Kst + (uint32_t)(r * 144 + (j0 + j) * 16), Ks + (long)r * EDIM + (j0 + j) * 8);
                cp16(Vst + (uint32_t)(r * 144 + (j0 + j) * 16), Vs + (long)r * SEQ + (j0 + j) * 8);
            }
        }
        cp_commit();
    }

    float il0 = 1.f / l_[0], il1 = 1.f / l_[1];
#pragma unroll
    for (int nf = 0; nf < 8; nf++) {
        long rowg = (long)(b * SEQ + qt * 128 + rq + g);
        int colg = h * HD + nf * 8 + 2 * tg;
        *(__half2*)&O[rowg * EDIM + colg] = __floats2half2_rn(o[nf][0] * il0, o[nf][1] * il0);
        *(__half2*)&O[(rowg + 8) * EDIM + colg] = __floats2half2_rn(o[nf][2] * il1, o[nf][3] * il1);
    }
}

// ---------------- fused residual add + LayerNorm (y fp16; fp32 + fp16 outputs) ------
__global__ __launch_bounds__(192) void ln_res_kernel(const float* __restrict__ x,
                                                     const __half* __restrict__ y,
                                                     const float* __restrict__ gam,
                                                     const float* __restrict__ bet,
                                                     float* __restrict__ out,
                                                     __half* __restrict__ outh) {
    int row = blockIdx.x, t = threadIdx.x;
    const float4* xr = (const float4*)(x + (long)row * EDIM);
    const __half2* yr = (const __half2*)(y + (long)row * EDIM);
    float4 a = xr[t];
    float2 y01 = __half22float2(yr[2 * t]);
    float2 y23 = __half22float2(yr[2 * t + 1]);
    float v0 = a.x + y01.x, v1 = a.y + y01.y, v2 = a.z + y23.x, v3 = a.w + y23.y;
    float s1 = v0 + v1 + v2 + v3;
    float s2 = v0 * v0 + v1 * v1 + v2 * v2 + v3 * v3;
    __shared__ float sh[2][6];
    int lane = t & 31, w = t >> 5;
#pragma unroll
    for (int off = 16; off; off >>= 1) {
        s1 += __shfl_xor_sync(0xffffffffu, s1, off);
        s2 += __shfl_xor_sync(0xffffffffu, s2, off);
    }
    if (!lane) { sh[0][w] = s1; sh[1][w] = s2; }
    __syncthreads();
    float a1 = 0.f, a2 = 0.f;
#pragma unroll
    for (int i = 0; i < 6; i++) { a1 += sh[0][i]; a2 += sh[1][i]; }
    float mean = a1 * (1.f / EDIM);
    float var = a2 * (1.f / EDIM) - mean * mean;
    float rstd = rsqrtf(var + 1e-5f);
    float4 gg = ((const float4*)gam)[t];
    float4 bb = ((const float4*)bet)[t];
    float4 o;
    o.x = (v0 - mean) * rstd * gg.x + bb.x;
    o.y = (v1 - mean) * rstd * gg.y + bb.y;
    o.z = (v2 - mean) * rstd * gg.z + bb.z;
    o.w = (v3 - mean) * rstd * gg.w + bb.w;
    ((float4*)(out + (long)row * EDIM))[t] = o;
    __half2* oh = (__half2*)(outh + (long)row * EDIM);
    oh[2 * t] = __floats2half2_rn(o.x, o.y);
    oh[2 * t + 1] = __floats2half2_rn(o.z, o.w);
}

// ---------------- mean pool: one warp per float4 output ----------------
__global__ __launch_bounds__(256) void pool_kernel(const float* __restrict__ x,
                                                   float* __restrict__ p) {
    int wid = (blockIdx.x * blockDim.x + threadIdx.x) >> 5;
    int lane = threadIdx.x & 31;
    if (wid >= 8 * (EDIM / 4)) return;
    int b = wid / (EDIM / 4), e4 = wid % (EDIM / 4);
    const float4* xb = (const float4*)(x + (long)b * SEQ * EDIM) + e4;
    float4 s = make_float4(0.f, 0.f, 0.f, 0.f);
    for (int si = lane; si < SEQ; si += 32) {
        float4 v = xb[(long)si * (EDIM / 4)];
        s.x += v.x; s.y += v.y; s.z += v.z; s.w += v.w;
    }
#pragma unroll
    for (int off = 16; off; off >>= 1) {
        s.x += __shfl_xor_sync(0xffffffffu, s.x, off);
        s.y += __shfl_xor_sync(0xffffffffu, s.y, off);
        s.z += __shfl_xor_sync(0xffffffffu, s.z, off);
        s.w += __shfl_xor_sync(0xffffffffu, s.w, off);
    }
    if (!lane) {
        s.x *= (1.f / SEQ); s.y *= (1.f / SEQ); s.z *= (1.f / SEQ); s.w *= (1.f / SEQ);
        ((float4*)p)[wid] = s;
    }
}

// ---------------- classifier ----------------
__global__ void cls_kernel(const float* __restrict__ p, const float* __restrict__ Wc,
                           const float* __restrict__ bc, float* __restrict__ out) {
    int w = threadIdx.x >> 5, lane = threadIdx.x & 31;
    int b = w >> 1, c = w & 1;
    float s = 0.f;
    for (int e = lane; e < EDIM; e += 32) s += p[b * EDIM + e] * Wc[e * 2 + c];
#pragma unroll
    for (int off = 16; off; off >>= 1) s += __shfl_xor_sync(0xffffffffu, s, off);
    if (!lane) out[b * 2 + c] = s + bc[c];
}

// ---------------- launch ----------------
extern "C" void kernel_launch(void* const* d_in, const int* in_sizes, int n_in,
                              void* d_out, int out_size) {
    (void)in_sizes; (void)n_in; (void)out_size;
    const int* ids = (const int*)d_in[0];
    const int* amask = (const int*)d_in[1];
    const float* emb = (const float*)d_in[2];
    const float* pe = (const float*)d_in[3];
    const float* Wq = (const float*)d_in[4];
    const float* bq = (const float*)d_in[5];
    const float* Wk = (const float*)d_in[6];
    const float* bk = (const float*)d_in[7];
    const float* Wv = (const float*)d_in[8];
    const float* bv = (const float*)d_in[9];
    const float* Wo = (const float*)d_in[10];
    const float* bo = (const float*)d_in[11];
    const float* l1g = (const float*)d_in[12];
    const float* l1b = (const float*)d_in[13];
    const float* W1 = (const float*)d_in[14];
    const float* b1 = (const float*)d_in[15];
    const float* W2 = (const float*)d_in[16];
    const float* b2 = (const float*)d_in[17];
    const float* l2g = (const float*)d_in[18];
    const float* l2b = (const float*)d_in[19];
    const float* Wc = (const float*)d_in[20];
    const float* bc = (const float*)d_in[21];
    float* out = (float*)d_out;

    float *x, *pl;
    __half *xh, *qh, *kh, *vh, *atth, *th, *ffnh, *wt;
    cudaGetSymbolAddress((void**)&x, g_x);
    cudaGetSymbolAddress((void**)&xh, g_xh);
    cudaGetSymbolAddress((void**)&qh, g_qh);
    cudaGetSymbolAddress((void**)&kh, g_kh);
    cudaGetSymbolAddress((void**)&vh, g_vh);
    cudaGetSymbolAddress((void**)&atth, g_atth);
    cudaGetSymbolAddress((void**)&th, g_th);
    cudaGetSymbolAddress((void**)&ffnh, g_ffnh);
    cudaGetSymbolAddress((void**)&pl, g_pool);
    cudaGetSymbolAddress((void**)&wt, g_wt);

    cudaFuncSetAttribute(gemm_h, cudaFuncAttributeMaxDynamicSharedMemorySize, GEMM_SMEM);
    cudaFuncSetAttribute(attn_kernel, cudaFuncAttributeMaxDynamicSharedMemorySize, ATT_SMEM);

    // one-time: transpose + fp16-convert all weights (batched over layers)
    dim3 tb(32, 8);
    transpose_all<<<dim3(EDIM / 32, EDIM / 32, NLAYER), tb>>>(Wq, wt + 0L * EE, EDIM, EDIM,
                                                             (long)EE, (long)WT_PER_LAYER);
    transpose_all<<<dim3(EDIM / 32, EDIM / 32, NLAYER), tb>>>(Wk, wt + 1L * EE, EDIM, EDIM,
                                                             (long)EE, (long)WT_PER_LAYER);
    transpose_all<<<dim3(EDIM / 32, EDIM / 32, NLAYER), tb>>>(Wv, wt + 2L * EE, EDIM, EDIM,
                                                             (long)EE, (long)WT_PER_LAYER);
    transpose_all<<<dim3(EDIM / 32, EDIM / 32, NLAYER), tb>>>(Wo, wt + 3L * EE, EDIM, EDIM,
                                                             (long)EE, (long)WT_PER_LAYER);
    transpose_all<<<dim3(FDIM / 32, EDIM / 32, NLAYER), tb>>>(W1, wt + 4L * EE, EDIM, FDIM,
                                                             (long)EF, (long)WT_PER_LAYER);
    transpose_all<<<dim3(EDIM / 32, FDIM / 32, NLAYER), tb>>>(W2, wt + 4L * EE + EF, FDIM, EDIM,
                                                             (long)EF, (long)WT_PER_LAYER);

    embed_kernel<<<(TOKS * EDIM + 255) / 256, 256>>>(ids, emb, pe, x, xh);

    for (int l = 0; l < NLAYER; l++) {
        long boff = (long)l * EDIM;
        __half* base = wt + (long)l * WT_PER_LAYER;
        Trip tq = {base + 0L * EE, bq + boff, qh, 2};
        Trip tk = {base + 1L * EE, bk + boff, kh, 2};
        Trip tv = {base + 2L * EE, bv + boff, vh, 3};
        gemm_h<<<dim3(6, 64, 3), 256, GEMM_SMEM>>>(xh, tq, tk, tv, EDIM, EDIM);
        attn_kernel<<<dim3(8, 12, 8), 256, ATT_SMEM>>>(qh, kh, vh, amask, atth);
        Trip to = {base + 3L * EE, bo + boff, th, 2};
        gemm_h<<<dim3(6, 64, 1), 256, GEMM_SMEM>>>(atth, to, to, to, EDIM, EDIM);
        ln_res_kernel<<<TOKS, 192>>>(x, th, l1g + boff, l1b + boff, x, xh);
        Trip t1 = {base + 4L * EE, b1 + (long)l * FDIM, ffnh, 1};
        gemm_h<<<dim3(24, 64, 1), 256, GEMM_SMEM>>>(xh, t1, t1, t1, FDIM, EDIM);
        Trip t2 = {base + 4L * EE + EF, b2 + boff, th, 2};
        gemm_h<<<dim3(6, 64, 1), 256, GEMM_SMEM>>>(ffnh, t2, t2, t2, EDIM, FDIM);
        ln_res_kernel<<<TOKS, 192>>>(x, th, l2g + boff, l2b + boff, x, xh);
    }

    pool_kernel<<<(8 * (EDIM / 4) * 32 + 255) / 256, 256>>>(x, pl);
    cls_kernel<<<1, 512>>>(pl, Wc, bc, out);
}

// round 16
// speedup vs baseline: 2.1635x; 1.0083x over previous
#include <cuda_runtime.h>
#include <cuda_fp16.h>
#include <cstdint>

#define TOKS 8192
#define EDIM 768
#define FDIM 3072
#define SEQ  1024
#define NH   12
#define HD   64
#define NLAYER 6

#define EE (EDIM * EDIM)
#define EF (EDIM * FDIM)
#define WT_PER_LAYER (4 * EE + 2 * EF)

// ---------------- scratch (device globals; no allocation) ----------------
__device__ __half g_xh[TOKS * EDIM];        // fp16 residual stream (LN output)
__device__ __half g_qh[TOKS * EDIM];        // Q fp16
__device__ __half g_kh[TOKS * EDIM];        // K fp16
__device__ __half g_vh[TOKS * EDIM];        // V^T fp16: [b][h][hd][seq]
__device__ __half g_atth[TOKS * EDIM];      // attention out (fp16, feeds O-proj)
__device__ __half g_th[TOKS * EDIM];        // O-proj / FFN2 out (fp16, feeds LN)
__device__ __half g_ffnh[TOKS * FDIM];      // relu out (fp16, feeds FFN2)
__device__ float g_pool[8 * EDIM];
__device__ __half g_wt[(long)NLAYER * WT_PER_LAYER];  // transposed fp16 weights

// ---------------- helpers ----------------
__device__ __forceinline__ void mma16(float* c, uint32_t a0, uint32_t a1, uint32_t a2, uint32_t a3,
                                      uint32_t b0, uint32_t b1) {
    asm volatile(
        "mma.sync.aligned.m16n8k16.row.col.f32.f16.f16.f32 "
        "{%0,%1,%2,%3}, {%4,%5,%6,%7}, {%8,%9}, {%0,%1,%2,%3};"
        : "+f"(c[0]), "+f"(c[1]), "+f"(c[2]), "+f"(c[3])
        : "r"(a0), "r"(a1), "r"(a2), "r"(a3), "r"(b0), "r"(b1));
}

__device__ __forceinline__ void ldsm4(uint32_t* r, uint32_t a) {
    asm volatile("ldmatrix.sync.aligned.m8n8.x4.shared.b16 {%0,%1,%2,%3}, [%4];"
                 : "=r"(r[0]), "=r"(r[1]), "=r"(r[2]), "=r"(r[3]) : "r"(a));
}

__device__ __forceinline__ void cp16(uint32_t saddr, const void* gaddr) {
    asm volatile("cp.async.cg.shared.global [%0], [%1], 16;" ::"r"(saddr), "l"(gaddr));
}
__device__ __forceinline__ void cp_commit() { asm volatile("cp.async.commit_group;"); }

__device__ __forceinline__ uint32_t smem_u32(const void* p) {
    uint32_t a;
    asm("{ .reg .u64 t; cvta.to.shared.u64 t, %1; cvt.u32.u64 %0, t; }" : "=r"(a) : "l"(p));
    return a;
}

// ---------------- batched weight transpose -> fp16: dst[N][K] = (half)src[K][N]^T ----
__global__ void transpose_all(const float* __restrict__ src, __half* __restrict__ dst,
                              int K, int N, long sstride, long dstride) {
    int lz = blockIdx.z;
    src += (long)lz * sstride;
    dst += (long)lz * dstride;
    __shared__ float tl[32][33];
    int n0 = blockIdx.x * 32, k0 = blockIdx.y * 32;
    int tx = threadIdx.x, ty = threadIdx.y;
#pragma unroll
    for (int j = 0; j < 32; j += 8) tl[ty + j][tx] = src[(long)(k0 + ty + j) * N + n0 + tx];
    __syncthreads();
#pragma unroll
    for (int j = 0; j < 32; j += 8)
        dst[(long)(n0 + ty + j) * K + k0 + tx] = __float2half_rn(tl[tx][ty + j]);
}

// ---------------- embedding + positional encoding (fp16 out) ----------------
__global__ void embed_kernel(const int* __restrict__ ids, const float* __restrict__ emb,
                             const float* __restrict__ pe, __half* __restrict__ xh) {
    long idx = (long)blockIdx.x * blockDim.x + threadIdx.x;
    if (idx >= (long)TOKS * EDIM) return;
    int tok = (int)(idx / EDIM);
    int e = (int)(idx - (long)tok * EDIM);
    int s = tok & (SEQ - 1);
    xh[idx] = __float2half_rn(emb[(long)ids[tok] * EDIM + e] + pe[s * EDIM + e]);
}

// ---------------- fp16 mma GEMM: block 128x128, BK=64, 3-stage, 256 thr (2x4) -------
// modes: 1 relu half out, 2 half out, 3 half V^T scatter
struct Trip {
    const __half* W;   // [N][K] transposed fp16
    const float* b;
    __half* C;
    int mode;
};

#define GROW 144                 // 64 halfs (128B) + 16B pad
#define GAS (128 * GROW)         // 18432 per tensor
#define GSTAGE (2 * GAS)         // 36864
#define GEMM_SMEM (3 * GSTAGE)   // 110592

__global__ __launch_bounds__(256, 2) void gemm_h(const __half* __restrict__ A,
                                                 Trip t0, Trip t1, Trip t2,
                                                 int N, int K) {
    extern __shared__ __align__(128) char smc[];
    uint32_t sb = smem_u32(smc);
    int t = threadIdx.x, l = t & 31, warp = t >> 5;
    int wm = warp >> 2, wn = warp & 3;
    int g = l >> 2, tg = l & 3;

    int z = blockIdx.z;
    Trip tr = (z == 0) ? t0 : (z == 1) ? t1 : t2;
    long bm = blockIdx.y, bn = blockIdx.x;
    const __half* Ab = A + bm * 128 * (long)K;
    const __half* Bb = tr.W + bn * 128 * (long)K;

    int ra = t >> 3, seg = t & 7;

    uint32_t aOff[4], bOff[2];
#pragma unroll
    for (int mf = 0; mf < 4; mf++)
        aOff[mf] = (uint32_t)((wm * 64 + mf * 16 + (l & 7) + ((l >> 3) & 1) * 8) * GROW +
                              (l >> 4) * 16);
#pragma unroll
    for (int j = 0; j < 2; j++)
        bOff[j] = (uint32_t)(GAS +
                             (wn * 32 + j * 16 + (l & 7) + (l >> 4) * 8) * GROW +
                             ((l >> 3) & 1) * 16);

    float acc[4][4][4];
#pragma unroll
    for (int i = 0; i < 4; i++)
#pragma unroll
        for (int j = 0; j < 4; j++)
#pragma unroll
            for (int q = 0; q < 4; q++) acc[i][j][q] = 0.f;

    int niter = K >> 6;

#pragma unroll
    for (int st = 0; st < 2; st++) {
        uint32_t sA = sb + st * GSTAGE, sB = sA + GAS;
        int k0 = st * 64;
#pragma unroll
        for (int p = 0; p < 4; p++) {
            int r = ra + p * 32;
            cp16(sA + (uint32_t)(r * GROW + seg * 16), Ab + (long)r * K + k0 + seg * 8);
            cp16(sB + (uint32_t)(r * GROW + seg * 16), Bb + (long)r * K + k0 + seg * 8);
        }
        cp_commit();
    }

    int s = 0;
    for (int it = 0; it < niter; it++) {
        asm volatile("cp.async.wait_group 1;");
        __syncthreads();

        int jn = it + 2;
        if (jn < niter) {
            int s2 = jn % 3;
            uint32_t sA2 = sb + s2 * GSTAGE, sB2 = sA2 + GAS;
            int k0 = jn * 64;
#pragma unroll
            for (int p = 0; p < 4; p++) {
                int r = ra + p * 32;
                cp16(sA2 + (uint32_t)(r * GROW + seg * 16), Ab + (long)r * K + k0 + seg * 8);
                cp16(sB2 + (uint32_t)(r * GROW + seg * 16), Bb + (long)r * K + k0 + seg * 8);
            }
        }
        cp_commit();

        uint32_t sA = sb + s * GSTAGE;
#pragma unroll
        for (int kk = 0; kk < 4; kk++) {
            uint32_t af[4][4], bf[2][4];
#pragma unroll
            for (int mf = 0; mf < 4; mf++) ldsm4(af[mf], sA + aOff[mf] + kk * 32);
#pragma unroll
            for (int j = 0; j < 2; j++) ldsm4(bf[j], sA + bOff[j] + kk * 32);
#pragma unroll
            for (int mf = 0; mf < 4; mf++) {
#pragma unroll
                for (int nf = 0; nf < 4; nf++) {
                    uint32_t b0 = bf[nf >> 1][(nf & 1) * 2];
                    uint32_t b1 = bf[nf >> 1][(nf & 1) * 2 + 1];
                    mma16(acc[mf][nf], af[mf][0], af[mf][1], af[mf][2], af[mf][3], b0, b1);
                }
            }
        }
        s = (s == 2) ? 0 : s + 1;
    }

    int mode = tr.mode;
    const float* bias = tr.b;
    __half* Ch = tr.C;
#pragma unroll
    for (int mf = 0; mf < 4; mf++) {
        int r0 = (int)bm * 128 + wm * 64 + mf * 16 + g;
#pragma unroll
        for (int nf = 0; nf < 4; nf++) {
            int c0 = (int)bn * 128 + wn * 32 + nf * 8 + 2 * tg;
            float bb0 = bias[c0], bb1 = bias[c0 + 1];
            float v0 = acc[mf][nf][0] + bb0;
            float v1 = acc[mf][nf][1] + bb1;
            float v2 = acc[mf][nf][2] + bb0;
            float v3 = acc[mf][nf][3] + bb1;
            if (mode == 1) {
                v0 = fmaxf(v0, 0.f); v1 = fmaxf(v1, 0.f);
                v2 = fmaxf(v2, 0.f); v3 = fmaxf(v3, 0.f);
            }
            if (mode == 3) {
                int b_ = r0 >> 10, sp = r0 & 1023;
                int h0 = c0 >> 6, d0 = c0 & 63;
                long vb = ((long)(b_ * NH + h0) * HD + d0) * SEQ + sp;
                Ch[vb] = __float2half_rn(v0);
                Ch[vb + SEQ] = __float2half_rn(v1);
                Ch[vb + 8] = __float2half_rn(v2);
                Ch[vb + SEQ + 8] = __float2half_rn(v3);
            } else {
                *(__half2*)&Ch[(long)r0 * N + c0] = __floats2half2_rn(v0, v1);
                *(__half2*)&Ch[(long)(r0 + 8) * N + c0] = __floats2half2_rn(v2, v3);
            }
        }
    }
}

// ---------------- fused flash attention (fp16 mma), q-tile 128, 2-stage K/V ---------
// smem: Q[128][144B] @0, P @18432, mask(f32) @36864, stages @40960 + s*18432
#define ATT_SMEM 77824

__global__ __launch_bounds__(256, 2) void attn_kernel(const __half* __restrict__ Q,
                                                      const __half* __restrict__ Kp,
                                                      const __half* __restrict__ Vt,
                                                      const int* __restrict__ mask,
                                                      __half* __restrict__ O) {
    extern __shared__ __align__(128) char smc[];
    uint32_t sb = smem_u32(smc);
    float* mAdd = (float*)(smc + 36864);

    int t = threadIdx.x, l = t & 31, warp = t >> 5;
    int g = l >> 2, tg = l & 3;
    int b = blockIdx.z, h = blockIdx.y, qt = blockIdx.x;
    int rq = warp * 16;

    const __half* Qb = Q + ((long)(b * SEQ + qt * 128)) * EDIM + h * HD;
    const __half* Kb = Kp + ((long)(b * SEQ)) * EDIM + h * HD;
    const __half* Vb = Vt + ((long)(b * NH + h) * HD) * SEQ;

    uint32_t aQoff = (uint32_t)((rq + (l & 7) + ((l >> 3) & 1) * 8) * 144 + (l >> 4) * 16);
    uint32_t bOff[4];
#pragma unroll
    for (int j = 0; j < 4; j++)
        bOff[j] = (uint32_t)((j * 16 + (l & 7) + (l >> 4) * 8) * 144 + ((l >> 3) & 1) * 16);

    {
        int r = t >> 1, s0 = (t & 1) * 4;
#pragma unroll
        for (int j = 0; j < 4; j++)
            cp16(sb + (uint32_t)(r * 144 + (s0 + j) * 16), Qb + (long)r * EDIM + (s0 + j) * 8);
        cp_commit();
    }
    for (int i = t; i < SEQ; i += 256) mAdd[i] = mask[b * SEQ + i] ? 0.f : -1e30f;

#pragma unroll
    for (int st = 0; st < 2; st++) {
        uint32_t Kst = sb + 40960 + st * 18432, Vst = Kst + 9216;
        int r = t >> 2, j0 = (t & 3) * 2;
        const __half* Ks = Kb + (long)(st * 64) * EDIM;
        const __half* Vs = Vb + st * 64;
#pragma unroll
        for (int j = 0; j < 2; j++) {
            cp16(Kst + (uint32_t)(r * 144 + (j0 + j) * 16), Ks + (long)r * EDIM + (j0 + j) * 8);
            cp16(Vst + (uint32_t)(r * 144 + (j0 + j) * 16), Vs + (long)r * SEQ + (j0 + j) * 8);
        }
        cp_commit();
    }

    float m_[2] = {-INFINITY, -INFINITY};
    float l_[2] = {0.f, 0.f};
    float o[8][4];
#pragma unroll
    for (int nf = 0; nf < 8; nf++)
#pragma unroll
        for (int q = 0; q < 4; q++) o[nf][q] = 0.f;

    for (int kt = 0; kt < 16; kt++) {
        int s = kt & 1;
        uint32_t Kst = sb + 40960 + s * 18432, Vst = Kst + 9216;
        asm volatile("cp.async.wait_group 1;");
        __syncthreads();

        float sc[8][4];
#pragma unroll
        for (int nf = 0; nf < 8; nf++)
#pragma unroll
            for (int q = 0; q < 4; q++) sc[nf][q] = 0.f;
#pragma unroll
        for (int kk = 0; kk < 4; kk++) {
            uint32_t af[4], bf[4][4];
            ldsm4(af, sb + aQoff + kk * 32);
#pragma unroll
            for (int j = 0; j < 4; j++) ldsm4(bf[j], Kst + bOff[j] + kk * 32);
#pragma unroll
            for (int nf = 0; nf < 8; nf++) {
                uint32_t b0 = bf[nf >> 1][(nf & 1) * 2];
                uint32_t b1 = bf[nf >> 1][(nf & 1) * 2 + 1];
                mma16(sc[nf], af[0], af[1], af[2], af[3], b0, b1);
            }
        }

        float rmax0 = -INFINITY, rmax1 = -INFINITY;
#pragma unroll
        for (int nf = 0; nf < 8; nf++) {
            int c0 = kt * 64 + nf * 8 + 2 * tg;
            float ma = mAdd[c0], mb = mAdd[c0 + 1];
            sc[nf][0] = sc[nf][0] * 0.125f + ma;
            sc[nf][1] = sc[nf][1] * 0.125f + mb;
            sc[nf][2] = sc[nf][2] * 0.125f + ma;
            sc[nf][3] = sc[nf][3] * 0.125f + mb;
            rmax0 = fmaxf(rmax0, fmaxf(sc[nf][0], sc[nf][1]));
            rmax1 = fmaxf(rmax1, fmaxf(sc[nf][2], sc[nf][3]));
        }
        rmax0 = fmaxf(rmax0, __shfl_xor_sync(0xffffffffu, rmax0, 1));
        rmax0 = fmaxf(rmax0, __shfl_xor_sync(0xffffffffu, rmax0, 2));
        rmax1 = fmaxf(rmax1, __shfl_xor_sync(0xffffffffu, rmax1, 1));
        rmax1 = fmaxf(rmax1, __shfl_xor_sync(0xffffffffu, rmax1, 2));
        float mn0 = fmaxf(m_[0], rmax0), mn1 = fmaxf(m_[1], rmax1);
        float cf0 = __expf(m_[0] - mn0), cf1 = __expf(m_[1] - mn1);
        float rs0 = 0.f, rs1 = 0.f;
#pragma unroll
        for (int nf = 0; nf < 8; nf++) {
            sc[nf][0] = __expf(sc[nf][0] - mn0);
            sc[nf][1] = __expf(sc[nf][1] - mn0);
            sc[nf][2] = __expf(sc[nf][2] - mn1);
            sc[nf][3] = __expf(sc[nf][3] - mn1);
            rs0 += sc[nf][0] + sc[nf][1];
            rs1 += sc[nf][2] + sc[nf][3];
        }
        rs0 += __shfl_xor_sync(0xffffffffu, rs0, 1);
        rs0 += __shfl_xor_sync(0xffffffffu, rs0, 2);
        rs1 += __shfl_xor_sync(0xffffffffu, rs1, 1);
        rs1 += __shfl_xor_sync(0xffffffffu, rs1, 2);
        l_[0] = l_[0] * cf0 + rs0;
        l_[1] = l_[1] * cf1 + rs1;
        m_[0] = mn0; m_[1] = mn1;
#pragma unroll
        for (int nf = 0; nf < 8; nf++) {
            o[nf][0] *= cf0; o[nf][1] *= cf0;
            o[nf][2] *= cf1; o[nf][3] *= cf1;
        }

#pragma unroll
        for (int nf = 0; nf < 8; nf++) {
            int pc = nf * 8 + 2 * tg;
            uint32_t a0 = sb + 18432 + (uint32_t)((rq + g) * 144 + pc * 2);
            uint32_t a1 = sb + 18432 + (uint32_t)((rq + 8 + g) * 144 + pc * 2);
            __half2 p01 = __floats2half2_rn(sc[nf][0], sc[nf][1]);
            __half2 p23 = __floats2half2_rn(sc[nf][2], sc[nf][3]);
            asm volatile("st.shared.b32 [%0], %1;" ::"r"(a0),
                         "r"(*(uint32_t*)&p01) : "memory");
            asm volatile("st.shared.b32 [%0], %1;" ::"r"(a1),
                         "r"(*(uint32_t*)&p23) : "memory");
        }
        __syncwarp();
#pragma unroll
        for (int kk = 0; kk < 4; kk++) {
            uint32_t af[4], bf[4][4];
            ldsm4(af, sb + 18432 + aQoff + kk * 32);
#pragma unroll
            for (int j = 0; j < 4; j++) ldsm4(bf[j], Vst + bOff[j] + kk * 32);
#pragma unroll
            for (int nf = 0; nf < 8; nf++) {
                uint32_t b0 = bf[nf >> 1][(nf & 1) * 2];
                uint32_t b1 = bf[nf >> 1][(nf & 1) * 2 + 1];
                mma16(o[nf], af[0], af[1], af[2], af[3], b0, b1);
            }
        }
        __syncthreads();

        int jn = kt + 2;
        if (jn < 16) {
            int r = t >> 2, j0 = (t & 3) * 2;
            const __half* Ks = Kb + (long)(jn * 64) * EDIM;
            const __half* Vs = Vb + jn * 64;
#pragma unroll
            for (int j = 0; j < 2; j++) {
                cp16(Kst + (uint32_t)(r * 144 + (j0 + j) * 16), Ks + (long)r * EDIM + (j0 + j) * 8);
                cp16(Vst + (uint32_t)(r * 144 + (j0 + j) * 16), Vs + (long)r * SEQ + (j0 + j) * 8);
            }
        }
        cp_commit();
    }

    float il0 = 1.f / l_[0], il1 = 1.f / l_[1];
#pragma unroll
    for (int nf = 0; nf < 8; nf++) {
        long rowg = (long)(b * SEQ + qt * 128 + rq + g);
        int colg = h * HD + nf * 8 + 2 * tg;
        *(__half2*)&O[rowg * EDIM + colg] = __floats2half2_rn(o[nf][0] * il0, o[nf][1] * il0);
        *(__half2*)&O[(rowg + 8) * EDIM + colg] = __floats2half2_rn(o[nf][2] * il1, o[nf][3] * il1);
    }
}

// ---------------- fused residual add + LayerNorm (fp16 streams, fp32 math) ----------
__global__ __launch_bounds__(192) void ln_res_kernel(const __half* __restrict__ xh,
                                                     const __half* __restrict__ y,
                                                     const float* __restrict__ gam,
                                                     const float* __restrict__ bet,
                                                     __half* __restrict__ outh) {
    int row = blockIdx.x, t = threadIdx.x;
    const __half2* xr = (const __half2*)(xh + (long)row * EDIM);
    const __half2* yr = (const __half2*)(y + (long)row * EDIM);
    float2 x01 = __half22float2(xr[2 * t]);
    float2 x23 = __half22float2(xr[2 * t + 1]);
    float2 y01 = __half22float2(yr[2 * t]);
    float2 y23 = __half22float2(yr[2 * t + 1]);
    float v0 = x01.x + y01.x, v1 = x01.y + y01.y;
    float v2 = x23.x + y23.x, v3 = x23.y + y23.y;
    float s1 = v0 + v1 + v2 + v3;
    float s2 = v0 * v0 + v1 * v1 + v2 * v2 + v3 * v3;
    __shared__ float sh[2][6];
    int lane = t & 31, w = t >> 5;
#pragma unroll
    for (int off = 16; off; off >>= 1) {
        s1 += __shfl_xor_sync(0xffffffffu, s1, off);
        s2 += __shfl_xor_sync(0xffffffffu, s2, off);
    }
    if (!lane) { sh[0][w] = s1; sh[1][w] = s2; }
    __syncthreads();
    float a1 = 0.f, a2 = 0.f;
#pragma unroll
    for (int i = 0; i < 6; i++) { a1 += sh[0][i]; a2 += sh[1][i]; }
    float mean = a1 * (1.f / EDIM);
    float var = a2 * (1.f / EDIM) - mean * mean;
    float rstd = rsqrtf(var + 1e-5f);
    float4 gg = ((const float4*)gam)[t];
    float4 bb = ((const float4*)bet)[t];
    __half2* oh = (__half2*)(outh + (long)row * EDIM);
    oh[2 * t] = __floats2half2_rn((v0 - mean) * rstd * gg.x + bb.x,
                                  (v1 - mean) * rstd * gg.y + bb.y);
    oh[2 * t + 1] = __floats2half2_rn((v2 - mean) * rstd * gg.z + bb.z,
                                      (v3 - mean) * rstd * gg.w + bb.w);
}

// ---------------- mean pool (fp16 in, fp32 accumulate): one warp per 4 outputs ------
__global__ __launch_bounds__(256) void pool_kernel(const __half* __restrict__ xh,
                                                   float* __restrict__ p) {
    int wid = (blockIdx.x * blockDim.x + threadIdx.x) >> 5;
    int lane = threadIdx.x & 31;
    if (wid >= 8 * (EDIM / 4)) return;
    int b = wid / (EDIM / 4), e4 = wid % (EDIM / 4);
    const __half2* xb = (const __half2*)(xh + (long)b * SEQ * EDIM) + 2 * e4;
    float4 s = make_float4(0.f, 0.f, 0.f, 0.f);
    for (int si = lane; si < SEQ; si += 32) {
        float2 a = __half22float2(xb[(long)si * (EDIM / 2)]);
        float2 c = __half22float2(xb[(long)si * (EDIM / 2) + 1]);
        s.x += a.x; s.y += a.y; s.z += c.x; s.w += c.y;
    }
#pragma unroll
    for (int off = 16; off; off >>= 1) {
        s.x += __shfl_xor_sync(0xffffffffu, s.x, off);
        s.y += __shfl_xor_sync(0xffffffffu, s.y, off);
        s.z += __shfl_xor_sync(0xffffffffu, s.z, off);
        s.w += __shfl_xor_sync(0xffffffffu, s.w, off);
    }
    if (!lane) {
        s.x *= (1.f / SEQ); s.y *= (1.f / SEQ); s.z *= (1.f / SEQ); s.w *= (1.f / SEQ);
        ((float4*)p)[wid] = s;
    }
}

// ---------------- classifier ----------------
__global__ void cls_kernel(const float* __restrict__ p, const float* __restrict__ Wc,
                           const float* __restrict__ bc, float* __restrict__ out) {
    int w = threadIdx.x >> 5, lane = threadIdx.x & 31;
    int b = w >> 1, c = w & 1;
    float s = 0.f;
    for (int e = lane; e < EDIM; e += 32) s += p[b * EDIM + e] * Wc[e * 2 + c];
#pragma unroll
    for (int off = 16; off; off >>= 1) s += __shfl_xor_sync(0xffffffffu, s, off);
    if (!lane) out[b * 2 + c] = s + bc[c];
}

// ---------------- launch ----------------
extern "C" void kernel_launch(void* const* d_in, const int* in_sizes, int n_in,
                              void* d_out, int out_size) {
    (void)in_sizes; (void)n_in; (void)out_size;
    const int* ids = (const int*)d_in[0];
    const int* amask = (const int*)d_in[1];
    const float* emb = (const float*)d_in[2];
    const float* pe = (const float*)d_in[3];
    const float* Wq = (const float*)d_in[4];
    const float* bq = (const float*)d_in[5];
    const float* Wk = (const float*)d_in[6];
    const float* bk = (const float*)d_in[7];
    const float* Wv = (const float*)d_in[8];
    const float* bv = (const float*)d_in[9];
    const float* Wo = (const float*)d_in[10];
    const float* bo = (const float*)d_in[11];
    const float* l1g = (const float*)d_in[12];
    const float* l1b = (const float*)d_in[13];
    const float* W1 = (const float*)d_in[14];
    const float* b1 = (const float*)d_in[15];
    const float* W2 = (const float*)d_in[16];
    const float* b2 = (const float*)d_in[17];
    const float* l2g = (const float*)d_in[18];
    const float* l2b = (const float*)d_in[19];
    const float* Wc = (const float*)d_in[20];
    const float* bc = (const float*)d_in[21];
    float* out = (float*)d_out;

    float* pl;
    __half *xh, *qh, *kh, *vh, *atth, *th, *ffnh, *wt;
    cudaGetSymbolAddress((void**)&xh, g_xh);
    cudaGetSymbolAddress((void**)&qh, g_qh);
    cudaGetSymbolAddress((void**)&kh, g_kh);
    cudaGetSymbolAddress((void**)&vh, g_vh);
    cudaGetSymbolAddress((void**)&atth, g_atth);
    cudaGetSymbolAddress((void**)&th, g_th);
    cudaGetSymbolAddress((void**)&ffnh, g_ffnh);
    cudaGetSymbolAddress((void**)&pl, g_pool);
    cudaGetSymbolAddress((void**)&wt, g_wt);

    cudaFuncSetAttribute(gemm_h, cudaFuncAttributeMaxDynamicSharedMemorySize, GEMM_SMEM);
    cudaFuncSetAttribute(attn_kernel, cudaFuncAttributeMaxDynamicSharedMemorySize, ATT_SMEM);

    // one-time: transpose + fp16-convert all weights (batched over layers)
    dim3 tb(32, 8);
    transpose_all<<<dim3(EDIM / 32, EDIM / 32, NLAYER), tb>>>(Wq, wt + 0L * EE, EDIM, EDIM,
                                                             (long)EE, (long)WT_PER_LAYER);
    transpose_all<<<dim3(EDIM / 32, EDIM / 32, NLAYER), tb>>>(Wk, wt + 1L * EE, EDIM, EDIM,
                                                             (long)EE, (long)WT_PER_LAYER);
    transpose_all<<<dim3(EDIM / 32, EDIM / 32, NLAYER), tb>>>(Wv, wt + 2L * EE, EDIM, EDIM,
                                                             (long)EE, (long)WT_PER_LAYER);
    transpose_all<<<dim3(EDIM / 32, EDIM / 32, NLAYER), tb>>>(Wo, wt + 3L * EE, EDIM, EDIM,
                                                             (long)EE, (long)WT_PER_LAYER);
    transpose_all<<<dim3(FDIM / 32, EDIM / 32, NLAYER), tb>>>(W1, wt + 4L * EE, EDIM, FDIM,
                                                             (long)EF, (long)WT_PER_LAYER);
    transpose_all<<<dim3(EDIM / 32, FDIM / 32, NLAYER), tb>>>(W2, wt + 4L * EE + EF, FDIM, EDIM,
                                                             (long)EF, (long)WT_PER_LAYER);

    embed_kernel<<<(TOKS * EDIM + 255) / 256, 256>>>(ids, emb, pe, xh);

    for (int l = 0; l < NLAYER; l++) {
        long boff = (long)l * EDIM;
        __half* base = wt + (long)l * WT_PER_LAYER;
        Trip tq = {base + 0L * EE, bq + boff, qh, 2};
        Trip tk = {base + 1L * EE, bk + boff, kh, 2};
        Trip tv = {base + 2L * EE, bv + boff, vh, 3};
        gemm_h<<<dim3(6, 64, 3), 256, GEMM_SMEM>>>(xh, tq, tk, tv, EDIM, EDIM);
        attn_kernel<<<dim3(8, 12, 8), 256, ATT_SMEM>>>(qh, kh, vh, amask, atth);
        Trip to = {base + 3L * EE, bo + boff, th, 2};
        gemm_h<<<dim3(6, 64, 1), 256, GEMM_SMEM>>>(atth, to, to, to, EDIM, EDIM);
        ln_res_kernel<<<TOKS, 192>>>(xh, th, l1g + boff, l1b + boff, xh);
        Trip t1 = {base + 4L * EE, b1 + (long)l * FDIM, ffnh, 1};
        gemm_h<<<dim3(24, 64, 1), 256, GEMM_SMEM>>>(xh, t1, t1, t1, FDIM, EDIM);
        Trip t2 = {base + 4L * EE + EF, b2 + boff, th, 2};
        gemm_h<<<dim3(6, 64, 1), 256, GEMM_SMEM>>>(ffnh, t2, t2, t2, EDIM, FDIM);
        ln_res_kernel<<<TOKS, 192>>>(xh, th, l2g + boff, l2b + boff, xh);
    }

    pool_kernel<<<(8 * (EDIM / 4) * 32 + 255) / 256, 256>>>(xh, pl);
    cls_kernel<<<1, 512>>>(pl, Wc, bc, out);
}

// round 17
// speedup vs baseline: 2.2220x; 1.0270x over previous
#include <cuda_runtime.h>
#include <cuda_fp16.h>
#include <cstdint>

#define TOKS 8192
#define EDIM 768
#define FDIM 3072
#define SEQ  1024
#define NH   12
#define HD   64
#define NLAYER 6

#define EE (EDIM * EDIM)
#define EF (EDIM * FDIM)
#define WT_PER_LAYER (4 * EE + 2 * EF)

// ---------------- scratch (device globals; no allocation) ----------------
__device__ __half g_xh[TOKS * EDIM];        // fp16 residual stream (LN output)
__device__ __half g_qh[TOKS * EDIM];        // Q fp16 (pre-scaled by 1/8)
__device__ __half g_kh[TOKS * EDIM];        // K fp16
__device__ __half g_vh[TOKS * EDIM];        // V^T fp16: [b][h][hd][seq]
__device__ __half g_atth[TOKS * EDIM];      // attention out (fp16, feeds O-proj)
__device__ __half g_th[TOKS * EDIM];        // O-proj / FFN2 out (fp16, feeds LN)
__device__ __half g_ffnh[TOKS * FDIM];      // relu out (fp16, feeds FFN2)
__device__ float g_pool[8 * EDIM];
__device__ __half g_wt[(long)NLAYER * WT_PER_LAYER];  // transposed fp16 weights

// ---------------- helpers ----------------
__device__ __forceinline__ void mma16(float* c, uint32_t a0, uint32_t a1, uint32_t a2, uint32_t a3,
                                      uint32_t b0, uint32_t b1) {
    asm volatile(
        "mma.sync.aligned.m16n8k16.row.col.f32.f16.f16.f32 "
        "{%0,%1,%2,%3}, {%4,%5,%6,%7}, {%8,%9}, {%0,%1,%2,%3};"
        : "+f"(c[0]), "+f"(c[1]), "+f"(c[2]), "+f"(c[3])
        : "r"(a0), "r"(a1), "r"(a2), "r"(a3), "r"(b0), "r"(b1));
}

__device__ __forceinline__ void ldsm4(uint32_t* r, uint32_t a) {
    asm volatile("ldmatrix.sync.aligned.m8n8.x4.shared.b16 {%0,%1,%2,%3}, [%4];"
                 : "=r"(r[0]), "=r"(r[1]), "=r"(r[2]), "=r"(r[3]) : "r"(a));
}

__device__ __forceinline__ void cp16(uint32_t saddr, const void* gaddr) {
    asm volatile("cp.async.cg.shared.global [%0], [%1], 16;" ::"r"(saddr), "l"(gaddr));
}
__device__ __forceinline__ void cp_commit() { asm volatile("cp.async.commit_group;"); }

__device__ __forceinline__ uint32_t smem_u32(const void* p) {
    uint32_t a;
    asm("{ .reg .u64 t; cvta.to.shared.u64 t, %1; cvt.u32.u64 %0, t; }" : "=r"(a) : "l"(p));
    return a;
}

__device__ __forceinline__ uint32_t packh2(float a, float b) {
    __half2 h = __floats2half2_rn(a, b);
    return *(uint32_t*)&h;
}

// ---------------- batched weight transpose -> fp16 (optional scale) ----------------
__global__ void transpose_all(const float* __restrict__ src, __half* __restrict__ dst,
                              int K, int N, long sstride, long dstride, float scale) {
    int lz = blockIdx.z;
    src += (long)lz * sstride;
    dst += (long)lz * dstride;
    __shared__ float tl[32][33];
    int n0 = blockIdx.x * 32, k0 = blockIdx.y * 32;
    int tx = threadIdx.x, ty = threadIdx.y;
#pragma unroll
    for (int j = 0; j < 32; j += 8) tl[ty + j][tx] = src[(long)(k0 + ty + j) * N + n0 + tx];
    __syncthreads();
#pragma unroll
    for (int j = 0; j < 32; j += 8)
        dst[(long)(n0 + ty + j) * K + k0 + tx] = __float2half_rn(tl[tx][ty + j] * scale);
}

// ---------------- embedding + positional encoding (fp16 out) ----------------
__global__ void embed_kernel(const int* __restrict__ ids, const float* __restrict__ emb,
                             const float* __restrict__ pe, __half* __restrict__ xh) {
    long idx = (long)blockIdx.x * blockDim.x + threadIdx.x;
    if (idx >= (long)TOKS * EDIM) return;
    int tok = (int)(idx / EDIM);
    int e = (int)(idx - (long)tok * EDIM);
    int s = tok & (SEQ - 1);
    xh[idx] = __float2half_rn(emb[(long)ids[tok] * EDIM + e] + pe[s * EDIM + e]);
}

// ---------------- fp16 mma GEMM: block 128x128, BK=64, 3-stage, 256 thr (2x4) -------
// modes: 1 relu half out, 2 half out, 3 half V^T scatter
struct Trip {
    const __half* W;   // [N][K] transposed fp16
    const float* b;
    __half* C;
    int mode;
    float bscale;
};

#define GROW 144                 // 64 halfs (128B) + 16B pad
#define GAS (128 * GROW)         // 18432 per tensor
#define GSTAGE (2 * GAS)         // 36864
#define GEMM_SMEM (3 * GSTAGE)   // 110592

__global__ __launch_bounds__(256, 2) void gemm_h(const __half* __restrict__ A,
                                                 Trip t0, Trip t1, Trip t2,
                                                 int N, int K) {
    extern __shared__ __align__(128) char smc[];
    uint32_t sb = smem_u32(smc);
    int t = threadIdx.x, l = t & 31, warp = t >> 5;
    int wm = warp >> 2, wn = warp & 3;
    int g = l >> 2, tg = l & 3;

    int z = blockIdx.z;
    Trip tr = (z == 0) ? t0 : (z == 1) ? t1 : t2;
    long bm = blockIdx.y, bn = blockIdx.x;
    const __half* Ab = A + bm * 128 * (long)K;
    const __half* Bb = tr.W + bn * 128 * (long)K;

    int ra = t >> 3, seg = t & 7;

    uint32_t aOff[4], bOff[2];
#pragma unroll
    for (int mf = 0; mf < 4; mf++)
        aOff[mf] = (uint32_t)((wm * 64 + mf * 16 + (l & 7) + ((l >> 3) & 1) * 8) * GROW +
                              (l >> 4) * 16);
#pragma unroll
    for (int j = 0; j < 2; j++)
        bOff[j] = (uint32_t)(GAS +
                             (wn * 32 + j * 16 + (l & 7) + (l >> 4) * 8) * GROW +
                             ((l >> 3) & 1) * 16);

    float acc[4][4][4];
#pragma unroll
    for (int i = 0; i < 4; i++)
#pragma unroll
        for (int j = 0; j < 4; j++)
#pragma unroll
            for (int q = 0; q < 4; q++) acc[i][j][q] = 0.f;

    int niter = K >> 6;

#pragma unroll
    for (int st = 0; st < 2; st++) {
        uint32_t sA = sb + st * GSTAGE, sB = sA + GAS;
        int k0 = st * 64;
#pragma unroll
        for (int p = 0; p < 4; p++) {
            int r = ra + p * 32;
            cp16(sA + (uint32_t)(r * GROW + seg * 16), Ab + (long)r * K + k0 + seg * 8);
            cp16(sB + (uint32_t)(r * GROW + seg * 16), Bb + (long)r * K + k0 + seg * 8);
        }
        cp_commit();
    }

    int s = 0;
    for (int it = 0; it < niter; it++) {
        asm volatile("cp.async.wait_group 1;");
        __syncthreads();

        int jn = it + 2;
        if (jn < niter) {
            int s2 = jn % 3;
            uint32_t sA2 = sb + s2 * GSTAGE, sB2 = sA2 + GAS;
            int k0 = jn * 64;
#pragma unroll
            for (int p = 0; p < 4; p++) {
                int r = ra + p * 32;
                cp16(sA2 + (uint32_t)(r * GROW + seg * 16), Ab + (long)r * K + k0 + seg * 8);
                cp16(sB2 + (uint32_t)(r * GROW + seg * 16), Bb + (long)r * K + k0 + seg * 8);
            }
        }
        cp_commit();

        uint32_t sA = sb + s * GSTAGE;
#pragma unroll
        for (int kk = 0; kk < 4; kk++) {
            uint32_t af[4][4], bf[2][4];
#pragma unroll
            for (int mf = 0; mf < 4; mf++) ldsm4(af[mf], sA + aOff[mf] + kk * 32);
#pragma unroll
            for (int j = 0; j < 2; j++) ldsm4(bf[j], sA + bOff[j] + kk * 32);
#pragma unroll
            for (int mf = 0; mf < 4; mf++) {
#pragma unroll
                for (int nf = 0; nf < 4; nf++) {
                    uint32_t b0 = bf[nf >> 1][(nf & 1) * 2];
                    uint32_t b1 = bf[nf >> 1][(nf & 1) * 2 + 1];
                    mma16(acc[mf][nf], af[mf][0], af[mf][1], af[mf][2], af[mf][3], b0, b1);
                }
            }
        }
        s = (s == 2) ? 0 : s + 1;
    }

    int mode = tr.mode;
    float bsc = tr.bscale;
    const float* bias = tr.b;
    __half* Ch = tr.C;
#pragma unroll
    for (int mf = 0; mf < 4; mf++) {
        int r0 = (int)bm * 128 + wm * 64 + mf * 16 + g;
#pragma unroll
        for (int nf = 0; nf < 4; nf++) {
            int c0 = (int)bn * 128 + wn * 32 + nf * 8 + 2 * tg;
            float bb0 = bias[c0] * bsc, bb1 = bias[c0 + 1] * bsc;
            float v0 = acc[mf][nf][0] + bb0;
            float v1 = acc[mf][nf][1] + bb1;
            float v2 = acc[mf][nf][2] + bb0;
            float v3 = acc[mf][nf][3] + bb1;
            if (mode == 1) {
                v0 = fmaxf(v0, 0.f); v1 = fmaxf(v1, 0.f);
                v2 = fmaxf(v2, 0.f); v3 = fmaxf(v3, 0.f);
            }
            if (mode == 3) {
                int b_ = r0 >> 10, sp = r0 & 1023;
                int h0 = c0 >> 6, d0 = c0 & 63;
                long vb = ((long)(b_ * NH + h0) * HD + d0) * SEQ + sp;
                Ch[vb] = __float2half_rn(v0);
                Ch[vb + SEQ] = __float2half_rn(v1);
                Ch[vb + 8] = __float2half_rn(v2);
                Ch[vb + SEQ + 8] = __float2half_rn(v3);
            } else {
                *(__half2*)&Ch[(long)r0 * N + c0] = __floats2half2_rn(v0, v1);
                *(__half2*)&Ch[(long)(r0 + 8) * N + c0] = __floats2half2_rn(v2, v3);
            }
        }
    }
}

// ---------------- fused flash attention (fp16 mma, register P), q-tile 128 ----------
// smem: Q[128][144B] @0 (18432), mask(f32) @18432 (4096), stages @22528 + s*18432
#define ATT_SMEM 59392

__global__ __launch_bounds__(256, 2) void attn_kernel(const __half* __restrict__ Q,
                                                      const __half* __restrict__ Kp,
                                                      const __half* __restrict__ Vt,
                                                      const int* __restrict__ mask,
                                                      __half* __restrict__ O) {
    extern __shared__ __align__(128) char smc[];
    uint32_t sb = smem_u32(smc);
    float* mAdd = (float*)(smc + 18432);

    int t = threadIdx.x, l = t & 31, warp = t >> 5;
    int g = l >> 2, tg = l & 3;
    int b = blockIdx.z, h = blockIdx.y, qt = blockIdx.x;
    int rq = warp * 16;

    const __half* Qb = Q + ((long)(b * SEQ + qt * 128)) * EDIM + h * HD;
    const __half* Kb = Kp + ((long)(b * SEQ)) * EDIM + h * HD;
    const __half* Vb = Vt + ((long)(b * NH + h) * HD) * SEQ;

    uint32_t aQoff = (uint32_t)((rq + (l & 7) + ((l >> 3) & 1) * 8) * 144 + (l >> 4) * 16);
    uint32_t bOff[4];
#pragma unroll
    for (int j = 0; j < 4; j++)
        bOff[j] = (uint32_t)((j * 16 + (l & 7) + (l >> 4) * 8) * 144 + ((l >> 3) & 1) * 16);

    {
        int r = t >> 1, s0 = (t & 1) * 4;
#pragma unroll
        for (int j = 0; j < 4; j++)
            cp16(sb + (uint32_t)(r * 144 + (s0 + j) * 16), Qb + (long)r * EDIM + (s0 + j) * 8);
        cp_commit();
    }
    for (int i = t; i < SEQ; i += 256) mAdd[i] = mask[b * SEQ + i] ? 0.f : -1e30f;

#pragma unroll
    for (int st = 0; st < 2; st++) {
        uint32_t Kst = sb + 22528 + st * 18432, Vst = Kst + 9216;
        int r = t >> 2, j0 = (t & 3) * 2;
        const __half* Ks = Kb + (long)(st * 64) * EDIM;
        const __half* Vs = Vb + st * 64;
#pragma unroll
        for (int j = 0; j < 2; j++) {
            cp16(Kst + (uint32_t)(r * 144 + (j0 + j) * 16), Ks + (long)r * EDIM + (j0 + j) * 8);
            cp16(Vst + (uint32_t)(r * 144 + (j0 + j) * 16), Vs + (long)r * SEQ + (j0 + j) * 8);
        }
        cp_commit();
    }

    float m_[2] = {-INFINITY, -INFINITY};
    float l_[2] = {0.f, 0.f};
    float o[8][4];
#pragma unroll
    for (int nf = 0; nf < 8; nf++)
#pragma unroll
        for (int q = 0; q < 4; q++) o[nf][q] = 0.f;

    for (int kt = 0; kt < 16; kt++) {
        int s = kt & 1;
        uint32_t Kst = sb + 22528 + s * 18432, Vst = Kst + 9216;
        asm volatile("cp.async.wait_group 1;");
        __syncthreads();

        // ---- S = Q K^T (Q pre-scaled by 1/8) ----
        float sc[8][4];
#pragma unroll
        for (int nf = 0; nf < 8; nf++)
#pragma unroll
            for (int q = 0; q < 4; q++) sc[nf][q] = 0.f;
#pragma unroll
        for (int kk = 0; kk < 4; kk++) {
            uint32_t af[4], bf[4][4];
            ldsm4(af, sb + aQoff + kk * 32);
#pragma unroll
            for (int j = 0; j < 4; j++) ldsm4(bf[j], Kst + bOff[j] + kk * 32);
#pragma unroll
            for (int nf = 0; nf < 8; nf++) {
                uint32_t b0 = bf[nf >> 1][(nf & 1) * 2];
                uint32_t b1 = bf[nf >> 1][(nf & 1) * 2 + 1];
                mma16(sc[nf], af[0], af[1], af[2], af[3], b0, b1);
            }
        }

        // ---- mask + online softmax (fp32) ----
        float rmax0 = -INFINITY, rmax1 = -INFINITY;
#pragma unroll
        for (int nf = 0; nf < 8; nf++) {
            int c0 = kt * 64 + nf * 8 + 2 * tg;
            float ma = mAdd[c0], mb = mAdd[c0 + 1];
            sc[nf][0] += ma;
            sc[nf][1] += mb;
            sc[nf][2] += ma;
            sc[nf][3] += mb;
            rmax0 = fmaxf(rmax0, fmaxf(sc[nf][0], sc[nf][1]));
            rmax1 = fmaxf(rmax1, fmaxf(sc[nf][2], sc[nf][3]));
        }
        rmax0 = fmaxf(rmax0, __shfl_xor_sync(0xffffffffu, rmax0, 1));
        rmax0 = fmaxf(rmax0, __shfl_xor_sync(0xffffffffu, rmax0, 2));
        rmax1 = fmaxf(rmax1, __shfl_xor_sync(0xffffffffu, rmax1, 1));
        rmax1 = fmaxf(rmax1, __shfl_xor_sync(0xffffffffu, rmax1, 2));
        float mn0 = fmaxf(m_[0], rmax0), mn1 = fmaxf(m_[1], rmax1);
        float cf0 = __expf(m_[0] - mn0), cf1 = __expf(m_[1] - mn1);
        float rs0 = 0.f, rs1 = 0.f;
#pragma unroll
        for (int nf = 0; nf < 8; nf++) {
            sc[nf][0] = __expf(sc[nf][0] - mn0);
            sc[nf][1] = __expf(sc[nf][1] - mn0);
            sc[nf][2] = __expf(sc[nf][2] - mn1);
            sc[nf][3] = __expf(sc[nf][3] - mn1);
            rs0 += sc[nf][0] + sc[nf][1];
            rs1 += sc[nf][2] + sc[nf][3];
        }
        rs0 += __shfl_xor_sync(0xffffffffu, rs0, 1);
        rs0 += __shfl_xor_sync(0xffffffffu, rs0, 2);
        rs1 += __shfl_xor_sync(0xffffffffu, rs1, 1);
        rs1 += __shfl_xor_sync(0xffffffffu, rs1, 2);
        l_[0] = l_[0] * cf0 + rs0;
        l_[1] = l_[1] * cf1 + rs1;
        m_[0] = mn0; m_[1] = mn1;
#pragma unroll
        for (int nf = 0; nf < 8; nf++) {
            o[nf][0] *= cf0; o[nf][1] *= cf0;
            o[nf][2] *= cf1; o[nf][3] *= cf1;
        }

        // ---- O += P V : P stays in registers (acc layout == A-fragment layout) ----
#pragma unroll
        for (int kk = 0; kk < 4; kk++) {
            uint32_t af0 = packh2(sc[2 * kk][0], sc[2 * kk][1]);
            uint32_t af1 = packh2(sc[2 * kk][2], sc[2 * kk][3]);
            uint32_t af2 = packh2(sc[2 * kk + 1][0], sc[2 * kk + 1][1]);
            uint32_t af3 = packh2(sc[2 * kk + 1][2], sc[2 * kk + 1][3]);
            uint32_t bf[4][4];
#pragma unroll
            for (int j = 0; j < 4; j++) ldsm4(bf[j], Vst + bOff[j] + kk * 32);
#pragma unroll
            for (int nf = 0; nf < 8; nf++) {
                uint32_t b0 = bf[nf >> 1][(nf & 1) * 2];
                uint32_t b1 = bf[nf >> 1][(nf & 1) * 2 + 1];
                mma16(o[nf], af0, af1, af2, af3, b0, b1);
            }
        }
        __syncthreads();

        int jn = kt + 2;
        if (jn < 16) {
            int r = t >> 2, j0 = (t & 3) * 2;
            const __half* Ks = Kb + (long)(jn * 64) * EDIM;
            const __half* Vs = Vb + jn * 64;
#pragma unroll
            for (int j = 0; j < 2; j++) {
                cp16(Kst + (uint32_t)(r * 144 + (j0 + j) * 16), Ks + (long)r * EDIM + (j0 + j) * 8);
                cp16(Vst + (uint32_t)(r * 144 + (j0 + j) * 16), Vs + (long)r * SEQ + (j0 + j) * 8);
            }
        }
        cp_commit();
    }

    float il0 = 1.f / l_[0], il1 = 1.f / l_[1];
#pragma unroll
    for (int nf = 0; nf < 8; nf++) {
        long rowg = (long)(b * SEQ + qt * 128 + rq + g);
        int colg = h * HD + nf * 8 + 2 * tg;
        *(__half2*)&O[rowg * EDIM + colg] = __floats2half2_rn(o[nf][0] * il0, o[nf][1] * il0);
        *(__half2*)&O[(rowg + 8) * EDIM + colg] = __floats2half2_rn(o[nf][2] * il1, o[nf][3] * il1);
    }
}

// ---------------- fused residual add + LayerNorm (fp16 streams, fp32 math) ----------
__global__ __launch_bounds__(192) void ln_res_kernel(const __half* __restrict__ xh,
                                                     const __half* __restrict__ y,
                                                     const float* __restrict__ gam,
                                                     const float* __restrict__ bet,
                                                     __half* __restrict__ outh) {
    int row = blockIdx.x, t = threadIdx.x;
    const __half2* xr = (const __half2*)(xh + (long)row * EDIM);
    const __half2* yr = (const __half2*)(y + (long)row * EDIM);
    float2 x01 = __half22float2(xr[2 * t]);
    float2 x23 = __half22float2(xr[2 * t + 1]);
    float2 y01 = __half22float2(yr[2 * t]);
    float2 y23 = __half22float2(yr[2 * t + 1]);
    float v0 = x01.x + y01.x, v1 = x01.y + y01.y;
    float v2 = x23.x + y23.x, v3 = x23.y + y23.y;
    float s1 = v0 + v1 + v2 + v3;
    float s2 = v0 * v0 + v1 * v1 + v2 * v2 + v3 * v3;
    __shared__ float sh[2][6];
    int lane = t & 31, w = t >> 5;
#pragma unroll
    for (int off = 16; off; off >>= 1) {
        s1 += __shfl_xor_sync(0xffffffffu, s1, off);
        s2 += __shfl_xor_sync(0xffffffffu, s2, off);
    }
    if (!lane) { sh[0][w] = s1; sh[1][w] = s2; }
    __syncthreads();
    float a1 = 0.f, a2 = 0.f;
#pragma unroll
    for (int i = 0; i < 6; i++) { a1 += sh[0][i]; a2 += sh[1][i]; }
    float mean = a1 * (1.f / EDIM);
    float var = a2 * (1.f / EDIM) - mean * mean;
    float rstd = rsqrtf(var + 1e-5f);
    float4 gg = ((const float4*)gam)[t];
    float4 bb = ((const float4*)bet)[t];
    __half2* oh = (__half2*)(outh + (long)row * EDIM);
    oh[2 * t] = __floats2half2_rn((v0 - mean) * rstd * gg.x + bb.x,
                                  (v1 - mean) * rstd * gg.y + bb.y);
    oh[2 * t + 1] = __floats2half2_rn((v2 - mean) * rstd * gg.z + bb.z,
                                      (v3 - mean) * rstd * gg.w + bb.w);
}

// ---------------- mean pool (fp16 in, fp32 accumulate): one warp per 4 outputs ------
__global__ __launch_bounds__(256) void pool_kernel(const __half* __restrict__ xh,
                                                   float* __restrict__ p) {
    int wid = (blockIdx.x * blockDim.x + threadIdx.x) >> 5;
    int lane = threadIdx.x & 31;
    if (wid >= 8 * (EDIM / 4)) return;
    int b = wid / (EDIM / 4), e4 = wid % (EDIM / 4);
    const __half2* xb = (const __half2*)(xh + (long)b * SEQ * EDIM) + 2 * e4;
    float4 s = make_float4(0.f, 0.f, 0.f, 0.f);
    for (int si = lane; si < SEQ; si += 32) {
        float2 a = __half22float2(xb[(long)si * (EDIM / 2)]);
        float2 c = __half22float2(xb[(long)si * (EDIM / 2) + 1]);
        s.x += a.x; s.y += a.y; s.z += c.x; s.w += c.y;
    }
#pragma unroll
    for (int off = 16; off; off >>= 1) {
        s.x += __shfl_xor_sync(0xffffffffu, s.x, off);
        s.y += __shfl_xor_sync(0xffffffffu, s.y, off);
        s.z += __shfl_xor_sync(0xffffffffu, s.z, off);
        s.w += __shfl_xor_sync(0xffffffffu, s.w, off);
    }
    if (!lane) {
        s.x *= (1.f / SEQ); s.y *= (1.f / SEQ); s.z *= (1.f / SEQ); s.w *= (1.f / SEQ);
        ((float4*)p)[wid] = s;
    }
}

// ---------------- classifier ----------------
__global__ void cls_kernel(const float* __restrict__ p, const float* __restrict__ Wc,
                           const float* __restrict__ bc, float* __restrict__ out) {
    int w = threadIdx.x >> 5, lane = threadIdx.x & 31;
    int b = w >> 1, c = w & 1;
    float s = 0.f;
    for (int e = lane; e < EDIM; e += 32) s += p[b * EDIM + e] * Wc[e * 2 + c];
#pragma unroll
    for (int off = 16; off; off >>= 1) s += __shfl_xor_sync(0xffffffffu, s, off);
    if (!lane) out[b * 2 + c] = s + bc[c];
}

// ---------------- launch ----------------
extern "C" void kernel_launch(void* const* d_in, const int* in_sizes, int n_in,
                              void* d_out, int out_size) {
    (void)in_sizes; (void)n_in; (void)out_size;
    const int* ids = (const int*)d_in[0];
    const int* amask = (const int*)d_in[1];
    const float* emb = (const float*)d_in[2];
    const float* pe = (const float*)d_in[3];
    const float* Wq = (const float*)d_in[4];
    const float* bq = (const float*)d_in[5];
    const float* Wk = (const float*)d_in[6];
    const float* bk = (const float*)d_in[7];
    const float* Wv = (const float*)d_in[8];
    const float* bv = (const float*)d_in[9];
    const float* Wo = (const float*)d_in[10];
    const float* bo = (const float*)d_in[11];
    const float* l1g = (const float*)d_in[12];
    const float* l1b = (const float*)d_in[13];
    const float* W1 = (const float*)d_in[14];
    const float* b1 = (const float*)d_in[15];
    const float* W2 = (const float*)d_in[16];
    const float* b2 = (const float*)d_in[17];
    const float* l2g = (const float*)d_in[18];
    const float* l2b = (const float*)d_in[19];
    const float* Wc = (const float*)d_in[20];
    const float* bc = (const float*)d_in[21];
    float* out = (float*)d_out;

    float* pl;
    __half *xh, *qh, *kh, *vh, *atth, *th, *ffnh, *wt;
    cudaGetSymbolAddress((void**)&xh, g_xh);
    cudaGetSymbolAddress((void**)&qh, g_qh);
    cudaGetSymbolAddress((void**)&kh, g_kh);
    cudaGetSymbolAddress((void**)&vh, g_vh);
    cudaGetSymbolAddress((void**)&atth, g_atth);
    cudaGetSymbolAddress((void**)&th, g_th);
    cudaGetSymbolAddress((void**)&ffnh, g_ffnh);
    cudaGetSymbolAddress((void**)&pl, g_pool);
    cudaGetSymbolAddress((void**)&wt, g_wt);

    cudaFuncSetAttribute(gemm_h, cudaFuncAttributeMaxDynamicSharedMemorySize, GEMM_SMEM);
    cudaFuncSetAttribute(attn_kernel, cudaFuncAttributeMaxDynamicSharedMemorySize, ATT_SMEM);

    // one-time: transpose + fp16-convert all weights (Wq scaled by 1/8)
    dim3 tb(32, 8);
    transpose_all<<<dim3(EDIM / 32, EDIM / 32, NLAYER), tb>>>(Wq, wt + 0L * EE, EDIM, EDIM,
                                                             (long)EE, (long)WT_PER_LAYER, 0.125f);
    transpose_all<<<dim3(EDIM / 32, EDIM / 32, NLAYER), tb>>>(Wk, wt + 1L * EE, EDIM, EDIM,
                                                             (long)EE, (long)WT_PER_LAYER, 1.f);
    transpose_all<<<dim3(EDIM / 32, EDIM / 32, NLAYER), tb>>>(Wv, wt + 2L * EE, EDIM, EDIM,
                                                             (long)EE, (long)WT_PER_LAYER, 1.f);
    transpose_all<<<dim3(EDIM / 32, EDIM / 32, NLAYER), tb>>>(Wo, wt + 3L * EE, EDIM, EDIM,
                                                             (long)EE, (long)WT_PER_LAYER, 1.f);
    transpose_all<<<dim3(FDIM / 32, EDIM / 32, NLAYER), tb>>>(W1, wt + 4L * EE, EDIM, FDIM,
                                                             (long)EF, (long)WT_PER_LAYER, 1.f);
    transpose_all<<<dim3(EDIM / 32, FDIM / 32, NLAYER), tb>>>(W2, wt + 4L * EE + EF, FDIM, EDIM,
                                                             (long)EF, (long)WT_PER_LAYER, 1.f);

    embed_kernel<<<(TOKS * EDIM + 255) / 256, 256>>>(ids, emb, pe, xh);

    for (int l = 0; l < NLAYER; l++) {
        long boff = (long)l * EDIM;
        __half* base = wt + (long)l * WT_PER_LAYER;
        Trip tq = {base + 0L * EE, bq + boff, qh, 2, 0.125f};
        Trip tk = {base + 1L * EE, bk + boff, kh, 2, 1.f};
        Trip tv = {base + 2L * EE, bv + boff, vh, 3, 1.f};
        gemm_h<<<dim3(6, 64, 3), 256, GEMM_SMEM>>>(xh, tq, tk, tv, EDIM, EDIM);
        attn_kernel<<<dim3(8, 12, 8), 256, ATT_SMEM>>>(qh, kh, vh, amask, atth);
        Trip to = {base + 3L * EE, bo + boff, th, 2, 1.f};
        gemm_h<<<dim3(6, 64, 1), 256, GEMM_SMEM>>>(atth, to, to, to, EDIM, EDIM);
        ln_res_kernel<<<TOKS, 192>>>(xh, th, l1g + boff, l1b + boff, xh);
        Trip t1 = {base + 4L * EE, b1 + (long)l * FDIM, ffnh, 1, 1.f};
        gemm_h<<<dim3(24, 64, 1), 256, GEMM_SMEM>>>(xh, t1, t1, t1, FDIM, EDIM);
        Trip t2 = {base + 4L * EE + EF, b2 + boff, th, 2, 1.f};
        gemm_h<<<dim3(6, 64, 1), 256, GEMM_SMEM>>>(ffnh, t2, t2, t2, EDIM, FDIM);
        ln_res_kernel<<<TOKS, 192>>>(xh, th, l2g + boff, l2b + boff, xh);
    }

    pool_kernel<<<(8 * (EDIM / 4) * 32 + 255) / 256, 256>>>(xh, pl);
    cls_kernel<<<1, 512>>>(pl, Wc, bc, out);
}